// round 12
// baseline (speedup 1.0000x reference)
#include <cuda_runtime.h>
#include <cuda_fp16.h>
#include <math.h>
#include <stdint.h>

// ---------------- problem constants ----------------
#define BATCH 128
#define SEQ   50
#define DMODEL 1024
#define DFF   4096
#define NHEAD 16
#define DK    64
#define NLAYER 5
#define KEMB  1200
#define KEMBP 1216
#define NTOK  6400
#define NCLS  71
#define NQKV  3072

#define GBK 32

// ---------------- weight scratch layout (transposed fp16) ----------------
#define WT_EMB_SZ (1024u*1216u)
#define WT_LAYER  (12u*1024u*1024u)
#define WT_TOTAL  (WT_EMB_SZ + 5u*WT_LAYER)

// ---------------- scratch (device globals) ----------------
__device__ float d_h  [NTOK * DMODEL];
__device__ float d_hc [BATCH * DMODEL];
__device__ float d_z0 [BATCH * DMODEL];
__device__ float d_z1 [BATCH * DMODEL];

__device__ __align__(16) __half d_qkv[NTOK * NQKV];
__device__ __align__(16) __half d_xh[NTOK * KEMBP];
__device__ __align__(16) __half d_a [NTOK * DMODEL];
__device__ __align__(16) __half d_o [NTOK * DMODEL];
__device__ __align__(16) __half d_f [NTOK * DFF];
__device__ __align__(16) __half d_wt[WT_TOTAL];
// compact (128-row) buffers for last-layer tail
__device__ __align__(16) __half d_oc[BATCH * DMODEL];
__device__ __align__(16) __half d_ac[BATCH * DMODEL];
__device__ __align__(16) __half d_fc[BATCH * DFF];

// ---------------- PTX helpers ----------------
__device__ __forceinline__ uint32_t smem_u32(const void* p) {
    uint32_t a;
    asm("{ .reg .u64 t; cvta.to.shared.u64 t, %1; cvt.u32.u64 %0, t; }" : "=r"(a) : "l"(p));
    return a;
}
__device__ __forceinline__ void cpa16(uint32_t dst, const void* src) {
    asm volatile("cp.async.cg.shared.global [%0], [%1], 16;" :: "r"(dst), "l"(src));
}
#define CP_COMMIT() asm volatile("cp.async.commit_group;" ::: "memory")
#define CP_WAIT2()  asm volatile("cp.async.wait_group 2;" ::: "memory")
#define CP_WAIT1()  asm volatile("cp.async.wait_group 1;" ::: "memory")
#define CP_WAIT0()  asm volatile("cp.async.wait_group 0;" ::: "memory")
#define LDSM4(r, a) \
    asm volatile("ldmatrix.sync.aligned.m8n8.x4.shared.b16 {%0,%1,%2,%3}, [%4];" \
        : "=r"((r)[0]), "=r"((r)[1]), "=r"((r)[2]), "=r"((r)[3]) : "r"(a))
#define MMA16816(c, a, b) \
    asm volatile("mma.sync.aligned.m16n8k16.row.col.f32.f16.f16.f32 " \
        "{%0,%1,%2,%3}, {%4,%5,%6,%7}, {%8,%9}, {%0,%1,%2,%3};" \
        : "+f"((c)[0]), "+f"((c)[1]), "+f"((c)[2]), "+f"((c)[3]) \
        : "r"((a)[0]), "r"((a)[1]), "r"((a)[2]), "r"((a)[3]), "r"((b)[0]), "r"((b)[1]))
__device__ __forceinline__ void red_add_f32(float* p, float v) {
    asm volatile("red.global.add.f32 [%0], %1;" :: "l"(p), "f"(v) : "memory");
}

// ================= HMMA GEMM core: 128x128 CTA tile, 128 thr, 4 warps (2x2, 64x64 warp tile)
// A: fp16 activations. B: fp16 weights (transposed [N][Kp]). 4-stage cp.async pipeline.
#define OFFB  8192u
#define STAGE 16384u
#define TGSMEM (4u * STAGE)

#define TG_LOAD_STAGE(sb, k0)                                                  \
    do {                                                                       \
        _Pragma("unroll")                                                      \
        for (int i_ = 0; i_ < 4; i_++) {                                       \
            const int id_ = tid + i_ * 128;                                    \
            const int row_ = id_ >> 2, cc_ = id_ & 3;                          \
            const uint32_t off_ = (uint32_t)((row_ << 6) + ((cc_ ^ ((row_ >> 1) & 3)) << 4)); \
            const size_t ka_ = (size_t)(m0 + row_) * Kp + (k0) + cc_ * 8;      \
            const size_t kb_ = (size_t)(n0 + row_) * Kp + (k0) + cc_ * 8;      \
            cpa16((sb) + off_, A + ka_);                                       \
            cpa16((sb) + OFFB + off_, B + kb_);                                \
        }                                                                      \
    } while (0)

#define TG_COMPUTE(sb)                                                         \
    do {                                                                       \
        _Pragma("unroll")                                                      \
        for (int ks = 0; ks < 2; ks++) {                                       \
            uint32_t aF[4][4];                                                 \
            _Pragma("unroll")                                                  \
            for (int mt = 0; mt < 4; mt++) {                                   \
                const int r = wm * 64 + mt * 16 + (lane & 15);                 \
                const int ch = ks * 2 + (lane >> 4);                           \
                const uint32_t off = (uint32_t)((r << 6) + ((ch ^ ((r >> 1) & 3)) << 4)); \
                LDSM4(aF[mt], (sb) + off);                                     \
            }                                                                  \
            _Pragma("unroll")                                                  \
            for (int half = 0; half < 2; half++) {                             \
                uint32_t bF[4][2];                                             \
                _Pragma("unroll")                                              \
                for (int p = 0; p < 2; p++) {                                  \
                    const int r = wn * 64 + half * 32 + p * 16 + (lane & 7) + ((lane & 16) >> 1); \
                    const int ch = ks * 2 + ((lane >> 3) & 1);                 \
                    const uint32_t off = (uint32_t)((r << 6) + ((ch ^ ((r >> 1) & 3)) << 4)); \
                    uint32_t q[4];                                             \
                    LDSM4(q, (sb) + OFFB + off);                               \
                    bF[p*2][0] = q[0]; bF[p*2][1] = q[1];                      \
                    bF[p*2+1][0] = q[2]; bF[p*2+1][1] = q[3];                  \
                }                                                              \
                _Pragma("unroll")                                              \
                for (int mt = 0; mt < 4; mt++)                                 \
                    _Pragma("unroll")                                          \
                    for (int nt = 0; nt < 4; nt++) MMA16816(acc[mt][half*4+nt], aF[mt], bF[nt]); \
            }                                                                  \
        }                                                                      \
    } while (0)

#define TG_MAINLOOP(kbase, nchunk)                                             \
    do {                                                                       \
        TG_LOAD_STAGE(smb, (kbase));                                           \
        CP_COMMIT();                                                           \
        if ((nchunk) > 1) { TG_LOAD_STAGE(smb + STAGE, (kbase) + GBK); CP_COMMIT(); } \
        if ((nchunk) > 2) { TG_LOAD_STAGE(smb + 2u * STAGE, (kbase) + 2 * GBK); CP_COMMIT(); } \
        int s_c = 0, s_ld = 3;                                                 \
        for (int c = 0; c < (nchunk); c++) {                                   \
            const int wg_ = (nchunk) - c - 1;                                  \
            if (wg_ >= 2) CP_WAIT2(); else if (wg_ == 1) CP_WAIT1(); else CP_WAIT0(); \
            __syncthreads();                                                   \
            if (c + 3 < (nchunk)) { TG_LOAD_STAGE(smb + (uint32_t)s_ld * STAGE, (kbase) + (c + 3) * GBK); CP_COMMIT(); } \
            TG_COMPUTE(smb + (uint32_t)s_c * STAGE);                           \
            s_c = (s_c + 1) & 3; s_ld = (s_ld + 1) & 3;                        \
        }                                                                      \
    } while (0)

// ---------------- standard GEMM with fused epilogue ----------------
// epi: 0 = +bias -> Ch (fp16); 1 = relu(+bias) -> Ch (fp16); 3 = +PE -> Cf
__global__ void __launch_bounds__(128, 3) tgemm_kernel(
    const __half* __restrict__ A, const __half* __restrict__ B,
    const float* __restrict__ bias,
    float* __restrict__ Cf, __half* __restrict__ Ch,
    int Kp, int N, int epi)
{
    extern __shared__ char sm[];
    const uint32_t smb = smem_u32(sm);
    const int tid  = threadIdx.x;
    const int lane = tid & 31;
    const int wid  = tid >> 5;
    const int wm   = wid & 1;
    const int wn   = wid >> 1;
    const int m0 = blockIdx.y * 128;
    const int n0 = blockIdx.x * 128;

    float acc[4][8][4];
#pragma unroll
    for (int i = 0; i < 4; i++)
#pragma unroll
        for (int j = 0; j < 8; j++)
#pragma unroll
            for (int t = 0; t < 4; t++) acc[i][j][t] = 0.f;

    TG_MAINLOOP(0, Kp / GBK);

    // epilogue
#pragma unroll
    for (int mt = 0; mt < 4; mt++) {
        const int r0 = m0 + wm * 64 + mt * 16 + (lane >> 2);
#pragma unroll
        for (int nt = 0; nt < 8; nt++) {
            const int col = n0 + wn * 64 + nt * 8 + (lane & 3) * 2;
            const float* a = acc[mt][nt];
            if (epi == 3) {
                const float dv = expf((float)(col & ~1) * (-9.210340371976184f / (float)DMODEL));
#pragma unroll
                for (int rr = 0; rr < 2; rr++) {
                    const int row = r0 + rr * 8;
                    const int srow = row % SEQ;
                    float sn, cs;
                    sincosf((float)srow * dv, &sn, &cs);
                    float2 o;
                    o.x = a[rr * 2 + 0] + sn;
                    o.y = a[rr * 2 + 1] + cs;
                    *reinterpret_cast<float2*>(&Cf[(size_t)row * N + col]) = o;
                }
            } else {
                const float b0 = __ldg(&bias[col]);
                const float b1 = __ldg(&bias[col + 1]);
#pragma unroll
                for (int rr = 0; rr < 2; rr++) {
                    const int row = r0 + rr * 8;
                    float v0 = a[rr * 2 + 0] + b0;
                    float v1 = a[rr * 2 + 1] + b1;
                    if (epi == 1) { v0 = fmaxf(v0, 0.f); v1 = fmaxf(v1, 0.f); }
                    *reinterpret_cast<__half2*>(&Ch[(size_t)row * N + col]) =
                        __halves2half2(__float2half_rn(v0), __float2half_rn(v1));
                }
            }
        }
    }
}

// ---------------- split-K GEMM: partial sums atomically added into prefilled C ----------------
__global__ void __launch_bounds__(128, 3) tgemm_atomic_kernel(
    const __half* __restrict__ A, const __half* __restrict__ B,
    float* __restrict__ Cf, int Kp, int Kz, int N)
{
    extern __shared__ char sm[];
    const uint32_t smb = smem_u32(sm);
    const int tid  = threadIdx.x;
    const int lane = tid & 31;
    const int wid  = tid >> 5;
    const int wm   = wid & 1;
    const int wn   = wid >> 1;
    const int m0 = blockIdx.y * 128;
    const int n0 = blockIdx.x * 128;
    const int kbase = blockIdx.z * Kz;

    float acc[4][8][4];
#pragma unroll
    for (int i = 0; i < 4; i++)
#pragma unroll
        for (int j = 0; j < 8; j++)
#pragma unroll
            for (int t = 0; t < 4; t++) acc[i][j][t] = 0.f;

    TG_MAINLOOP(kbase, Kz / GBK);

    // atomic epilogue
#pragma unroll
    for (int mt = 0; mt < 4; mt++) {
        const int r0 = m0 + wm * 64 + mt * 16 + (lane >> 2);
#pragma unroll
        for (int nt = 0; nt < 8; nt++) {
            const int col = n0 + wn * 64 + nt * 8 + (lane & 3) * 2;
            const float* a = acc[mt][nt];
#pragma unroll
            for (int rr = 0; rr < 2; rr++) {
                const int row = r0 + rr * 8;
                float* p = &Cf[(size_t)row * N + col];
                red_add_f32(p,     a[rr * 2 + 0]);
                red_add_f32(p + 1, a[rr * 2 + 1]);
            }
        }
    }
}

// ---------------- converters ----------------
__global__ void __launch_bounds__(256) cvt_x_kernel(
    const float* __restrict__ x, __half* __restrict__ xh)
{
    const int idx = blockIdx.x * 256 + threadIdx.x;
    if (idx >= NTOK * KEMBP) return;
    const int r = idx / KEMBP, c = idx % KEMBP;
    const float v = (c < KEMB) ? x[(size_t)r * KEMB + c] : 0.f;
    xh[idx] = __float2half_rn(v);
}

__global__ void cvt_wT_batch_kernel(
    const float* __restrict__ W, __half* __restrict__ Th,
    int K, int N, int Kp,
    size_t w_stride, size_t o_outer, size_t o_inner, int inner_mod)
{
    const int z = blockIdx.z;
    const float* Wz = W + (size_t)z * w_stride;
    const size_t ooff = (size_t)(z / inner_mod) * o_outer + (size_t)(z % inner_mod) * o_inner;
    __shared__ float t[32][33];
    const int k0 = blockIdx.y * 32, n0 = blockIdx.x * 32;
    const int tx = threadIdx.x, ty = threadIdx.y;
#pragma unroll
    for (int i = 0; i < 32; i += 8) {
        const int k = k0 + ty + i;
        t[ty + i][tx] = (k < K) ? Wz[(size_t)k * N + n0 + tx] : 0.f;
    }
    __syncthreads();
#pragma unroll
    for (int i = 0; i < 32; i += 8) {
        const int n = n0 + ty + i;
        const int k = k0 + tx;
        Th[ooff + (size_t)n * Kp + k] = __float2half_rn(t[tx][ty + i]);
    }
}

// ---------------- LayerNorm (ddof=1, eps on std) -> fp16, optional h += bias fused ----------------
__global__ void __launch_bounds__(256) ln_kernel(
    float* __restrict__ hio, const float* __restrict__ g,
    const float* __restrict__ b, __half* __restrict__ outh,
    const float* __restrict__ pbias)
{
    const int row = blockIdx.x;
    float* x = hio + (size_t)row * DMODEL;
    float vals[4];
    float s = 0.f, s2 = 0.f;
#pragma unroll
    for (int i = 0; i < 4; i++) {
        float v = x[threadIdx.x + i * 256];
        vals[i] = v; s += v; s2 += v * v;
    }
#pragma unroll
    for (int o = 16; o; o >>= 1) {
        s  += __shfl_xor_sync(0xffffffffu, s, o);
        s2 += __shfl_xor_sync(0xffffffffu, s2, o);
    }
    __shared__ float sh[2][8];
    const int w = threadIdx.x >> 5;
    if ((threadIdx.x & 31) == 0) { sh[0][w] = s; sh[1][w] = s2; }
    __syncthreads();
    if (threadIdx.x < 32) {
        s  = (threadIdx.x < 8) ? sh[0][threadIdx.x] : 0.f;
        s2 = (threadIdx.x < 8) ? sh[1][threadIdx.x] : 0.f;
#pragma unroll
        for (int o = 4; o; o >>= 1) {
            s  += __shfl_xor_sync(0xffffffffu, s, o);
            s2 += __shfl_xor_sync(0xffffffffu, s2, o);
        }
        if (threadIdx.x == 0) { sh[0][0] = s; sh[1][0] = s2; }
    }
    __syncthreads();
    const float mean = sh[0][0] * (1.f / (float)DMODEL);
    float var = (sh[1][0] - (float)DMODEL * mean * mean) * (1.f / (float)(DMODEL - 1));
    var = fmaxf(var, 0.f);
    const float inv = 1.f / (sqrtf(var) + 1e-6f);
#pragma unroll
    for (int i = 0; i < 4; i++) {
        const int c = threadIdx.x + i * 256;
        const float r = g[c] * (vals[i] - mean) * inv + b[c];
        outh[(size_t)row * DMODEL + c] = __float2half_rn(r);
        if (pbias) x[c] = vals[i] + pbias[c];
    }
}

// ---------------- gather last token per batch ----------------
__global__ void __launch_bounds__(256) gather_last_kernel(
    const float* __restrict__ h, const __half* __restrict__ o,
    const float* __restrict__ bias_o,
    float* __restrict__ hc, __half* __restrict__ oc)
{
    const int b = blockIdx.x;
    const size_t src = (size_t)(b * SEQ + (SEQ - 1)) * DMODEL;
    const size_t dst = (size_t)b * DMODEL;
#pragma unroll
    for (int i = 0; i < 4; i++) {
        const int c = threadIdx.x + i * 256;
        hc[dst + c] = h[src + c] + bias_o[c];
        oc[dst + c] = o[src + c];
    }
}

// ---------------- attention on fused fp16 QKV buffer; warp-parallel softmax ----------------
__global__ void __launch_bounds__(256) attn_kernel(
    const __half* __restrict__ QKV, __half* __restrict__ O)
{
    const int bh = blockIdx.x;
    const int b = bh >> 4;
    const int h = bh & 15;

    __shared__ float qs[SEQ][DK];
    __shared__ float ks[SEQ][DK + 1];
    __shared__ float vs[SEQ][DK];
    __shared__ float sc[SEQ][SEQ + 2];

    const int tid = threadIdx.x;
    const int lane = tid & 31;
    const int wid = tid >> 5;

    for (int e = tid; e < SEQ * DK; e += 256) {
        const int s = e >> 6;
        const int d = e & 63;
        const size_t gbase = (size_t)(b * SEQ + s) * NQKV + h * DK + d;
        qs[s][d] = __half2float(QKV[gbase]);
        ks[s][d] = __half2float(QKV[gbase + DMODEL]);
        vs[s][d] = __half2float(QKV[gbase + 2 * DMODEL]);
    }
    __syncthreads();

    for (int e = tid; e < SEQ * SEQ; e += 256) {
        const int i = e / SEQ;
        const int j = e % SEQ;
        float acc = 0.f;
#pragma unroll
        for (int d = 0; d < DK; d++) acc = fmaf(qs[i][d], ks[j][d], acc);
        sc[i][j] = acc * 0.125f;
    }
    __syncthreads();

    for (int r = wid; r < SEQ; r += 8) {
        const float v0 = (lane < SEQ) ? sc[r][lane] : -1e30f;
        const float v1 = (lane + 32 < SEQ) ? sc[r][lane + 32] : -1e30f;
        float mx = fmaxf(v0, v1);
#pragma unroll
        for (int o = 16; o; o >>= 1) mx = fmaxf(mx, __shfl_xor_sync(0xffffffffu, mx, o));
        const float e0 = (lane < SEQ) ? expf(v0 - mx) : 0.f;
        const float e1 = (lane + 32 < SEQ) ? expf(v1 - mx) : 0.f;
        float sum = e0 + e1;
#pragma unroll
        for (int o = 16; o; o >>= 1) sum += __shfl_xor_sync(0xffffffffu, sum, o);
        const float rinv = 1.f / sum;
        if (lane < SEQ) sc[r][lane] = e0 * rinv;
        if (lane + 32 < SEQ) sc[r][lane + 32] = e1 * rinv;
    }
    __syncthreads();

    for (int e = tid; e < SEQ * DK; e += 256) {
        const int i = e >> 6;
        const int d = e & 63;
        float acc = 0.f;
#pragma unroll
        for (int j = 0; j < SEQ; j++) acc = fmaf(sc[i][j], vs[j][d], acc);
        const size_t gidx = (size_t)(b * SEQ + i) * DMODEL + h * DK + d;
        O[gidx] = __float2half_rn(acc);
    }
}

// ---------------- head kernels ----------------
__global__ void __launch_bounds__(256) pool_ln_scale_kernel(
    const float* __restrict__ hc,
    const float* __restrict__ fin_g, const float* __restrict__ fin_b,
    const float* __restrict__ bn_g, const float* __restrict__ bn_b,
    float* __restrict__ z)
{
    const int bb = blockIdx.x;
    const float* x = hc + (size_t)bb * DMODEL;
    float vals[4];
    float s = 0.f, s2 = 0.f;
#pragma unroll
    for (int i = 0; i < 4; i++) {
        float v = x[threadIdx.x + i * 256];
        vals[i] = v; s += v; s2 += v * v;
    }
#pragma unroll
    for (int o = 16; o; o >>= 1) {
        s  += __shfl_xor_sync(0xffffffffu, s, o);
        s2 += __shfl_xor_sync(0xffffffffu, s2, o);
    }
    __shared__ float sh[2][8];
    const int w = threadIdx.x >> 5;
    if ((threadIdx.x & 31) == 0) { sh[0][w] = s; sh[1][w] = s2; }
    __syncthreads();
    if (threadIdx.x < 32) {
        s  = (threadIdx.x < 8) ? sh[0][threadIdx.x] : 0.f;
        s2 = (threadIdx.x < 8) ? sh[1][threadIdx.x] : 0.f;
#pragma unroll
        for (int o = 4; o; o >>= 1) {
            s  += __shfl_xor_sync(0xffffffffu, s, o);
            s2 += __shfl_xor_sync(0xffffffffu, s2, o);
        }
        if (threadIdx.x == 0) { sh[0][0] = s; sh[1][0] = s2; }
    }
    __syncthreads();
    const float mean = sh[0][0] * (1.f / (float)DMODEL);
    float var = (sh[1][0] - (float)DMODEL * mean * mean) * (1.f / (float)(DMODEL - 1));
    var = fmaxf(var, 0.f);
    const float inv = 1.f / (sqrtf(var) + 1e-6f);
    const float invbn = 1.f / sqrtf(1.0f + 1e-5f);
#pragma unroll
    for (int i = 0; i < 4; i++) {
        const int c = threadIdx.x + i * 256;
        const float lnv = fin_g[c] * (vals[i] - mean) * inv + fin_b[c];
        z[(size_t)bb * DMODEL + c] = lnv * invbn * bn_g[c] + bn_b[c];
    }
}

// ---------------- fp32 SGEMM (head only) ----------------
#define BM_S 128
#define BN_S 128
#define BK_S 8
__global__ void __launch_bounds__(256) sgemm_kernel(
    const float* __restrict__ A, const float* __restrict__ B,
    const float* __restrict__ bias, float* __restrict__ C,
    int M, int N, int K, int relu)
{
    __shared__ float As[BK_S][BM_S];
    __shared__ float Bs[BK_S][BN_S];
    const int tid = threadIdx.x;
    const int m0 = blockIdx.y * BM_S;
    const int n0 = blockIdx.x * BN_S;
    const int arow = tid >> 1;
    const int acol = (tid & 1) * 4;
    const int brow = tid >> 5;
    const int bcol = (tid & 31) * 4;
    const float* Aptr = A + (size_t)(m0 + arow) * K + acol;
    const float* Bptr = B + (size_t)brow * N + n0 + bcol;
    const int tx = tid & 15;
    const int ty = tid >> 4;
    float acc[8][8];
#pragma unroll
    for (int i = 0; i < 8; i++)
#pragma unroll
        for (int j = 0; j < 8; j++) acc[i][j] = 0.f;
    for (int k0 = 0; k0 < K; k0 += BK_S) {
        float4 a4 = *reinterpret_cast<const float4*>(Aptr + k0);
        float4 b4 = *reinterpret_cast<const float4*>(Bptr + (size_t)k0 * N);
        As[acol + 0][arow] = a4.x;
        As[acol + 1][arow] = a4.y;
        As[acol + 2][arow] = a4.z;
        As[acol + 3][arow] = a4.w;
        *reinterpret_cast<float4*>(&Bs[brow][bcol]) = b4;
        __syncthreads();
#pragma unroll
        for (int k = 0; k < BK_S; k++) {
            float ra[8], rb[8];
            *reinterpret_cast<float4*>(&ra[0]) = *reinterpret_cast<const float4*>(&As[k][ty * 8]);
            *reinterpret_cast<float4*>(&ra[4]) = *reinterpret_cast<const float4*>(&As[k][ty * 8 + 4]);
            *reinterpret_cast<float4*>(&rb[0]) = *reinterpret_cast<const float4*>(&Bs[k][tx * 8]);
            *reinterpret_cast<float4*>(&rb[4]) = *reinterpret_cast<const float4*>(&Bs[k][tx * 8 + 4]);
#pragma unroll
            for (int i = 0; i < 8; i++)
#pragma unroll
                for (int j = 0; j < 8; j++)
                    acc[i][j] = fmaf(ra[i], rb[j], acc[i][j]);
        }
        __syncthreads();
    }
#pragma unroll
    for (int i = 0; i < 8; i++) {
        const size_t base = (size_t)(m0 + ty * 8 + i) * N + n0 + tx * 8;
#pragma unroll
        for (int j = 0; j < 8; j++) {
            float v = acc[i][j] + __ldg(&bias[n0 + tx * 8 + j]);
            if (relu) v = fmaxf(v, 0.f);
            C[base + j] = v;
        }
    }
}

__global__ void __launch_bounds__(128) fc_kernel(
    const float* __restrict__ z1, const float* __restrict__ bn_g,
    const float* __restrict__ bn_b, const float* __restrict__ W,
    const float* __restrict__ bias, float* __restrict__ out)
{
    __shared__ float zs[DMODEL];
    const int bb = blockIdx.x;
    const float invbn = 1.f / sqrtf(1.0f + 1e-5f);
    for (int i = threadIdx.x; i < DMODEL; i += 128)
        zs[i] = z1[(size_t)bb * DMODEL + i] * invbn * bn_g[i] + bn_b[i];
    __syncthreads();
    const int c = threadIdx.x;
    if (c < NCLS) {
        float acc = bias[c];
        for (int k = 0; k < DMODEL; k++) acc = fmaf(zs[k], W[(size_t)k * NCLS + c], acc);
        out[(size_t)bb * NCLS + c] = acc;
    }
}

// ---------------- host launcher ----------------
extern "C" void kernel_launch(void* const* d_in, const int* in_sizes, int n_in,
                              void* d_out, int out_size)
{
    const float* x        = (const float*)d_in[0];
    const float* embed_w  = (const float*)d_in[1];
    const float* attn_w   = (const float*)d_in[2];
    const float* attn_b   = (const float*)d_in[3];
    const float* ff_w1    = (const float*)d_in[4];
    const float* ff_b1    = (const float*)d_in[5];
    const float* ff_w2    = (const float*)d_in[6];
    const float* ff_b2    = (const float*)d_in[7];
    const float* ln_g     = (const float*)d_in[8];
    const float* ln_b     = (const float*)d_in[9];
    const float* fin_g    = (const float*)d_in[10];
    const float* fin_b    = (const float*)d_in[11];
    const float* cf_bn_g  = (const float*)d_in[12];
    const float* cf_bn_b  = (const float*)d_in[13];
    const float* cf_w     = (const float*)d_in[14];
    const float* cf_b     = (const float*)d_in[15];
    const float* fc_bn_g  = (const float*)d_in[16];
    const float* fc_bn_b  = (const float*)d_in[17];
    const float* fc_w     = (const float*)d_in[18];
    const float* fc_b     = (const float*)d_in[19];

    cudaFuncSetAttribute(tgemm_kernel, cudaFuncAttributeMaxDynamicSharedMemorySize, TGSMEM);
    cudaFuncSetAttribute(tgemm_atomic_kernel, cudaFuncAttributeMaxDynamicSharedMemorySize, TGSMEM);

    float *g_h, *g_hc, *g_z0, *g_z1;
    __half *g_qkv, *g_xh, *g_a, *g_o, *g_f, *g_wt, *g_oc, *g_ac, *g_fc;
    cudaGetSymbolAddress((void**)&g_h,   d_h);
    cudaGetSymbolAddress((void**)&g_qkv, d_qkv);
    cudaGetSymbolAddress((void**)&g_hc,  d_hc);
    cudaGetSymbolAddress((void**)&g_z0,  d_z0);
    cudaGetSymbolAddress((void**)&g_z1,  d_z1);
    cudaGetSymbolAddress((void**)&g_xh,  d_xh);
    cudaGetSymbolAddress((void**)&g_a,   d_a);
    cudaGetSymbolAddress((void**)&g_o,   d_o);
    cudaGetSymbolAddress((void**)&g_f,   d_f);
    cudaGetSymbolAddress((void**)&g_wt,  d_wt);
    cudaGetSymbolAddress((void**)&g_oc,  d_oc);
    cudaGetSymbolAddress((void**)&g_ac,  d_ac);
    cudaGetSymbolAddress((void**)&g_fc,  d_fc);

    dim3 blk(32, 8);

    // converts
    cvt_x_kernel<<<(NTOK * KEMBP + 255) / 256, 256>>>(x, g_xh);
    cvt_wT_batch_kernel<<<dim3(1024 / 32, KEMBP / 32, 1), blk>>>(
        embed_w, g_wt, KEMB, DMODEL, KEMBP, 0, 0, 0, 1);
    cvt_wT_batch_kernel<<<dim3(32, 32, 20), blk>>>(
        attn_w, g_wt + WT_EMB_SZ, DMODEL, DMODEL, DMODEL,
        (size_t)DMODEL * DMODEL, (size_t)WT_LAYER, (size_t)1048576u, 4);
    cvt_wT_batch_kernel<<<dim3(DFF / 32, 32, 5), blk>>>(
        ff_w1, g_wt + WT_EMB_SZ + 4u * 1048576u,
        DMODEL, DFF, DMODEL, (size_t)DMODEL * DFF, (size_t)WT_LAYER, 0, 1);
    cvt_wT_batch_kernel<<<dim3(32, DFF / 32, 5), blk>>>(
        ff_w2, g_wt + WT_EMB_SZ + 8u * 1048576u,
        DFF, DMODEL, DFF, (size_t)DFF * DMODEL, (size_t)WT_LAYER, 0, 1);
    // embed GEMM, h = X @ We + PE
    {
        dim3 grid(DMODEL / 128, NTOK / 128);
        tgemm_kernel<<<grid, 128, TGSMEM>>>(
            g_xh, g_wt, nullptr, g_h, nullptr, KEMBP, DMODEL, 3);
    }

    // ---- layers 0..3 (full) ----
    for (int l = 0; l < NLAYER - 1; l++) {
        const size_t lw = (size_t)WT_EMB_SZ + (size_t)l * WT_LAYER;
        const __half* wq = g_wt + lw;
        const float* bq = attn_b + (size_t)l * 4 * DMODEL;

        ln_kernel<<<NTOK, 256>>>(g_h, ln_g + (size_t)(l * 2) * DMODEL,
                                 ln_b + (size_t)(l * 2) * DMODEL, g_a,
                                 bq + 3 * DMODEL);
        {
            dim3 grid(NQKV / 128, NTOK / 128);
            tgemm_kernel<<<grid, 128, TGSMEM>>>(
                g_a, wq, bq, nullptr, g_qkv, DMODEL, NQKV, 0);
        }
        attn_kernel<<<BATCH * NHEAD, 256>>>(g_qkv, g_o);
        {
            dim3 grid(DMODEL / 128, NTOK / 128, 2);
            tgemm_atomic_kernel<<<grid, 128, TGSMEM>>>(
                g_o, wq + 3u * 1048576u, g_h, DMODEL, DMODEL / 2, DMODEL);
        }
        ln_kernel<<<NTOK, 256>>>(g_h, ln_g + (size_t)(l * 2 + 1) * DMODEL,
                                 ln_b + (size_t)(l * 2 + 1) * DMODEL, g_a,
                                 ff_b2 + (size_t)l * DMODEL);
        {
            dim3 grid(DFF / 128, NTOK / 128);
            tgemm_kernel<<<grid, 128, TGSMEM>>>(
                g_a, g_wt + lw + 4u * 1048576u,
                ff_b1 + (size_t)l * DFF, nullptr, g_f, DMODEL, DFF, 1);
        }
        {
            dim3 grid(DMODEL / 128, NTOK / 128, 2);
            tgemm_atomic_kernel<<<grid, 128, TGSMEM>>>(
                g_f, g_wt + lw + 8u * 1048576u, g_h, DFF, DFF / 2, DMODEL);
        }
    }

    // ---- layer 4 (last): full QKV + attention, then compact 128-row tail ----
    {
        const int l = NLAYER - 1;
        const size_t lw = (size_t)WT_EMB_SZ + (size_t)l * WT_LAYER;
        const __half* wq = g_wt + lw;
        const float* bq = attn_b + (size_t)l * 4 * DMODEL;

        ln_kernel<<<NTOK, 256>>>(g_h, ln_g + (size_t)(l * 2) * DMODEL,
                                 ln_b + (size_t)(l * 2) * DMODEL, g_a, nullptr);
        {
            dim3 grid(NQKV / 128, NTOK / 128);
            tgemm_kernel<<<grid, 128, TGSMEM>>>(
                g_a, wq, bq, nullptr, g_qkv, DMODEL, NQKV, 0);
        }
        attn_kernel<<<BATCH * NHEAD, 256>>>(g_qkv, g_o);
        gather_last_kernel<<<BATCH, 256>>>(g_h, g_o, bq + 3 * DMODEL, g_hc, g_oc);
        {
            dim3 grid(DMODEL / 128, 1, 8);
            tgemm_atomic_kernel<<<grid, 128, TGSMEM>>>(
                g_oc, wq + 3u * 1048576u, g_hc, DMODEL, DMODEL / 8, DMODEL);
        }
        ln_kernel<<<BATCH, 256>>>(g_hc, ln_g + (size_t)(l * 2 + 1) * DMODEL,
                                  ln_b + (size_t)(l * 2 + 1) * DMODEL, g_ac,
                                  ff_b2 + (size_t)l * DMODEL);
        {
            dim3 grid(DFF / 128, 1);
            tgemm_kernel<<<grid, 128, TGSMEM>>>(
                g_ac, g_wt + lw + 4u * 1048576u,
                ff_b1 + (size_t)l * DFF, nullptr, g_fc, DMODEL, DFF, 1);
        }
        {
            dim3 grid(DMODEL / 128, 1, 8);
            tgemm_atomic_kernel<<<grid, 128, TGSMEM>>>(
                g_fc, g_wt + lw + 8u * 1048576u, g_hc, DFF, DFF / 8, DMODEL);
        }
    }

    // ---- classifier head ----
    pool_ln_scale_kernel<<<BATCH, 256>>>(g_hc, fin_g, fin_b, cf_bn_g, cf_bn_b, g_z0);
    sgemm_kernel<<<dim3(DMODEL / BN_S, 1), 256>>>(g_z0, cf_w, cf_b, g_z1, BATCH, DMODEL, DMODEL, 1);
    fc_kernel<<<BATCH, 128>>>(g_z1, fc_bn_g, fc_bn_b, fc_w, fc_b, (float*)d_out);
}

// round 13
// speedup vs baseline: 1.0887x; 1.0887x over previous
#include <cuda_runtime.h>
#include <cuda_fp16.h>
#include <math.h>
#include <stdint.h>

// ---------------- problem constants ----------------
#define BATCH 128
#define SEQ   50
#define DMODEL 1024
#define DFF   4096
#define NHEAD 16
#define DK    64
#define NLAYER 5
#define KEMB  1200
#define KEMBP 1216
#define NTOK  6400
#define NCLS  71
#define NQKV  3072

#define GBK 32

// ---------------- weight scratch layout (transposed fp16) ----------------
#define WT_EMB_SZ (1024u*1216u)
#define WT_LAYER  (12u*1024u*1024u)
#define WT_CF     (WT_EMB_SZ + 5u*WT_LAYER)
#define WT_TOTAL  (WT_CF + 1048576u)

// ---------------- scratch (device globals) ----------------
__device__ float d_h  [NTOK * DMODEL];
__device__ float d_hc [BATCH * DMODEL];
__device__ float d_z1 [BATCH * DMODEL];

__device__ __align__(16) __half d_qkv[NTOK * NQKV];
__device__ __align__(16) __half d_xh[NTOK * KEMBP];
__device__ __align__(16) __half d_a [NTOK * DMODEL];
__device__ __align__(16) __half d_o [NTOK * DMODEL];
__device__ __align__(16) __half d_f [NTOK * DFF];
__device__ __align__(16) __half d_wt[WT_TOTAL];
// compact (128-row) buffers for last-layer tail + head
__device__ __align__(16) __half d_oc[BATCH * DMODEL];
__device__ __align__(16) __half d_ac[BATCH * DMODEL];
__device__ __align__(16) __half d_fc[BATCH * DFF];
__device__ __align__(16) __half d_z0h[BATCH * DMODEL];

// ---------------- PTX helpers ----------------
__device__ __forceinline__ uint32_t smem_u32(const void* p) {
    uint32_t a;
    asm("{ .reg .u64 t; cvta.to.shared.u64 t, %1; cvt.u32.u64 %0, t; }" : "=r"(a) : "l"(p));
    return a;
}
__device__ __forceinline__ void cpa16(uint32_t dst, const void* src) {
    asm volatile("cp.async.cg.shared.global [%0], [%1], 16;" :: "r"(dst), "l"(src));
}
#define CP_COMMIT() asm volatile("cp.async.commit_group;" ::: "memory")
#define CP_WAIT2()  asm volatile("cp.async.wait_group 2;" ::: "memory")
#define CP_WAIT1()  asm volatile("cp.async.wait_group 1;" ::: "memory")
#define CP_WAIT0()  asm volatile("cp.async.wait_group 0;" ::: "memory")
#define LDSM4(r, a) \
    asm volatile("ldmatrix.sync.aligned.m8n8.x4.shared.b16 {%0,%1,%2,%3}, [%4];" \
        : "=r"((r)[0]), "=r"((r)[1]), "=r"((r)[2]), "=r"((r)[3]) : "r"(a))
#define MMA16816(c, a, b) \
    asm volatile("mma.sync.aligned.m16n8k16.row.col.f32.f16.f16.f32 " \
        "{%0,%1,%2,%3}, {%4,%5,%6,%7}, {%8,%9}, {%0,%1,%2,%3};" \
        : "+f"((c)[0]), "+f"((c)[1]), "+f"((c)[2]), "+f"((c)[3]) \
        : "r"((a)[0]), "r"((a)[1]), "r"((a)[2]), "r"((a)[3]), "r"((b)[0]), "r"((b)[1]))
__device__ __forceinline__ void red_add_f32(float* p, float v) {
    asm volatile("red.global.add.f32 [%0], %1;" :: "l"(p), "f"(v) : "memory");
}

// ================= HMMA GEMM core: 128x128 CTA tile, 128 thr, 4 warps (2x2, 64x64 warp tile)
// A: fp16 activations. B: fp16 weights (transposed [N][Kp]). 4-stage cp.async pipeline.
#define OFFB  8192u
#define STAGE 16384u
#define TGSMEM (4u * STAGE)

#define TG_LOAD_STAGE(sb, k0)                                                  \
    do {                                                                       \
        _Pragma("unroll")                                                      \
        for (int i_ = 0; i_ < 4; i_++) {                                       \
            const int id_ = tid + i_ * 128;                                    \
            const int row_ = id_ >> 2, cc_ = id_ & 3;                          \
            const uint32_t off_ = (uint32_t)((row_ << 6) + ((cc_ ^ ((row_ >> 1) & 3)) << 4)); \
            const size_t ka_ = (size_t)(m0 + row_) * Kp + (k0) + cc_ * 8;      \
            const size_t kb_ = (size_t)(n0 + row_) * Kp + (k0) + cc_ * 8;      \
            cpa16((sb) + off_, A + ka_);                                       \
            cpa16((sb) + OFFB + off_, B + kb_);                                \
        }                                                                      \
    } while (0)

#define TG_COMPUTE(sb)                                                         \
    do {                                                                       \
        _Pragma("unroll")                                                      \
        for (int ks = 0; ks < 2; ks++) {                                       \
            uint32_t aF[4][4];                                                 \
            _Pragma("unroll")                                                  \
            for (int mt = 0; mt < 4; mt++) {                                   \
                const int r = wm * 64 + mt * 16 + (lane & 15);                 \
                const int ch = ks * 2 + (lane >> 4);                           \
                const uint32_t off = (uint32_t)((r << 6) + ((ch ^ ((r >> 1) & 3)) << 4)); \
                LDSM4(aF[mt], (sb) + off);                                     \
            }                                                                  \
            _Pragma("unroll")                                                  \
            for (int half = 0; half < 2; half++) {                             \
                uint32_t bF[4][2];                                             \
                _Pragma("unroll")                                              \
                for (int p = 0; p < 2; p++) {                                  \
                    const int r = wn * 64 + half * 32 + p * 16 + (lane & 7) + ((lane & 16) >> 1); \
                    const int ch = ks * 2 + ((lane >> 3) & 1);                 \
                    const uint32_t off = (uint32_t)((r << 6) + ((ch ^ ((r >> 1) & 3)) << 4)); \
                    uint32_t q[4];                                             \
                    LDSM4(q, (sb) + OFFB + off);                               \
                    bF[p*2][0] = q[0]; bF[p*2][1] = q[1];                      \
                    bF[p*2+1][0] = q[2]; bF[p*2+1][1] = q[3];                  \
                }                                                              \
                _Pragma("unroll")                                              \
                for (int mt = 0; mt < 4; mt++)                                 \
                    _Pragma("unroll")                                          \
                    for (int nt = 0; nt < 4; nt++) MMA16816(acc[mt][half*4+nt], aF[mt], bF[nt]); \
            }                                                                  \
        }                                                                      \
    } while (0)

#define TG_MAINLOOP(kbase, nchunk)                                             \
    do {                                                                       \
        TG_LOAD_STAGE(smb, (kbase));                                           \
        CP_COMMIT();                                                           \
        if ((nchunk) > 1) { TG_LOAD_STAGE(smb + STAGE, (kbase) + GBK); CP_COMMIT(); } \
        if ((nchunk) > 2) { TG_LOAD_STAGE(smb + 2u * STAGE, (kbase) + 2 * GBK); CP_COMMIT(); } \
        int s_c = 0, s_ld = 3;                                                 \
        for (int c = 0; c < (nchunk); c++) {                                   \
            const int wg_ = (nchunk) - c - 1;                                  \
            if (wg_ >= 2) CP_WAIT2(); else if (wg_ == 1) CP_WAIT1(); else CP_WAIT0(); \
            __syncthreads();                                                   \
            if (c + 3 < (nchunk)) { TG_LOAD_STAGE(smb + (uint32_t)s_ld * STAGE, (kbase) + (c + 3) * GBK); CP_COMMIT(); } \
            TG_COMPUTE(smb + (uint32_t)s_c * STAGE);                           \
            s_c = (s_c + 1) & 3; s_ld = (s_ld + 1) & 3;                        \
        }                                                                      \
    } while (0)

// ---------------- standard GEMM with fused epilogue ----------------
// epi: 0 = +bias -> Ch (fp16); 1 = relu(+bias) -> Ch (fp16); 3 = +PE -> Cf
__global__ void __launch_bounds__(128, 2) tgemm_kernel(
    const __half* __restrict__ A, const __half* __restrict__ B,
    const float* __restrict__ bias,
    float* __restrict__ Cf, __half* __restrict__ Ch,
    int Kp, int N, int epi)
{
    extern __shared__ char sm[];
    const uint32_t smb = smem_u32(sm);
    const int tid  = threadIdx.x;
    const int lane = tid & 31;
    const int wid  = tid >> 5;
    const int wm   = wid & 1;
    const int wn   = wid >> 1;
    const int m0 = blockIdx.y * 128;
    const int n0 = blockIdx.x * 128;

    float acc[4][8][4];
#pragma unroll
    for (int i = 0; i < 4; i++)
#pragma unroll
        for (int j = 0; j < 8; j++)
#pragma unroll
            for (int t = 0; t < 4; t++) acc[i][j][t] = 0.f;

    TG_MAINLOOP(0, Kp / GBK);

    // epilogue
#pragma unroll
    for (int mt = 0; mt < 4; mt++) {
        const int r0 = m0 + wm * 64 + mt * 16 + (lane >> 2);
#pragma unroll
        for (int nt = 0; nt < 8; nt++) {
            const int col = n0 + wn * 64 + nt * 8 + (lane & 3) * 2;
            const float* a = acc[mt][nt];
            if (epi == 3) {
                const float dv = expf((float)(col & ~1) * (-9.210340371976184f / (float)DMODEL));
#pragma unroll
                for (int rr = 0; rr < 2; rr++) {
                    const int row = r0 + rr * 8;
                    const int srow = row % SEQ;
                    float sn, cs;
                    sincosf((float)srow * dv, &sn, &cs);
                    float2 o;
                    o.x = a[rr * 2 + 0] + sn;
                    o.y = a[rr * 2 + 1] + cs;
                    *reinterpret_cast<float2*>(&Cf[(size_t)row * N + col]) = o;
                }
            } else {
                const float b0 = __ldg(&bias[col]);
                const float b1 = __ldg(&bias[col + 1]);
#pragma unroll
                for (int rr = 0; rr < 2; rr++) {
                    const int row = r0 + rr * 8;
                    float v0 = a[rr * 2 + 0] + b0;
                    float v1 = a[rr * 2 + 1] + b1;
                    if (epi == 1) { v0 = fmaxf(v0, 0.f); v1 = fmaxf(v1, 0.f); }
                    *reinterpret_cast<__half2*>(&Ch[(size_t)row * N + col]) =
                        __halves2half2(__float2half_rn(v0), __float2half_rn(v1));
                }
            }
        }
    }
}

// ---------------- split-K GEMM: partial sums atomically added into C ----------------
// blockIdx.z == 0 additionally adds bias[col] (if bias != nullptr)
__global__ void __launch_bounds__(128, 2) tgemm_atomic_kernel(
    const __half* __restrict__ A, const __half* __restrict__ B,
    const float* __restrict__ bias,
    float* __restrict__ Cf, int Kp, int Kz, int N)
{
    extern __shared__ char sm[];
    const uint32_t smb = smem_u32(sm);
    const int tid  = threadIdx.x;
    const int lane = tid & 31;
    const int wid  = tid >> 5;
    const int wm   = wid & 1;
    const int wn   = wid >> 1;
    const int m0 = blockIdx.y * 128;
    const int n0 = blockIdx.x * 128;
    const int kbase = blockIdx.z * Kz;
    const bool addb = (bias != nullptr) && (blockIdx.z == 0);

    float acc[4][8][4];
#pragma unroll
    for (int i = 0; i < 4; i++)
#pragma unroll
        for (int j = 0; j < 8; j++)
#pragma unroll
            for (int t = 0; t < 4; t++) acc[i][j][t] = 0.f;

    TG_MAINLOOP(kbase, Kz / GBK);

    // atomic epilogue
#pragma unroll
    for (int mt = 0; mt < 4; mt++) {
        const int r0 = m0 + wm * 64 + mt * 16 + (lane >> 2);
#pragma unroll
        for (int nt = 0; nt < 8; nt++) {
            const int col = n0 + wn * 64 + nt * 8 + (lane & 3) * 2;
            const float* a = acc[mt][nt];
            const float b0 = addb ? __ldg(&bias[col])     : 0.f;
            const float b1 = addb ? __ldg(&bias[col + 1]) : 0.f;
#pragma unroll
            for (int rr = 0; rr < 2; rr++) {
                const int row = r0 + rr * 8;
                float* p = &Cf[(size_t)row * N + col];
                red_add_f32(p,     a[rr * 2 + 0] + b0);
                red_add_f32(p + 1, a[rr * 2 + 1] + b1);
            }
        }
    }
}

// ---------------- converters ----------------
__global__ void __launch_bounds__(256) cvt_x_kernel(
    const float* __restrict__ x, __half* __restrict__ xh)
{
    const int idx = blockIdx.x * 256 + threadIdx.x;
    if (idx >= NTOK * KEMBP) return;
    const int r = idx / KEMBP, c = idx % KEMBP;
    const float v = (c < KEMB) ? x[(size_t)r * KEMB + c] : 0.f;
    xh[idx] = __float2half_rn(v);
}

__global__ void cvt_wT_batch_kernel(
    const float* __restrict__ W, __half* __restrict__ Th,
    int K, int N, int Kp,
    size_t w_stride, size_t o_outer, size_t o_inner, int inner_mod)
{
    const int z = blockIdx.z;
    const float* Wz = W + (size_t)z * w_stride;
    const size_t ooff = (size_t)(z / inner_mod) * o_outer + (size_t)(z % inner_mod) * o_inner;
    __shared__ float t[32][33];
    const int k0 = blockIdx.y * 32, n0 = blockIdx.x * 32;
    const int tx = threadIdx.x, ty = threadIdx.y;
#pragma unroll
    for (int i = 0; i < 32; i += 8) {
        const int k = k0 + ty + i;
        t[ty + i][tx] = (k < K) ? Wz[(size_t)k * N + n0 + tx] : 0.f;
    }
    __syncthreads();
#pragma unroll
    for (int i = 0; i < 32; i += 8) {
        const int n = n0 + ty + i;
        const int k = k0 + tx;
        Th[ooff + (size_t)n * Kp + k] = __float2half_rn(t[tx][ty + i]);
    }
}

// ---------------- LayerNorm (ddof=1, eps on std) -> fp16 (read-only on h) ----------------
__global__ void __launch_bounds__(256) ln_kernel(
    const float* __restrict__ hio, const float* __restrict__ g,
    const float* __restrict__ b, __half* __restrict__ outh)
{
    const int row = blockIdx.x;
    const float* x = hio + (size_t)row * DMODEL;
    float vals[4];
    float s = 0.f, s2 = 0.f;
#pragma unroll
    for (int i = 0; i < 4; i++) {
        float v = x[threadIdx.x + i * 256];
        vals[i] = v; s += v; s2 += v * v;
    }
#pragma unroll
    for (int o = 16; o; o >>= 1) {
        s  += __shfl_xor_sync(0xffffffffu, s, o);
        s2 += __shfl_xor_sync(0xffffffffu, s2, o);
    }
    __shared__ float sh[2][8];
    const int w = threadIdx.x >> 5;
    if ((threadIdx.x & 31) == 0) { sh[0][w] = s; sh[1][w] = s2; }
    __syncthreads();
    if (threadIdx.x < 32) {
        s  = (threadIdx.x < 8) ? sh[0][threadIdx.x] : 0.f;
        s2 = (threadIdx.x < 8) ? sh[1][threadIdx.x] : 0.f;
#pragma unroll
        for (int o = 4; o; o >>= 1) {
            s  += __shfl_xor_sync(0xffffffffu, s, o);
            s2 += __shfl_xor_sync(0xffffffffu, s2, o);
        }
        if (threadIdx.x == 0) { sh[0][0] = s; sh[1][0] = s2; }
    }
    __syncthreads();
    const float mean = sh[0][0] * (1.f / (float)DMODEL);
    float var = (sh[1][0] - (float)DMODEL * mean * mean) * (1.f / (float)(DMODEL - 1));
    var = fmaxf(var, 0.f);
    const float inv = 1.f / (sqrtf(var) + 1e-6f);
#pragma unroll
    for (int i = 0; i < 4; i++) {
        const int c = threadIdx.x + i * 256;
        const float r = g[c] * (vals[i] - mean) * inv + b[c];
        outh[(size_t)row * DMODEL + c] = __float2half_rn(r);
    }
}

// ---------------- gather last token per batch ----------------
__global__ void __launch_bounds__(256) gather_last_kernel(
    const float* __restrict__ h, const __half* __restrict__ o,
    float* __restrict__ hc, __half* __restrict__ oc)
{
    const int b = blockIdx.x;
    const size_t src = (size_t)(b * SEQ + (SEQ - 1)) * DMODEL;
    const size_t dst = (size_t)b * DMODEL;
#pragma unroll
    for (int i = 0; i < 4; i++) {
        const int c = threadIdx.x + i * 256;
        hc[dst + c] = h[src + c];
        oc[dst + c] = o[src + c];
    }
}

// ---------------- attention on fused fp16 QKV buffer; warp-parallel softmax ----------------
__global__ void __launch_bounds__(256) attn_kernel(
    const __half* __restrict__ QKV, __half* __restrict__ O)
{
    const int bh = blockIdx.x;
    const int b = bh >> 4;
    const int h = bh & 15;

    __shared__ float qs[SEQ][DK];
    __shared__ float ks[SEQ][DK + 1];
    __shared__ float vs[SEQ][DK];
    __shared__ float sc[SEQ][SEQ + 2];

    const int tid = threadIdx.x;
    const int lane = tid & 31;
    const int wid = tid >> 5;

    for (int e = tid; e < SEQ * DK; e += 256) {
        const int s = e >> 6;
        const int d = e & 63;
        const size_t gbase = (size_t)(b * SEQ + s) * NQKV + h * DK + d;
        qs[s][d] = __half2float(QKV[gbase]);
        ks[s][d] = __half2float(QKV[gbase + DMODEL]);
        vs[s][d] = __half2float(QKV[gbase + 2 * DMODEL]);
    }
    __syncthreads();

    for (int e = tid; e < SEQ * SEQ; e += 256) {
        const int i = e / SEQ;
        const int j = e % SEQ;
        float acc = 0.f;
#pragma unroll
        for (int d = 0; d < DK; d++) acc = fmaf(qs[i][d], ks[j][d], acc);
        sc[i][j] = acc * 0.125f;
    }
    __syncthreads();

    for (int r = wid; r < SEQ; r += 8) {
        const float v0 = (lane < SEQ) ? sc[r][lane] : -1e30f;
        const float v1 = (lane + 32 < SEQ) ? sc[r][lane + 32] : -1e30f;
        float mx = fmaxf(v0, v1);
#pragma unroll
        for (int o = 16; o; o >>= 1) mx = fmaxf(mx, __shfl_xor_sync(0xffffffffu, mx, o));
        const float e0 = (lane < SEQ) ? expf(v0 - mx) : 0.f;
        const float e1 = (lane + 32 < SEQ) ? expf(v1 - mx) : 0.f;
        float sum = e0 + e1;
#pragma unroll
        for (int o = 16; o; o >>= 1) sum += __shfl_xor_sync(0xffffffffu, sum, o);
        const float rinv = 1.f / sum;
        if (lane < SEQ) sc[r][lane] = e0 * rinv;
        if (lane + 32 < SEQ) sc[r][lane + 32] = e1 * rinv;
    }
    __syncthreads();

    for (int e = tid; e < SEQ * DK; e += 256) {
        const int i = e >> 6;
        const int d = e & 63;
        float acc = 0.f;
#pragma unroll
        for (int j = 0; j < SEQ; j++) acc = fmaf(sc[i][j], vs[j][d], acc);
        const size_t gidx = (size_t)(b * SEQ + i) * DMODEL + h * DK + d;
        O[gidx] = __float2half_rn(acc);
    }
}

// ---------------- head: final LN + bn scale -> z0h (fp16 GEMM input); zero z1 ----------------
__global__ void __launch_bounds__(256) pool_ln_scale_kernel(
    const float* __restrict__ hc,
    const float* __restrict__ fin_g, const float* __restrict__ fin_b,
    const float* __restrict__ bn_g, const float* __restrict__ bn_b,
    __half* __restrict__ z0h, float* __restrict__ z1)
{
    const int bb = blockIdx.x;
    const float* x = hc + (size_t)bb * DMODEL;
    float vals[4];
    float s = 0.f, s2 = 0.f;
#pragma unroll
    for (int i = 0; i < 4; i++) {
        float v = x[threadIdx.x + i * 256];
        vals[i] = v; s += v; s2 += v * v;
    }
#pragma unroll
    for (int o = 16; o; o >>= 1) {
        s  += __shfl_xor_sync(0xffffffffu, s, o);
        s2 += __shfl_xor_sync(0xffffffffu, s2, o);
    }
    __shared__ float sh[2][8];
    const int w = threadIdx.x >> 5;
    if ((threadIdx.x & 31) == 0) { sh[0][w] = s; sh[1][w] = s2; }
    __syncthreads();
    if (threadIdx.x < 32) {
        s  = (threadIdx.x < 8) ? sh[0][threadIdx.x] : 0.f;
        s2 = (threadIdx.x < 8) ? sh[1][threadIdx.x] : 0.f;
#pragma unroll
        for (int o = 4; o; o >>= 1) {
            s  += __shfl_xor_sync(0xffffffffu, s, o);
            s2 += __shfl_xor_sync(0xffffffffu, s2, o);
        }
        if (threadIdx.x == 0) { sh[0][0] = s; sh[1][0] = s2; }
    }
    __syncthreads();
    const float mean = sh[0][0] * (1.f / (float)DMODEL);
    float var = (sh[1][0] - (float)DMODEL * mean * mean) * (1.f / (float)(DMODEL - 1));
    var = fmaxf(var, 0.f);
    const float inv = 1.f / (sqrtf(var) + 1e-6f);
    const float invbn = 1.f / sqrtf(1.0f + 1e-5f);
#pragma unroll
    for (int i = 0; i < 4; i++) {
        const int c = threadIdx.x + i * 256;
        const float lnv = fin_g[c] * (vals[i] - mean) * inv + fin_b[c];
        const float zz = lnv * invbn * bn_g[c] + bn_b[c];
        z0h[(size_t)bb * DMODEL + c] = __float2half_rn(zz);
        z1[(size_t)bb * DMODEL + c] = 0.f;
    }
}

// ---------------- final fc: relu(z1) -> bn2 scale -> @fc_w + fc_b ----------------
__global__ void __launch_bounds__(128) fc_kernel(
    const float* __restrict__ z1, const float* __restrict__ bn_g,
    const float* __restrict__ bn_b, const float* __restrict__ W,
    const float* __restrict__ bias, float* __restrict__ out)
{
    __shared__ float zs[DMODEL];
    const int bb = blockIdx.x;
    const float invbn = 1.f / sqrtf(1.0f + 1e-5f);
    for (int i = threadIdx.x; i < DMODEL; i += 128)
        zs[i] = fmaxf(z1[(size_t)bb * DMODEL + i], 0.f) * invbn * bn_g[i] + bn_b[i];
    __syncthreads();
    const int c = threadIdx.x;
    if (c < NCLS) {
        float acc = bias[c];
        for (int k = 0; k < DMODEL; k++) acc = fmaf(zs[k], W[(size_t)k * NCLS + c], acc);
        out[(size_t)bb * NCLS + c] = acc;
    }
}

// ---------------- host launcher ----------------
extern "C" void kernel_launch(void* const* d_in, const int* in_sizes, int n_in,
                              void* d_out, int out_size)
{
    const float* x        = (const float*)d_in[0];
    const float* embed_w  = (const float*)d_in[1];
    const float* attn_w   = (const float*)d_in[2];
    const float* attn_b   = (const float*)d_in[3];
    const float* ff_w1    = (const float*)d_in[4];
    const float* ff_b1    = (const float*)d_in[5];
    const float* ff_w2    = (const float*)d_in[6];
    const float* ff_b2    = (const float*)d_in[7];
    const float* ln_g     = (const float*)d_in[8];
    const float* ln_b     = (const float*)d_in[9];
    const float* fin_g    = (const float*)d_in[10];
    const float* fin_b    = (const float*)d_in[11];
    const float* cf_bn_g  = (const float*)d_in[12];
    const float* cf_bn_b  = (const float*)d_in[13];
    const float* cf_w     = (const float*)d_in[14];
    const float* cf_b     = (const float*)d_in[15];
    const float* fc_bn_g  = (const float*)d_in[16];
    const float* fc_bn_b  = (const float*)d_in[17];
    const float* fc_w     = (const float*)d_in[18];
    const float* fc_b     = (const float*)d_in[19];

    cudaFuncSetAttribute(tgemm_kernel, cudaFuncAttributeMaxDynamicSharedMemorySize, TGSMEM);
    cudaFuncSetAttribute(tgemm_atomic_kernel, cudaFuncAttributeMaxDynamicSharedMemorySize, TGSMEM);

    float *g_h, *g_hc, *g_z1;
    __half *g_qkv, *g_xh, *g_a, *g_o, *g_f, *g_wt, *g_oc, *g_ac, *g_fc, *g_z0h;
    cudaGetSymbolAddress((void**)&g_h,   d_h);
    cudaGetSymbolAddress((void**)&g_qkv, d_qkv);
    cudaGetSymbolAddress((void**)&g_hc,  d_hc);
    cudaGetSymbolAddress((void**)&g_z1,  d_z1);
    cudaGetSymbolAddress((void**)&g_xh,  d_xh);
    cudaGetSymbolAddress((void**)&g_a,   d_a);
    cudaGetSymbolAddress((void**)&g_o,   d_o);
    cudaGetSymbolAddress((void**)&g_f,   d_f);
    cudaGetSymbolAddress((void**)&g_wt,  d_wt);
    cudaGetSymbolAddress((void**)&g_oc,  d_oc);
    cudaGetSymbolAddress((void**)&g_ac,  d_ac);
    cudaGetSymbolAddress((void**)&g_fc,  d_fc);
    cudaGetSymbolAddress((void**)&g_z0h, d_z0h);

    dim3 blk(32, 8);

    // converts
    cvt_x_kernel<<<(NTOK * KEMBP + 255) / 256, 256>>>(x, g_xh);
    cvt_wT_batch_kernel<<<dim3(1024 / 32, KEMBP / 32, 1), blk>>>(
        embed_w, g_wt, KEMB, DMODEL, KEMBP, 0, 0, 0, 1);
    cvt_wT_batch_kernel<<<dim3(32, 32, 20), blk>>>(
        attn_w, g_wt + WT_EMB_SZ, DMODEL, DMODEL, DMODEL,
        (size_t)DMODEL * DMODEL, (size_t)WT_LAYER, (size_t)1048576u, 4);
    cvt_wT_batch_kernel<<<dim3(DFF / 32, 32, 5), blk>>>(
        ff_w1, g_wt + WT_EMB_SZ + 4u * 1048576u,
        DMODEL, DFF, DMODEL, (size_t)DMODEL * DFF, (size_t)WT_LAYER, 0, 1);
    cvt_wT_batch_kernel<<<dim3(32, DFF / 32, 5), blk>>>(
        ff_w2, g_wt + WT_EMB_SZ + 8u * 1048576u,
        DFF, DMODEL, DFF, (size_t)DFF * DMODEL, (size_t)WT_LAYER, 0, 1);
    cvt_wT_batch_kernel<<<dim3(32, 32, 1), blk>>>(
        cf_w, g_wt + WT_CF, DMODEL, DMODEL, DMODEL, 0, 0, 0, 1);
    // embed GEMM, h = X @ We + PE
    {
        dim3 grid(DMODEL / 128, NTOK / 128);
        tgemm_kernel<<<grid, 128, TGSMEM>>>(
            g_xh, g_wt, nullptr, g_h, nullptr, KEMBP, DMODEL, 3);
    }

    // ---- layers 0..3 (full) ----
    for (int l = 0; l < NLAYER - 1; l++) {
        const size_t lw = (size_t)WT_EMB_SZ + (size_t)l * WT_LAYER;
        const __half* wq = g_wt + lw;
        const float* bq = attn_b + (size_t)l * 4 * DMODEL;

        ln_kernel<<<NTOK, 256>>>(g_h, ln_g + (size_t)(l * 2) * DMODEL,
                                 ln_b + (size_t)(l * 2) * DMODEL, g_a);
        {
            dim3 grid(NQKV / 128, NTOK / 128);
            tgemm_kernel<<<grid, 128, TGSMEM>>>(
                g_a, wq, bq, nullptr, g_qkv, DMODEL, NQKV, 0);
        }
        attn_kernel<<<BATCH * NHEAD, 256>>>(g_qkv, g_o);
        {
            dim3 grid(DMODEL / 128, NTOK / 128, 2);
            tgemm_atomic_kernel<<<grid, 128, TGSMEM>>>(
                g_o, wq + 3u * 1048576u, bq + 3 * DMODEL, g_h, DMODEL, DMODEL / 2, DMODEL);
        }
        ln_kernel<<<NTOK, 256>>>(g_h, ln_g + (size_t)(l * 2 + 1) * DMODEL,
                                 ln_b + (size_t)(l * 2 + 1) * DMODEL, g_a);
        {
            dim3 grid(DFF / 128, NTOK / 128);
            tgemm_kernel<<<grid, 128, TGSMEM>>>(
                g_a, g_wt + lw + 4u * 1048576u,
                ff_b1 + (size_t)l * DFF, nullptr, g_f, DMODEL, DFF, 1);
        }
        {
            dim3 grid(DMODEL / 128, NTOK / 128, 2);
            tgemm_atomic_kernel<<<grid, 128, TGSMEM>>>(
                g_f, g_wt + lw + 8u * 1048576u, ff_b2 + (size_t)l * DMODEL,
                g_h, DFF, DFF / 2, DMODEL);
        }
    }

    // ---- layer 4 (last): full QKV + attention, then compact 128-row tail ----
    {
        const int l = NLAYER - 1;
        const size_t lw = (size_t)WT_EMB_SZ + (size_t)l * WT_LAYER;
        const __half* wq = g_wt + lw;
        const float* bq = attn_b + (size_t)l * 4 * DMODEL;

        ln_kernel<<<NTOK, 256>>>(g_h, ln_g + (size_t)(l * 2) * DMODEL,
                                 ln_b + (size_t)(l * 2) * DMODEL, g_a);
        {
            dim3 grid(NQKV / 128, NTOK / 128);
            tgemm_kernel<<<grid, 128, TGSMEM>>>(
                g_a, wq, bq, nullptr, g_qkv, DMODEL, NQKV, 0);
        }
        attn_kernel<<<BATCH * NHEAD, 256>>>(g_qkv, g_o);
        gather_last_kernel<<<BATCH, 256>>>(g_h, g_o, g_hc, g_oc);
        {
            dim3 grid(DMODEL / 128, 1, 8);
            tgemm_atomic_kernel<<<grid, 128, TGSMEM>>>(
                g_oc, wq + 3u * 1048576u, bq + 3 * DMODEL, g_hc, DMODEL, DMODEL / 8, DMODEL);
        }
        ln_kernel<<<BATCH, 256>>>(g_hc, ln_g + (size_t)(l * 2 + 1) * DMODEL,
                                  ln_b + (size_t)(l * 2 + 1) * DMODEL, g_ac);
        {
            dim3 grid(DFF / 128, 1);
            tgemm_kernel<<<grid, 128, TGSMEM>>>(
                g_ac, g_wt + lw + 4u * 1048576u,
                ff_b1 + (size_t)l * DFF, nullptr, g_fc, DMODEL, DFF, 1);
        }
        {
            dim3 grid(DMODEL / 128, 1, 8);
            tgemm_atomic_kernel<<<grid, 128, TGSMEM>>>(
                g_fc, g_wt + lw + 8u * 1048576u, ff_b2 + (size_t)l * DMODEL,
                g_hc, DFF, DFF / 8, DMODEL);
        }
    }

    // ---- classifier head (fp16 tensor path) ----
    pool_ln_scale_kernel<<<BATCH, 256>>>(g_hc, fin_g, fin_b, cf_bn_g, cf_bn_b, g_z0h, g_z1);
    {
        dim3 grid(DMODEL / 128, 1, 8);
        tgemm_atomic_kernel<<<grid, 128, TGSMEM>>>(
            g_z0h, g_wt + WT_CF, cf_b, g_z1, DMODEL, DMODEL / 8, DMODEL);
    }
    fc_kernel<<<BATCH, 128>>>(g_z1, fc_bn_g, fc_bn_b, fc_w, fc_b, (float*)d_out);
}

// round 14
// speedup vs baseline: 1.1015x; 1.0118x over previous
#include <cuda_runtime.h>
#include <cuda_fp16.h>
#include <math.h>
#include <stdint.h>

// ---------------- problem constants ----------------
#define BATCH 128
#define SEQ   50
#define DMODEL 1024
#define DFF   4096
#define NHEAD 16
#define DK    64
#define NLAYER 5
#define KEMB  1200
#define KEMBP 1216
#define NTOK  6400
#define NCLS  71
#define NQKV  3072

#define GBK 32

// ---------------- weight scratch layout (transposed fp16) ----------------
#define WT_EMB_SZ (1024u*1216u)
#define WT_LAYER  (12u*1024u*1024u)
#define WT_CF     (WT_EMB_SZ + 5u*WT_LAYER)
#define WT_TOTAL  (WT_CF + 1048576u)

// ---------------- scratch (device globals) ----------------
__device__ float d_h  [NTOK * DMODEL];
__device__ float d_hc [BATCH * DMODEL];
__device__ float d_z1 [BATCH * DMODEL];

__device__ __align__(16) __half d_qkv[NTOK * NQKV];
__device__ __align__(16) __half d_xh[NTOK * KEMBP];
__device__ __align__(16) __half d_a [NTOK * DMODEL];
__device__ __align__(16) __half d_o [NTOK * DMODEL];
__device__ __align__(16) __half d_f [NTOK * DFF];
__device__ __align__(16) __half d_wt[WT_TOTAL];
// compact (128-row) buffers for last-layer tail + head
__device__ __align__(16) __half d_oc[BATCH * DMODEL];
__device__ __align__(16) __half d_ac[BATCH * DMODEL];
__device__ __align__(16) __half d_fc[BATCH * DFF];
__device__ __align__(16) __half d_z0h[BATCH * DMODEL];

// ---------------- PTX helpers ----------------
__device__ __forceinline__ uint32_t smem_u32(const void* p) {
    uint32_t a;
    asm("{ .reg .u64 t; cvta.to.shared.u64 t, %1; cvt.u32.u64 %0, t; }" : "=r"(a) : "l"(p));
    return a;
}
__device__ __forceinline__ void cpa16(uint32_t dst, const void* src) {
    asm volatile("cp.async.cg.shared.global [%0], [%1], 16;" :: "r"(dst), "l"(src));
}
#define CP_COMMIT() asm volatile("cp.async.commit_group;" ::: "memory")
#define CP_WAIT2()  asm volatile("cp.async.wait_group 2;" ::: "memory")
#define CP_WAIT1()  asm volatile("cp.async.wait_group 1;" ::: "memory")
#define CP_WAIT0()  asm volatile("cp.async.wait_group 0;" ::: "memory")
#define LDSM4(r, a) \
    asm volatile("ldmatrix.sync.aligned.m8n8.x4.shared.b16 {%0,%1,%2,%3}, [%4];" \
        : "=r"((r)[0]), "=r"((r)[1]), "=r"((r)[2]), "=r"((r)[3]) : "r"(a))
#define MMA16816(c, a, b) \
    asm volatile("mma.sync.aligned.m16n8k16.row.col.f32.f16.f16.f32 " \
        "{%0,%1,%2,%3}, {%4,%5,%6,%7}, {%8,%9}, {%0,%1,%2,%3};" \
        : "+f"((c)[0]), "+f"((c)[1]), "+f"((c)[2]), "+f"((c)[3]) \
        : "r"((a)[0]), "r"((a)[1]), "r"((a)[2]), "r"((a)[3]), "r"((b)[0]), "r"((b)[1]))
__device__ __forceinline__ void red_add_f32(float* p, float v) {
    asm volatile("red.global.add.f32 [%0], %1;" :: "l"(p), "f"(v) : "memory");
}

// ================= HMMA GEMM core: 128x128 CTA tile, 128 thr, 4 warps (2x2, 64x64 warp tile)
// A: fp16 activations. B: fp16 weights (transposed [N][Kp]). 4-stage cp.async pipeline.
#define OFFB  8192u
#define STAGE 16384u
#define TGSMEM (4u * STAGE)

#define TG_LOAD_STAGE(sb, k0)                                                  \
    do {                                                                       \
        _Pragma("unroll")                                                      \
        for (int i_ = 0; i_ < 4; i_++) {                                       \
            const int id_ = tid + i_ * 128;                                    \
            const int row_ = id_ >> 2, cc_ = id_ & 3;                          \
            const uint32_t off_ = (uint32_t)((row_ << 6) + ((cc_ ^ ((row_ >> 1) & 3)) << 4)); \
            const size_t ka_ = (size_t)(m0 + row_) * Kp + (k0) + cc_ * 8;      \
            const size_t kb_ = (size_t)(n0 + row_) * Kp + (k0) + cc_ * 8;      \
            cpa16((sb) + off_, A + ka_);                                       \
            cpa16((sb) + OFFB + off_, B + kb_);                                \
        }                                                                      \
    } while (0)

#define TG_COMPUTE(sb)                                                         \
    do {                                                                       \
        _Pragma("unroll")                                                      \
        for (int ks = 0; ks < 2; ks++) {                                       \
            uint32_t aF[4][4];                                                 \
            _Pragma("unroll")                                                  \
            for (int mt = 0; mt < 4; mt++) {                                   \
                const int r = wm * 64 + mt * 16 + (lane & 15);                 \
                const int ch = ks * 2 + (lane >> 4);                           \
                const uint32_t off = (uint32_t)((r << 6) + ((ch ^ ((r >> 1) & 3)) << 4)); \
                LDSM4(aF[mt], (sb) + off);                                     \
            }                                                                  \
            _Pragma("unroll")                                                  \
            for (int half = 0; half < 2; half++) {                             \
                uint32_t bF[4][2];                                             \
                _Pragma("unroll")                                              \
                for (int p = 0; p < 2; p++) {                                  \
                    const int r = wn * 64 + half * 32 + p * 16 + (lane & 7) + ((lane & 16) >> 1); \
                    const int ch = ks * 2 + ((lane >> 3) & 1);                 \
                    const uint32_t off = (uint32_t)((r << 6) + ((ch ^ ((r >> 1) & 3)) << 4)); \
                    uint32_t q[4];                                             \
                    LDSM4(q, (sb) + OFFB + off);                               \
                    bF[p*2][0] = q[0]; bF[p*2][1] = q[1];                      \
                    bF[p*2+1][0] = q[2]; bF[p*2+1][1] = q[3];                  \
                }                                                              \
                _Pragma("unroll")                                              \
                for (int mt = 0; mt < 4; mt++)                                 \
                    _Pragma("unroll")                                          \
                    for (int nt = 0; nt < 4; nt++) MMA16816(acc[mt][half*4+nt], aF[mt], bF[nt]); \
            }                                                                  \
        }                                                                      \
    } while (0)

#define TG_MAINLOOP(kbase, nchunk)                                             \
    do {                                                                       \
        TG_LOAD_STAGE(smb, (kbase));                                           \
        CP_COMMIT();                                                           \
        if ((nchunk) > 1) { TG_LOAD_STAGE(smb + STAGE, (kbase) + GBK); CP_COMMIT(); } \
        if ((nchunk) > 2) { TG_LOAD_STAGE(smb + 2u * STAGE, (kbase) + 2 * GBK); CP_COMMIT(); } \
        int s_c = 0, s_ld = 3;                                                 \
        for (int c = 0; c < (nchunk); c++) {                                   \
            const int wg_ = (nchunk) - c - 1;                                  \
            if (wg_ >= 2) CP_WAIT2(); else if (wg_ == 1) CP_WAIT1(); else CP_WAIT0(); \
            __syncthreads();                                                   \
            if (c + 3 < (nchunk)) { TG_LOAD_STAGE(smb + (uint32_t)s_ld * STAGE, (kbase) + (c + 3) * GBK); CP_COMMIT(); } \
            TG_COMPUTE(smb + (uint32_t)s_c * STAGE);                           \
            s_c = (s_c + 1) & 3; s_ld = (s_ld + 1) & 3;                        \
        }                                                                      \
    } while (0)

// ---------------- standard GEMM with fused epilogue ----------------
// epi: 0 = +bias -> Ch (fp16); 1 = relu(+bias) -> Ch (fp16); 3 = +PE -> Cf
__global__ void __launch_bounds__(128, 2) tgemm_kernel(
    const __half* __restrict__ A, const __half* __restrict__ B,
    const float* __restrict__ bias,
    float* __restrict__ Cf, __half* __restrict__ Ch,
    int Kp, int N, int epi)
{
    extern __shared__ char sm[];
    const uint32_t smb = smem_u32(sm);
    const int tid  = threadIdx.x;
    const int lane = tid & 31;
    const int wid  = tid >> 5;
    const int wm   = wid & 1;
    const int wn   = wid >> 1;
    const int m0 = blockIdx.y * 128;
    const int n0 = blockIdx.x * 128;

    float acc[4][8][4];
#pragma unroll
    for (int i = 0; i < 4; i++)
#pragma unroll
        for (int j = 0; j < 8; j++)
#pragma unroll
            for (int t = 0; t < 4; t++) acc[i][j][t] = 0.f;

    TG_MAINLOOP(0, Kp / GBK);

    // epilogue
#pragma unroll
    for (int mt = 0; mt < 4; mt++) {
        const int r0 = m0 + wm * 64 + mt * 16 + (lane >> 2);
#pragma unroll
        for (int nt = 0; nt < 8; nt++) {
            const int col = n0 + wn * 64 + nt * 8 + (lane & 3) * 2;
            const float* a = acc[mt][nt];
            if (epi == 3) {
                const float dv = expf((float)(col & ~1) * (-9.210340371976184f / (float)DMODEL));
#pragma unroll
                for (int rr = 0; rr < 2; rr++) {
                    const int row = r0 + rr * 8;
                    const int srow = row % SEQ;
                    float sn, cs;
                    sincosf((float)srow * dv, &sn, &cs);
                    float2 o;
                    o.x = a[rr * 2 + 0] + sn;
                    o.y = a[rr * 2 + 1] + cs;
                    *reinterpret_cast<float2*>(&Cf[(size_t)row * N + col]) = o;
                }
            } else {
                const float b0 = __ldg(&bias[col]);
                const float b1 = __ldg(&bias[col + 1]);
#pragma unroll
                for (int rr = 0; rr < 2; rr++) {
                    const int row = r0 + rr * 8;
                    float v0 = a[rr * 2 + 0] + b0;
                    float v1 = a[rr * 2 + 1] + b1;
                    if (epi == 1) { v0 = fmaxf(v0, 0.f); v1 = fmaxf(v1, 0.f); }
                    *reinterpret_cast<__half2*>(&Ch[(size_t)row * N + col]) =
                        __halves2half2(__float2half_rn(v0), __float2half_rn(v1));
                }
            }
        }
    }
}

// ---------------- split-K GEMM: partial sums atomically added into C ----------------
// blockIdx.z == 0 additionally adds bias[col] (if bias != nullptr)
__global__ void __launch_bounds__(128, 2) tgemm_atomic_kernel(
    const __half* __restrict__ A, const __half* __restrict__ B,
    const float* __restrict__ bias,
    float* __restrict__ Cf, int Kp, int Kz, int N)
{
    extern __shared__ char sm[];
    const uint32_t smb = smem_u32(sm);
    const int tid  = threadIdx.x;
    const int lane = tid & 31;
    const int wid  = tid >> 5;
    const int wm   = wid & 1;
    const int wn   = wid >> 1;
    const int m0 = blockIdx.y * 128;
    const int n0 = blockIdx.x * 128;
    const int kbase = blockIdx.z * Kz;
    const bool addb = (bias != nullptr) && (blockIdx.z == 0);

    float acc[4][8][4];
#pragma unroll
    for (int i = 0; i < 4; i++)
#pragma unroll
        for (int j = 0; j < 8; j++)
#pragma unroll
            for (int t = 0; t < 4; t++) acc[i][j][t] = 0.f;

    TG_MAINLOOP(kbase, Kz / GBK);

    // atomic epilogue
#pragma unroll
    for (int mt = 0; mt < 4; mt++) {
        const int r0 = m0 + wm * 64 + mt * 16 + (lane >> 2);
#pragma unroll
        for (int nt = 0; nt < 8; nt++) {
            const int col = n0 + wn * 64 + nt * 8 + (lane & 3) * 2;
            const float* a = acc[mt][nt];
            const float b0 = addb ? __ldg(&bias[col])     : 0.f;
            const float b1 = addb ? __ldg(&bias[col + 1]) : 0.f;
#pragma unroll
            for (int rr = 0; rr < 2; rr++) {
                const int row = r0 + rr * 8;
                float* p = &Cf[(size_t)row * N + col];
                red_add_f32(p,     a[rr * 2 + 0] + b0);
                red_add_f32(p + 1, a[rr * 2 + 1] + b1);
            }
        }
    }
}

// ---------------- converters ----------------
// half2 stores; pairs never straddle the KEMB boundary (both even)
__global__ void __launch_bounds__(256) cvt_x_kernel(
    const float* __restrict__ x, __half* __restrict__ xh)
{
    const int idx = blockIdx.x * 256 + threadIdx.x;   // half2 index
    if (idx >= NTOK * KEMBP / 2) return;
    const int c = (idx * 2) % KEMBP;
    const int r = (idx * 2) / KEMBP;
    float v0 = 0.f, v1 = 0.f;
    if (c < KEMB) {
        const float2 xv = *reinterpret_cast<const float2*>(&x[(size_t)r * KEMB + c]);
        v0 = xv.x; v1 = xv.y;
    }
    reinterpret_cast<__half2*>(xh)[idx] = __halves2half2(__float2half_rn(v0), __float2half_rn(v1));
}

// W [K][N] fp32 -> transposed fp16 [N][Kp]; tile 256(k) x 32(n); uint4 stores along k
__global__ void cvt_wT_batch_kernel(
    const float* __restrict__ W, __half* __restrict__ Th,
    int K, int N, int Kp,
    size_t w_stride, size_t o_outer, size_t o_inner, int inner_mod)
{
    const int z = blockIdx.z;
    const float* Wz = W + (size_t)z * w_stride;
    const size_t ooff = (size_t)(z / inner_mod) * o_outer + (size_t)(z % inner_mod) * o_inner;
    __shared__ float t[256][33];
    const int k0 = blockIdx.y * 256, n0 = blockIdx.x * 32;
    const int tx = threadIdx.x, ty = threadIdx.y;   // block (32, 8)
#pragma unroll
    for (int i = 0; i < 256; i += 8) {
        const int k = k0 + ty + i;
        t[ty + i][tx] = (k < K) ? Wz[(size_t)k * N + n0 + tx] : 0.f;
    }
    __syncthreads();
    const int kk = k0 + tx * 8;
    if (kk < Kp) {
#pragma unroll
        for (int i = 0; i < 4; i++) {
            const int nn = ty * 4 + i;
            __half h8[8];
#pragma unroll
            for (int j = 0; j < 8; j++) h8[j] = __float2half_rn(t[tx * 8 + j][nn]);
            *reinterpret_cast<uint4*>(&Th[ooff + (size_t)(n0 + nn) * Kp + kk]) =
                *reinterpret_cast<uint4*>(h8);
        }
    }
}

// ---------------- LayerNorm (ddof=1, eps on std) -> fp16; float4 path ----------------
__global__ void __launch_bounds__(256) ln_kernel(
    const float* __restrict__ hio, const float* __restrict__ g,
    const float* __restrict__ b, __half* __restrict__ outh)
{
    const int row = blockIdx.x;
    const int c = threadIdx.x * 4;
    const float4 v = *reinterpret_cast<const float4*>(&hio[(size_t)row * DMODEL + c]);
    float s  = v.x + v.y + v.z + v.w;
    float s2 = v.x * v.x + v.y * v.y + v.z * v.z + v.w * v.w;
#pragma unroll
    for (int o = 16; o; o >>= 1) {
        s  += __shfl_xor_sync(0xffffffffu, s, o);
        s2 += __shfl_xor_sync(0xffffffffu, s2, o);
    }
    __shared__ float sh[2][8];
    const int w = threadIdx.x >> 5;
    if ((threadIdx.x & 31) == 0) { sh[0][w] = s; sh[1][w] = s2; }
    __syncthreads();
    if (threadIdx.x < 32) {
        s  = (threadIdx.x < 8) ? sh[0][threadIdx.x] : 0.f;
        s2 = (threadIdx.x < 8) ? sh[1][threadIdx.x] : 0.f;
#pragma unroll
        for (int o = 4; o; o >>= 1) {
            s  += __shfl_xor_sync(0xffffffffu, s, o);
            s2 += __shfl_xor_sync(0xffffffffu, s2, o);
        }
        if (threadIdx.x == 0) { sh[0][0] = s; sh[1][0] = s2; }
    }
    __syncthreads();
    const float mean = sh[0][0] * (1.f / (float)DMODEL);
    float var = (sh[1][0] - (float)DMODEL * mean * mean) * (1.f / (float)(DMODEL - 1));
    var = fmaxf(var, 0.f);
    const float inv = 1.f / (sqrtf(var) + 1e-6f);
    const float4 g4 = *reinterpret_cast<const float4*>(&g[c]);
    const float4 b4 = *reinterpret_cast<const float4*>(&b[c]);
    __half h4[4];
    h4[0] = __float2half_rn(g4.x * (v.x - mean) * inv + b4.x);
    h4[1] = __float2half_rn(g4.y * (v.y - mean) * inv + b4.y);
    h4[2] = __float2half_rn(g4.z * (v.z - mean) * inv + b4.z);
    h4[3] = __float2half_rn(g4.w * (v.w - mean) * inv + b4.w);
    *reinterpret_cast<uint2*>(&outh[(size_t)row * DMODEL + c]) = *reinterpret_cast<uint2*>(h4);
}

// ---------------- gather last token per batch ----------------
__global__ void __launch_bounds__(256) gather_last_kernel(
    const float* __restrict__ h, const __half* __restrict__ o,
    float* __restrict__ hc, __half* __restrict__ oc)
{
    const int b = blockIdx.x;
    const int c = threadIdx.x * 4;
    const size_t src = (size_t)(b * SEQ + (SEQ - 1)) * DMODEL + c;
    const size_t dst = (size_t)b * DMODEL + c;
    *reinterpret_cast<float4*>(&hc[dst]) = *reinterpret_cast<const float4*>(&h[src]);
    *reinterpret_cast<uint2*>(&oc[dst])  = *reinterpret_cast<const uint2*>(&o[src]);
}

// ---------------- attention on fused fp16 QKV buffer; warp-parallel softmax ----------------
__global__ void __launch_bounds__(256) attn_kernel(
    const __half* __restrict__ QKV, __half* __restrict__ O)
{
    const int bh = blockIdx.x;
    const int b = bh >> 4;
    const int h = bh & 15;

    __shared__ float qs[SEQ][DK];
    __shared__ float ks[SEQ][DK + 1];
    __shared__ float vs[SEQ][DK];
    __shared__ float sc[SEQ][SEQ + 2];

    const int tid = threadIdx.x;
    const int lane = tid & 31;
    const int wid = tid >> 5;

    for (int e = tid; e < SEQ * DK / 2; e += 256) {
        const int s = e >> 5;           // 32 half2 per row
        const int d = (e & 31) * 2;
        const size_t gbase = (size_t)(b * SEQ + s) * NQKV + h * DK + d;
        const float2 q2 = __half22float2(*reinterpret_cast<const __half2*>(&QKV[gbase]));
        const float2 k2 = __half22float2(*reinterpret_cast<const __half2*>(&QKV[gbase + DMODEL]));
        const float2 v2 = __half22float2(*reinterpret_cast<const __half2*>(&QKV[gbase + 2 * DMODEL]));
        qs[s][d] = q2.x; qs[s][d + 1] = q2.y;
        ks[s][d] = k2.x; ks[s][d + 1] = k2.y;
        vs[s][d] = v2.x; vs[s][d + 1] = v2.y;
    }
    __syncthreads();

    for (int e = tid; e < SEQ * SEQ; e += 256) {
        const int i = e / SEQ;
        const int j = e % SEQ;
        float acc = 0.f;
#pragma unroll
        for (int d = 0; d < DK; d++) acc = fmaf(qs[i][d], ks[j][d], acc);
        sc[i][j] = acc * 0.125f;
    }
    __syncthreads();

    for (int r = wid; r < SEQ; r += 8) {
        const float v0 = (lane < SEQ) ? sc[r][lane] : -1e30f;
        const float v1 = (lane + 32 < SEQ) ? sc[r][lane + 32] : -1e30f;
        float mx = fmaxf(v0, v1);
#pragma unroll
        for (int o = 16; o; o >>= 1) mx = fmaxf(mx, __shfl_xor_sync(0xffffffffu, mx, o));
        const float e0 = (lane < SEQ) ? expf(v0 - mx) : 0.f;
        const float e1 = (lane + 32 < SEQ) ? expf(v1 - mx) : 0.f;
        float sum = e0 + e1;
#pragma unroll
        for (int o = 16; o; o >>= 1) sum += __shfl_xor_sync(0xffffffffu, sum, o);
        const float rinv = 1.f / sum;
        if (lane < SEQ) sc[r][lane] = e0 * rinv;
        if (lane + 32 < SEQ) sc[r][lane + 32] = e1 * rinv;
    }
    __syncthreads();

    for (int e = tid; e < SEQ * DK; e += 256) {
        const int i = e >> 6;
        const int d = e & 63;
        float acc = 0.f;
#pragma unroll
        for (int j = 0; j < SEQ; j++) acc = fmaf(sc[i][j], vs[j][d], acc);
        const size_t gidx = (size_t)(b * SEQ + i) * DMODEL + h * DK + d;
        O[gidx] = __float2half_rn(acc);
    }
}

// ---------------- head: final LN + bn scale -> z0h; zero z1 ----------------
__global__ void __launch_bounds__(256) pool_ln_scale_kernel(
    const float* __restrict__ hc,
    const float* __restrict__ fin_g, const float* __restrict__ fin_b,
    const float* __restrict__ bn_g, const float* __restrict__ bn_b,
    __half* __restrict__ z0h, float* __restrict__ z1)
{
    const int bb = blockIdx.x;
    const int c = threadIdx.x * 4;
    const float4 v = *reinterpret_cast<const float4*>(&hc[(size_t)bb * DMODEL + c]);
    float s  = v.x + v.y + v.z + v.w;
    float s2 = v.x * v.x + v.y * v.y + v.z * v.z + v.w * v.w;
#pragma unroll
    for (int o = 16; o; o >>= 1) {
        s  += __shfl_xor_sync(0xffffffffu, s, o);
        s2 += __shfl_xor_sync(0xffffffffu, s2, o);
    }
    __shared__ float sh[2][8];
    const int w = threadIdx.x >> 5;
    if ((threadIdx.x & 31) == 0) { sh[0][w] = s; sh[1][w] = s2; }
    __syncthreads();
    if (threadIdx.x < 32) {
        s  = (threadIdx.x < 8) ? sh[0][threadIdx.x] : 0.f;
        s2 = (threadIdx.x < 8) ? sh[1][threadIdx.x] : 0.f;
#pragma unroll
        for (int o = 4; o; o >>= 1) {
            s  += __shfl_xor_sync(0xffffffffu, s, o);
            s2 += __shfl_xor_sync(0xffffffffu, s2, o);
        }
        if (threadIdx.x == 0) { sh[0][0] = s; sh[1][0] = s2; }
    }
    __syncthreads();
    const float mean = sh[0][0] * (1.f / (float)DMODEL);
    float var = (sh[1][0] - (float)DMODEL * mean * mean) * (1.f / (float)(DMODEL - 1));
    var = fmaxf(var, 0.f);
    const float inv = 1.f / (sqrtf(var) + 1e-6f);
    const float invbn = 1.f / sqrtf(1.0f + 1e-5f);
    const float4 g4 = *reinterpret_cast<const float4*>(&fin_g[c]);
    const float4 b4 = *reinterpret_cast<const float4*>(&fin_b[c]);
    const float4 bg = *reinterpret_cast<const float4*>(&bn_g[c]);
    const float4 bb4 = *reinterpret_cast<const float4*>(&bn_b[c]);
    __half h4[4];
    h4[0] = __float2half_rn((g4.x * (v.x - mean) * inv + b4.x) * invbn * bg.x + bb4.x);
    h4[1] = __float2half_rn((g4.y * (v.y - mean) * inv + b4.y) * invbn * bg.y + bb4.y);
    h4[2] = __float2half_rn((g4.z * (v.z - mean) * inv + b4.z) * invbn * bg.z + bb4.z);
    h4[3] = __float2half_rn((g4.w * (v.w - mean) * inv + b4.w) * invbn * bg.w + bb4.w);
    *reinterpret_cast<uint2*>(&z0h[(size_t)bb * DMODEL + c]) = *reinterpret_cast<uint2*>(h4);
    const float4 zz = {0.f, 0.f, 0.f, 0.f};
    *reinterpret_cast<float4*>(&z1[(size_t)bb * DMODEL + c]) = zz;
}

// ---------------- final fc: relu(z1) -> bn2 scale -> @fc_w + fc_b ----------------
__global__ void __launch_bounds__(128) fc_kernel(
    const float* __restrict__ z1, const float* __restrict__ bn_g,
    const float* __restrict__ bn_b, const float* __restrict__ W,
    const float* __restrict__ bias, float* __restrict__ out)
{
    __shared__ float zs[DMODEL];
    const int bb = blockIdx.x;
    const float invbn = 1.f / sqrtf(1.0f + 1e-5f);
    for (int i = threadIdx.x; i < DMODEL; i += 128)
        zs[i] = fmaxf(z1[(size_t)bb * DMODEL + i], 0.f) * invbn * bn_g[i] + bn_b[i];
    __syncthreads();
    const int c = threadIdx.x;
    if (c < NCLS) {
        float acc = bias[c];
        for (int k = 0; k < DMODEL; k++) acc = fmaf(zs[k], W[(size_t)k * NCLS + c], acc);
        out[(size_t)bb * NCLS + c] = acc;
    }
}

// ---------------- host launcher ----------------
extern "C" void kernel_launch(void* const* d_in, const int* in_sizes, int n_in,
                              void* d_out, int out_size)
{
    const float* x        = (const float*)d_in[0];
    const float* embed_w  = (const float*)d_in[1];
    const float* attn_w   = (const float*)d_in[2];
    const float* attn_b   = (const float*)d_in[3];
    const float* ff_w1    = (const float*)d_in[4];
    const float* ff_b1    = (const float*)d_in[5];
    const float* ff_w2    = (const float*)d_in[6];
    const float* ff_b2    = (const float*)d_in[7];
    const float* ln_g     = (const float*)d_in[8];
    const float* ln_b     = (const float*)d_in[9];
    const float* fin_g    = (const float*)d_in[10];
    const float* fin_b    = (const float*)d_in[11];
    const float* cf_bn_g  = (const float*)d_in[12];
    const float* cf_bn_b  = (const float*)d_in[13];
    const float* cf_w     = (const float*)d_in[14];
    const float* cf_b     = (const float*)d_in[15];
    const float* fc_bn_g  = (const float*)d_in[16];
    const float* fc_bn_b  = (const float*)d_in[17];
    const float* fc_w     = (const float*)d_in[18];
    const float* fc_b     = (const float*)d_in[19];

    cudaFuncSetAttribute(tgemm_kernel, cudaFuncAttributeMaxDynamicSharedMemorySize, TGSMEM);
    cudaFuncSetAttribute(tgemm_atomic_kernel, cudaFuncAttributeMaxDynamicSharedMemorySize, TGSMEM);

    float *g_h, *g_hc, *g_z1;
    __half *g_qkv, *g_xh, *g_a, *g_o, *g_f, *g_wt, *g_oc, *g_ac, *g_fc, *g_z0h;
    cudaGetSymbolAddress((void**)&g_h,   d_h);
    cudaGetSymbolAddress((void**)&g_qkv, d_qkv);
    cudaGetSymbolAddress((void**)&g_hc,  d_hc);
    cudaGetSymbolAddress((void**)&g_z1,  d_z1);
    cudaGetSymbolAddress((void**)&g_xh,  d_xh);
    cudaGetSymbolAddress((void**)&g_a,   d_a);
    cudaGetSymbolAddress((void**)&g_o,   d_o);
    cudaGetSymbolAddress((void**)&g_f,   d_f);
    cudaGetSymbolAddress((void**)&g_wt,  d_wt);
    cudaGetSymbolAddress((void**)&g_oc,  d_oc);
    cudaGetSymbolAddress((void**)&g_ac,  d_ac);
    cudaGetSymbolAddress((void**)&g_fc,  d_fc);
    cudaGetSymbolAddress((void**)&g_z0h, d_z0h);

    dim3 blk(32, 8);

    // converts
    cvt_x_kernel<<<(NTOK * KEMBP / 2 + 255) / 256, 256>>>(x, g_xh);
    cvt_wT_batch_kernel<<<dim3(1024 / 32, (KEMBP + 255) / 256, 1), blk>>>(
        embed_w, g_wt, KEMB, DMODEL, KEMBP, 0, 0, 0, 1);
    cvt_wT_batch_kernel<<<dim3(32, 4, 20), blk>>>(
        attn_w, g_wt + WT_EMB_SZ, DMODEL, DMODEL, DMODEL,
        (size_t)DMODEL * DMODEL, (size_t)WT_LAYER, (size_t)1048576u, 4);
    cvt_wT_batch_kernel<<<dim3(DFF / 32, 4, 5), blk>>>(
        ff_w1, g_wt + WT_EMB_SZ + 4u * 1048576u,
        DMODEL, DFF, DMODEL, (size_t)DMODEL * DFF, (size_t)WT_LAYER, 0, 1);
    cvt_wT_batch_kernel<<<dim3(32, 16, 5), blk>>>(
        ff_w2, g_wt + WT_EMB_SZ + 8u * 1048576u,
        DFF, DMODEL, DFF, (size_t)DFF * DMODEL, (size_t)WT_LAYER, 0, 1);
    cvt_wT_batch_kernel<<<dim3(32, 4, 1), blk>>>(
        cf_w, g_wt + WT_CF, DMODEL, DMODEL, DMODEL, 0, 0, 0, 1);
    // embed GEMM, h = X @ We + PE
    {
        dim3 grid(DMODEL / 128, NTOK / 128);
        tgemm_kernel<<<grid, 128, TGSMEM>>>(
            g_xh, g_wt, nullptr, g_h, nullptr, KEMBP, DMODEL, 3);
    }

    // ---- layers 0..3 (full) ----
    for (int l = 0; l < NLAYER - 1; l++) {
        const size_t lw = (size_t)WT_EMB_SZ + (size_t)l * WT_LAYER;
        const __half* wq = g_wt + lw;
        const float* bq = attn_b + (size_t)l * 4 * DMODEL;

        ln_kernel<<<NTOK, 256>>>(g_h, ln_g + (size_t)(l * 2) * DMODEL,
                                 ln_b + (size_t)(l * 2) * DMODEL, g_a);
        {
            dim3 grid(NQKV / 128, NTOK / 128);
            tgemm_kernel<<<grid, 128, TGSMEM>>>(
                g_a, wq, bq, nullptr, g_qkv, DMODEL, NQKV, 0);
        }
        attn_kernel<<<BATCH * NHEAD, 256>>>(g_qkv, g_o);
        {
            dim3 grid(DMODEL / 128, NTOK / 128, 2);
            tgemm_atomic_kernel<<<grid, 128, TGSMEM>>>(
                g_o, wq + 3u * 1048576u, bq + 3 * DMODEL, g_h, DMODEL, DMODEL / 2, DMODEL);
        }
        ln_kernel<<<NTOK, 256>>>(g_h, ln_g + (size_t)(l * 2 + 1) * DMODEL,
                                 ln_b + (size_t)(l * 2 + 1) * DMODEL, g_a);
        {
            dim3 grid(DFF / 128, NTOK / 128);
            tgemm_kernel<<<grid, 128, TGSMEM>>>(
                g_a, g_wt + lw + 4u * 1048576u,
                ff_b1 + (size_t)l * DFF, nullptr, g_f, DMODEL, DFF, 1);
        }
        {
            dim3 grid(DMODEL / 128, NTOK / 128, 2);
            tgemm_atomic_kernel<<<grid, 128, TGSMEM>>>(
                g_f, g_wt + lw + 8u * 1048576u, ff_b2 + (size_t)l * DMODEL,
                g_h, DFF, DFF / 2, DMODEL);
        }
    }

    // ---- layer 4 (last): full QKV + attention, then compact 128-row tail ----
    {
        const int l = NLAYER - 1;
        const size_t lw = (size_t)WT_EMB_SZ + (size_t)l * WT_LAYER;
        const __half* wq = g_wt + lw;
        const float* bq = attn_b + (size_t)l * 4 * DMODEL;

        ln_kernel<<<NTOK, 256>>>(g_h, ln_g + (size_t)(l * 2) * DMODEL,
                                 ln_b + (size_t)(l * 2) * DMODEL, g_a);
        {
            dim3 grid(NQKV / 128, NTOK / 128);
            tgemm_kernel<<<grid, 128, TGSMEM>>>(
                g_a, wq, bq, nullptr, g_qkv, DMODEL, NQKV, 0);
        }
        attn_kernel<<<BATCH * NHEAD, 256>>>(g_qkv, g_o);
        gather_last_kernel<<<BATCH, 256>>>(g_h, g_o, g_hc, g_oc);
        {
            dim3 grid(DMODEL / 128, 1, 8);
            tgemm_atomic_kernel<<<grid, 128, TGSMEM>>>(
                g_oc, wq + 3u * 1048576u, bq + 3 * DMODEL, g_hc, DMODEL, DMODEL / 8, DMODEL);
        }
        ln_kernel<<<BATCH, 256>>>(g_hc, ln_g + (size_t)(l * 2 + 1) * DMODEL,
                                  ln_b + (size_t)(l * 2 + 1) * DMODEL, g_ac);
        {
            dim3 grid(DFF / 128, 1);
            tgemm_kernel<<<grid, 128, TGSMEM>>>(
                g_ac, g_wt + lw + 4u * 1048576u,
                ff_b1 + (size_t)l * DFF, nullptr, g_fc, DMODEL, DFF, 1);
        }
        {
            dim3 grid(DMODEL / 128, 1, 8);
            tgemm_atomic_kernel<<<grid, 128, TGSMEM>>>(
                g_fc, g_wt + lw + 8u * 1048576u, ff_b2 + (size_t)l * DMODEL,
                g_hc, DFF, DFF / 8, DMODEL);
        }
    }

    // ---- classifier head (fp16 tensor path) ----
    pool_ln_scale_kernel<<<BATCH, 256>>>(g_hc, fin_g, fin_b, cf_bn_g, cf_bn_b, g_z0h, g_z1);
    {
        dim3 grid(DMODEL / 128, 1, 8);
        tgemm_atomic_kernel<<<grid, 128, TGSMEM>>>(
            g_z0h, g_wt + WT_CF, cf_b, g_z1, DMODEL, DMODEL / 8, DMODEL);
    }
    fc_kernel<<<BATCH, 128>>>(g_z1, fc_bn_g, fc_bn_b, fc_w, fc_b, (float*)d_out);
}

// round 15
// speedup vs baseline: 1.1400x; 1.0350x over previous
#include <cuda_runtime.h>
#include <cuda_fp16.h>
#include <math.h>
#include <stdint.h>

// ---------------- problem constants ----------------
#define BATCH 128
#define SEQ   50
#define DMODEL 1024
#define DFF   4096
#define NHEAD 16
#define DK    64
#define NLAYER 5
#define KEMB  1200
#define KEMBP 1216
#define NTOK  6400
#define NCLS  71
#define NQKV  3072
#define NKV   2048

#define GBK 32

// ---------------- weight scratch layout (transposed fp16) ----------------
#define WT_EMB_SZ (1024u*1216u)
#define WT_LAYER  (12u*1024u*1024u)
#define WT_CF     (WT_EMB_SZ + 5u*WT_LAYER)
#define WT_TOTAL  (WT_CF + 1048576u)

// ---------------- scratch (device globals) ----------------
__device__ float d_h  [NTOK * DMODEL];
__device__ float d_hc [BATCH * DMODEL];
__device__ float d_z1 [BATCH * DMODEL];

__device__ __align__(16) __half d_qkv[NTOK * NQKV];
__device__ __align__(16) __half d_kv [NTOK * NKV];
__device__ __align__(16) __half d_xh[NTOK * KEMBP];
__device__ __align__(16) __half d_a [NTOK * DMODEL];
__device__ __align__(16) __half d_o [NTOK * DMODEL];
__device__ __align__(16) __half d_f [NTOK * DFF];
__device__ __align__(16) __half d_wt[WT_TOTAL];
// compact (128-row) buffers for last-layer tail + head
__device__ __align__(16) __half d_aq[BATCH * DMODEL];
__device__ __align__(16) __half d_qc[BATCH * DMODEL];
__device__ __align__(16) __half d_oc[BATCH * DMODEL];
__device__ __align__(16) __half d_ac[BATCH * DMODEL];
__device__ __align__(16) __half d_fc[BATCH * DFF];
__device__ __align__(16) __half d_z0h[BATCH * DMODEL];

// ---------------- PTX helpers ----------------
__device__ __forceinline__ uint32_t smem_u32(const void* p) {
    uint32_t a;
    asm("{ .reg .u64 t; cvta.to.shared.u64 t, %1; cvt.u32.u64 %0, t; }" : "=r"(a) : "l"(p));
    return a;
}
__device__ __forceinline__ void cpa16(uint32_t dst, const void* src) {
    asm volatile("cp.async.cg.shared.global [%0], [%1], 16;" :: "r"(dst), "l"(src));
}
#define CP_COMMIT() asm volatile("cp.async.commit_group;" ::: "memory")
#define CP_WAIT2()  asm volatile("cp.async.wait_group 2;" ::: "memory")
#define CP_WAIT1()  asm volatile("cp.async.wait_group 1;" ::: "memory")
#define CP_WAIT0()  asm volatile("cp.async.wait_group 0;" ::: "memory")
#define LDSM4(r, a) \
    asm volatile("ldmatrix.sync.aligned.m8n8.x4.shared.b16 {%0,%1,%2,%3}, [%4];" \
        : "=r"((r)[0]), "=r"((r)[1]), "=r"((r)[2]), "=r"((r)[3]) : "r"(a))
#define MMA16816(c, a, b) \
    asm volatile("mma.sync.aligned.m16n8k16.row.col.f32.f16.f16.f32 " \
        "{%0,%1,%2,%3}, {%4,%5,%6,%7}, {%8,%9}, {%0,%1,%2,%3};" \
        : "+f"((c)[0]), "+f"((c)[1]), "+f"((c)[2]), "+f"((c)[3]) \
        : "r"((a)[0]), "r"((a)[1]), "r"((a)[2]), "r"((a)[3]), "r"((b)[0]), "r"((b)[1]))
__device__ __forceinline__ void red_add_f32(float* p, float v) {
    asm volatile("red.global.add.f32 [%0], %1;" :: "l"(p), "f"(v) : "memory");
}

// ================= HMMA GEMM core: 128x128 CTA tile, 128 thr, 4 warps (2x2, 64x64 warp tile)
#define OFFB  8192u
#define STAGE 16384u
#define TGSMEM (4u * STAGE)

#define TG_LOAD_STAGE(sb, k0)                                                  \
    do {                                                                       \
        _Pragma("unroll")                                                      \
        for (int i_ = 0; i_ < 4; i_++) {                                       \
            const int id_ = tid + i_ * 128;                                    \
            const int row_ = id_ >> 2, cc_ = id_ & 3;                          \
            const uint32_t off_ = (uint32_t)((row_ << 6) + ((cc_ ^ ((row_ >> 1) & 3)) << 4)); \
            const size_t ka_ = (size_t)(m0 + row_) * Kp + (k0) + cc_ * 8;      \
            const size_t kb_ = (size_t)(n0 + row_) * Kp + (k0) + cc_ * 8;      \
            cpa16((sb) + off_, A + ka_);                                       \
            cpa16((sb) + OFFB + off_, B + kb_);                                \
        }                                                                      \
    } while (0)

#define TG_COMPUTE(sb)                                                         \
    do {                                                                       \
        _Pragma("unroll")                                                      \
        for (int ks = 0; ks < 2; ks++) {                                       \
            uint32_t aF[4][4];                                                 \
            _Pragma("unroll")                                                  \
            for (int mt = 0; mt < 4; mt++) {                                   \
                const int r = wm * 64 + mt * 16 + (lane & 15);                 \
                const int ch = ks * 2 + (lane >> 4);                           \
                const uint32_t off = (uint32_t)((r << 6) + ((ch ^ ((r >> 1) & 3)) << 4)); \
                LDSM4(aF[mt], (sb) + off);                                     \
            }                                                                  \
            _Pragma("unroll")                                                  \
            for (int half = 0; half < 2; half++) {                             \
                uint32_t bF[4][2];                                             \
                _Pragma("unroll")                                              \
                for (int p = 0; p < 2; p++) {                                  \
                    const int r = wn * 64 + half * 32 + p * 16 + (lane & 7) + ((lane & 16) >> 1); \
                    const int ch = ks * 2 + ((lane >> 3) & 1);                 \
                    const uint32_t off = (uint32_t)((r << 6) + ((ch ^ ((r >> 1) & 3)) << 4)); \
                    uint32_t q[4];                                             \
                    LDSM4(q, (sb) + OFFB + off);                               \
                    bF[p*2][0] = q[0]; bF[p*2][1] = q[1];                      \
                    bF[p*2+1][0] = q[2]; bF[p*2+1][1] = q[3];                  \
                }                                                              \
                _Pragma("unroll")                                              \
                for (int mt = 0; mt < 4; mt++)                                 \
                    _Pragma("unroll")                                          \
                    for (int nt = 0; nt < 4; nt++) MMA16816(acc[mt][half*4+nt], aF[mt], bF[nt]); \
            }                                                                  \
        }                                                                      \
    } while (0)

#define TG_MAINLOOP(kbase, nchunk)                                             \
    do {                                                                       \
        TG_LOAD_STAGE(smb, (kbase));                                           \
        CP_COMMIT();                                                           \
        if ((nchunk) > 1) { TG_LOAD_STAGE(smb + STAGE, (kbase) + GBK); CP_COMMIT(); } \
        if ((nchunk) > 2) { TG_LOAD_STAGE(smb + 2u * STAGE, (kbase) + 2 * GBK); CP_COMMIT(); } \
        int s_c = 0, s_ld = 3;                                                 \
        for (int c = 0; c < (nchunk); c++) {                                   \
            const int wg_ = (nchunk) - c - 1;                                  \
            if (wg_ >= 2) CP_WAIT2(); else if (wg_ == 1) CP_WAIT1(); else CP_WAIT0(); \
            __syncthreads();                                                   \
            if (c + 3 < (nchunk)) { TG_LOAD_STAGE(smb + (uint32_t)s_ld * STAGE, (kbase) + (c + 3) * GBK); CP_COMMIT(); } \
            TG_COMPUTE(smb + (uint32_t)s_c * STAGE);                           \
            s_c = (s_c + 1) & 3; s_ld = (s_ld + 1) & 3;                        \
        }                                                                      \
    } while (0)

// ---------------- standard GEMM with fused epilogue ----------------
// epi: 0 = +bias -> Ch (fp16); 1 = relu(+bias) -> Ch (fp16); 3 = +PE -> Cf
__global__ void __launch_bounds__(128, 2) tgemm_kernel(
    const __half* __restrict__ A, const __half* __restrict__ B,
    const float* __restrict__ bias,
    float* __restrict__ Cf, __half* __restrict__ Ch,
    int Kp, int N, int epi)
{
    extern __shared__ char sm[];
    const uint32_t smb = smem_u32(sm);
    const int tid  = threadIdx.x;
    const int lane = tid & 31;
    const int wid  = tid >> 5;
    const int wm   = wid & 1;
    const int wn   = wid >> 1;
    const int m0 = blockIdx.y * 128;
    const int n0 = blockIdx.x * 128;

    float acc[4][8][4];
#pragma unroll
    for (int i = 0; i < 4; i++)
#pragma unroll
        for (int j = 0; j < 8; j++)
#pragma unroll
            for (int t = 0; t < 4; t++) acc[i][j][t] = 0.f;

    TG_MAINLOOP(0, Kp / GBK);

    // epilogue
#pragma unroll
    for (int mt = 0; mt < 4; mt++) {
        const int r0 = m0 + wm * 64 + mt * 16 + (lane >> 2);
#pragma unroll
        for (int nt = 0; nt < 8; nt++) {
            const int col = n0 + wn * 64 + nt * 8 + (lane & 3) * 2;
            const float* a = acc[mt][nt];
            if (epi == 3) {
                const float dv = expf((float)(col & ~1) * (-9.210340371976184f / (float)DMODEL));
#pragma unroll
                for (int rr = 0; rr < 2; rr++) {
                    const int row = r0 + rr * 8;
                    const int srow = row % SEQ;
                    float sn, cs;
                    sincosf((float)srow * dv, &sn, &cs);
                    float2 o;
                    o.x = a[rr * 2 + 0] + sn;
                    o.y = a[rr * 2 + 1] + cs;
                    *reinterpret_cast<float2*>(&Cf[(size_t)row * N + col]) = o;
                }
            } else {
                const float b0 = __ldg(&bias[col]);
                const float b1 = __ldg(&bias[col + 1]);
#pragma unroll
                for (int rr = 0; rr < 2; rr++) {
                    const int row = r0 + rr * 8;
                    float v0 = a[rr * 2 + 0] + b0;
                    float v1 = a[rr * 2 + 1] + b1;
                    if (epi == 1) { v0 = fmaxf(v0, 0.f); v1 = fmaxf(v1, 0.f); }
                    *reinterpret_cast<__half2*>(&Ch[(size_t)row * N + col]) =
                        __halves2half2(__float2half_rn(v0), __float2half_rn(v1));
                }
            }
        }
    }
}

// ---------------- split-K GEMM: partial sums atomically added into C ----------------
__global__ void __launch_bounds__(128, 2) tgemm_atomic_kernel(
    const __half* __restrict__ A, const __half* __restrict__ B,
    const float* __restrict__ bias,
    float* __restrict__ Cf, int Kp, int Kz, int N)
{
    extern __shared__ char sm[];
    const uint32_t smb = smem_u32(sm);
    const int tid  = threadIdx.x;
    const int lane = tid & 31;
    const int wid  = tid >> 5;
    const int wm   = wid & 1;
    const int wn   = wid >> 1;
    const int m0 = blockIdx.y * 128;
    const int n0 = blockIdx.x * 128;
    const int kbase = blockIdx.z * Kz;
    const bool addb = (bias != nullptr) && (blockIdx.z == 0);

    float acc[4][8][4];
#pragma unroll
    for (int i = 0; i < 4; i++)
#pragma unroll
        for (int j = 0; j < 8; j++)
#pragma unroll
            for (int t = 0; t < 4; t++) acc[i][j][t] = 0.f;

    TG_MAINLOOP(kbase, Kz / GBK);

#pragma unroll
    for (int mt = 0; mt < 4; mt++) {
        const int r0 = m0 + wm * 64 + mt * 16 + (lane >> 2);
#pragma unroll
        for (int nt = 0; nt < 8; nt++) {
            const int col = n0 + wn * 64 + nt * 8 + (lane & 3) * 2;
            const float* a = acc[mt][nt];
            const float b0 = addb ? __ldg(&bias[col])     : 0.f;
            const float b1 = addb ? __ldg(&bias[col + 1]) : 0.f;
#pragma unroll
            for (int rr = 0; rr < 2; rr++) {
                const int row = r0 + rr * 8;
                float* p = &Cf[(size_t)row * N + col];
                red_add_f32(p,     a[rr * 2 + 0] + b0);
                red_add_f32(p + 1, a[rr * 2 + 1] + b1);
            }
        }
    }
}

// ---------------- converters ----------------
__global__ void __launch_bounds__(256) cvt_x_kernel(
    const float* __restrict__ x, __half* __restrict__ xh)
{
    const int idx = blockIdx.x * 256 + threadIdx.x;
    if (idx >= NTOK * KEMBP / 2) return;
    const int c = (idx * 2) % KEMBP;
    const int r = (idx * 2) / KEMBP;
    float v0 = 0.f, v1 = 0.f;
    if (c < KEMB) {
        const float2 xv = *reinterpret_cast<const float2*>(&x[(size_t)r * KEMB + c]);
        v0 = xv.x; v1 = xv.y;
    }
    reinterpret_cast<__half2*>(xh)[idx] = __halves2half2(__float2half_rn(v0), __float2half_rn(v1));
}

__global__ void cvt_wT_batch_kernel(
    const float* __restrict__ W, __half* __restrict__ Th,
    int K, int N, int Kp,
    size_t w_stride, size_t o_outer, size_t o_inner, int inner_mod)
{
    const int z = blockIdx.z;
    const float* Wz = W + (size_t)z * w_stride;
    const size_t ooff = (size_t)(z / inner_mod) * o_outer + (size_t)(z % inner_mod) * o_inner;
    __shared__ float t[256][33];
    const int k0 = blockIdx.y * 256, n0 = blockIdx.x * 32;
    const int tx = threadIdx.x, ty = threadIdx.y;
#pragma unroll
    for (int i = 0; i < 256; i += 8) {
        const int k = k0 + ty + i;
        t[ty + i][tx] = (k < K) ? Wz[(size_t)k * N + n0 + tx] : 0.f;
    }
    __syncthreads();
    const int kk = k0 + tx * 8;
    if (kk < Kp) {
#pragma unroll
        for (int i = 0; i < 4; i++) {
            const int nn = ty * 4 + i;
            __half h8[8];
#pragma unroll
            for (int j = 0; j < 8; j++) h8[j] = __float2half_rn(t[tx * 8 + j][nn]);
            *reinterpret_cast<uint4*>(&Th[ooff + (size_t)(n0 + nn) * Kp + kk]) =
                *reinterpret_cast<uint4*>(h8);
        }
    }
}

// ---------------- LayerNorm (ddof=1, eps on std) -> fp16; float4 path ----------------
__global__ void __launch_bounds__(256) ln_kernel(
    const float* __restrict__ hio, const float* __restrict__ g,
    const float* __restrict__ b, __half* __restrict__ outh)
{
    const int row = blockIdx.x;
    const int c = threadIdx.x * 4;
    const float4 v = *reinterpret_cast<const float4*>(&hio[(size_t)row * DMODEL + c]);
    float s  = v.x + v.y + v.z + v.w;
    float s2 = v.x * v.x + v.y * v.y + v.z * v.z + v.w * v.w;
#pragma unroll
    for (int o = 16; o; o >>= 1) {
        s  += __shfl_xor_sync(0xffffffffu, s, o);
        s2 += __shfl_xor_sync(0xffffffffu, s2, o);
    }
    __shared__ float sh[2][8];
    const int w = threadIdx.x >> 5;
    if ((threadIdx.x & 31) == 0) { sh[0][w] = s; sh[1][w] = s2; }
    __syncthreads();
    if (threadIdx.x < 32) {
        s  = (threadIdx.x < 8) ? sh[0][threadIdx.x] : 0.f;
        s2 = (threadIdx.x < 8) ? sh[1][threadIdx.x] : 0.f;
#pragma unroll
        for (int o = 4; o; o >>= 1) {
            s  += __shfl_xor_sync(0xffffffffu, s, o);
            s2 += __shfl_xor_sync(0xffffffffu, s2, o);
        }
        if (threadIdx.x == 0) { sh[0][0] = s; sh[1][0] = s2; }
    }
    __syncthreads();
    const float mean = sh[0][0] * (1.f / (float)DMODEL);
    float var = (sh[1][0] - (float)DMODEL * mean * mean) * (1.f / (float)(DMODEL - 1));
    var = fmaxf(var, 0.f);
    const float inv = 1.f / (sqrtf(var) + 1e-6f);
    const float4 g4 = *reinterpret_cast<const float4*>(&g[c]);
    const float4 b4 = *reinterpret_cast<const float4*>(&b[c]);
    __half h4[4];
    h4[0] = __float2half_rn(g4.x * (v.x - mean) * inv + b4.x);
    h4[1] = __float2half_rn(g4.y * (v.y - mean) * inv + b4.y);
    h4[2] = __float2half_rn(g4.z * (v.z - mean) * inv + b4.z);
    h4[3] = __float2half_rn(g4.w * (v.w - mean) * inv + b4.w);
    *reinterpret_cast<uint2*>(&outh[(size_t)row * DMODEL + c]) = *reinterpret_cast<uint2*>(h4);
}

// ---------------- gather last token: hc = h[last] (fp32), aq = a[last] (fp16) ----------------
__global__ void __launch_bounds__(256) gather2_kernel(
    const float* __restrict__ h, const __half* __restrict__ a,
    float* __restrict__ hc, __half* __restrict__ aq)
{
    const int b = blockIdx.x;
    const int c = threadIdx.x * 4;
    const size_t src = (size_t)(b * SEQ + (SEQ - 1)) * DMODEL + c;
    const size_t dst = (size_t)b * DMODEL + c;
    *reinterpret_cast<float4*>(&hc[dst]) = *reinterpret_cast<const float4*>(&h[src]);
    *reinterpret_cast<uint2*>(&aq[dst])  = *reinterpret_cast<const uint2*>(&a[src]);
}

// ---------------- attention on fused fp16 QKV buffer (layers 0..3) ----------------
__global__ void __launch_bounds__(256) attn_kernel(
    const __half* __restrict__ QKV, __half* __restrict__ O)
{
    const int bh = blockIdx.x;
    const int b = bh >> 4;
    const int h = bh & 15;

    __shared__ float qs[SEQ][DK];
    __shared__ float ks[SEQ][DK + 1];
    __shared__ float vs[SEQ][DK];
    __shared__ float sc[SEQ][SEQ + 2];

    const int tid = threadIdx.x;
    const int lane = tid & 31;
    const int wid = tid >> 5;

    for (int e = tid; e < SEQ * DK / 2; e += 256) {
        const int s = e >> 5;
        const int d = (e & 31) * 2;
        const size_t gbase = (size_t)(b * SEQ + s) * NQKV + h * DK + d;
        const float2 q2 = __half22float2(*reinterpret_cast<const __half2*>(&QKV[gbase]));
        const float2 k2 = __half22float2(*reinterpret_cast<const __half2*>(&QKV[gbase + DMODEL]));
        const float2 v2 = __half22float2(*reinterpret_cast<const __half2*>(&QKV[gbase + 2 * DMODEL]));
        qs[s][d] = q2.x; qs[s][d + 1] = q2.y;
        ks[s][d] = k2.x; ks[s][d + 1] = k2.y;
        vs[s][d] = v2.x; vs[s][d + 1] = v2.y;
    }
    __syncthreads();

    for (int e = tid; e < SEQ * SEQ; e += 256) {
        const int i = e / SEQ;
        const int j = e % SEQ;
        float acc = 0.f;
#pragma unroll
        for (int d = 0; d < DK; d++) acc = fmaf(qs[i][d], ks[j][d], acc);
        sc[i][j] = acc * 0.125f;
    }
    __syncthreads();

    for (int r = wid; r < SEQ; r += 8) {
        const float v0 = (lane < SEQ) ? sc[r][lane] : -1e30f;
        const float v1 = (lane + 32 < SEQ) ? sc[r][lane + 32] : -1e30f;
        float mx = fmaxf(v0, v1);
#pragma unroll
        for (int o = 16; o; o >>= 1) mx = fmaxf(mx, __shfl_xor_sync(0xffffffffu, mx, o));
        const float e0 = (lane < SEQ) ? expf(v0 - mx) : 0.f;
        const float e1 = (lane + 32 < SEQ) ? expf(v1 - mx) : 0.f;
        float sum = e0 + e1;
#pragma unroll
        for (int o = 16; o; o >>= 1) sum += __shfl_xor_sync(0xffffffffu, sum, o);
        const float rinv = 1.f / sum;
        if (lane < SEQ) sc[r][lane] = e0 * rinv;
        if (lane + 32 < SEQ) sc[r][lane + 32] = e1 * rinv;
    }
    __syncthreads();

    for (int e = tid; e < SEQ * DK; e += 256) {
        const int i = e >> 6;
        const int d = e & 63;
        float acc = 0.f;
#pragma unroll
        for (int j = 0; j < SEQ; j++) acc = fmaf(sc[i][j], vs[j][d], acc);
        const size_t gidx = (size_t)(b * SEQ + i) * DMODEL + h * DK + d;
        O[gidx] = __float2half_rn(acc);
    }
}

// ---------------- last-layer attention: single query row per (b,h) ----------------
// qc: [BATCH][DMODEL] fp16 query of last token. kv: [NTOK][NKV], cols 0..1023 K, 1024..2047 V.
__global__ void __launch_bounds__(64) attn_last_kernel(
    const __half* __restrict__ qc, const __half* __restrict__ kv,
    __half* __restrict__ oc)
{
    const int bh = blockIdx.x;
    const int b = bh >> 4;
    const int h = bh & 15;
    const int tid = threadIdx.x;   // 64 threads

    __shared__ float qsh[DK];
    __shared__ float red[64];
    __shared__ float p[SEQ];

    qsh[tid] = __half2float(qc[(size_t)b * DMODEL + h * DK + tid]);
    __syncthreads();

    float sc = -1e30f;
    if (tid < SEQ) {
        const __half* kr = kv + (size_t)(b * SEQ + tid) * NKV + h * DK;
        float acc = 0.f;
#pragma unroll
        for (int d = 0; d < DK; d++) acc = fmaf(qsh[d], __half2float(kr[d]), acc);
        sc = acc * 0.125f;
    }
    red[tid] = sc;
    __syncthreads();
    float mx = -1e30f;
#pragma unroll 1
    for (int j = 0; j < SEQ; j++) mx = fmaxf(mx, red[j]);
    const float e = (tid < SEQ) ? expf(sc - mx) : 0.f;
    red[tid] = e;
    __syncthreads();
    float sum = 0.f;
#pragma unroll 1
    for (int j = 0; j < SEQ; j++) sum += red[j];
    if (tid < SEQ) p[tid] = e / sum;
    __syncthreads();

    float acc = 0.f;
#pragma unroll 1
    for (int j = 0; j < SEQ; j++)
        acc = fmaf(p[j], __half2float(kv[(size_t)(b * SEQ + j) * NKV + DMODEL + h * DK + tid]), acc);
    oc[(size_t)b * DMODEL + h * DK + tid] = __float2half_rn(acc);
}

// ---------------- head: final LN + bn scale -> z0h; zero z1 ----------------
__global__ void __launch_bounds__(256) pool_ln_scale_kernel(
    const float* __restrict__ hc,
    const float* __restrict__ fin_g, const float* __restrict__ fin_b,
    const float* __restrict__ bn_g, const float* __restrict__ bn_b,
    __half* __restrict__ z0h, float* __restrict__ z1)
{
    const int bb = blockIdx.x;
    const int c = threadIdx.x * 4;
    const float4 v = *reinterpret_cast<const float4*>(&hc[(size_t)bb * DMODEL + c]);
    float s  = v.x + v.y + v.z + v.w;
    float s2 = v.x * v.x + v.y * v.y + v.z * v.z + v.w * v.w;
#pragma unroll
    for (int o = 16; o; o >>= 1) {
        s  += __shfl_xor_sync(0xffffffffu, s, o);
        s2 += __shfl_xor_sync(0xffffffffu, s2, o);
    }
    __shared__ float sh[2][8];
    const int w = threadIdx.x >> 5;
    if ((threadIdx.x & 31) == 0) { sh[0][w] = s; sh[1][w] = s2; }
    __syncthreads();
    if (threadIdx.x < 32) {
        s  = (threadIdx.x < 8) ? sh[0][threadIdx.x] : 0.f;
        s2 = (threadIdx.x < 8) ? sh[1][threadIdx.x] : 0.f;
#pragma unroll
        for (int o = 4; o; o >>= 1) {
            s  += __shfl_xor_sync(0xffffffffu, s, o);
            s2 += __shfl_xor_sync(0xffffffffu, s2, o);
        }
        if (threadIdx.x == 0) { sh[0][0] = s; sh[1][0] = s2; }
    }
    __syncthreads();
    const float mean = sh[0][0] * (1.f / (float)DMODEL);
    float var = (sh[1][0] - (float)DMODEL * mean * mean) * (1.f / (float)(DMODEL - 1));
    var = fmaxf(var, 0.f);
    const float inv = 1.f / (sqrtf(var) + 1e-6f);
    const float invbn = 1.f / sqrtf(1.0f + 1e-5f);
    const float4 g4 = *reinterpret_cast<const float4*>(&fin_g[c]);
    const float4 b4 = *reinterpret_cast<const float4*>(&fin_b[c]);
    const float4 bg = *reinterpret_cast<const float4*>(&bn_g[c]);
    const float4 bb4 = *reinterpret_cast<const float4*>(&bn_b[c]);
    __half h4[4];
    h4[0] = __float2half_rn((g4.x * (v.x - mean) * inv + b4.x) * invbn * bg.x + bb4.x);
    h4[1] = __float2half_rn((g4.y * (v.y - mean) * inv + b4.y) * invbn * bg.y + bb4.y);
    h4[2] = __float2half_rn((g4.z * (v.z - mean) * inv + b4.z) * invbn * bg.z + bb4.z);
    h4[3] = __float2half_rn((g4.w * (v.w - mean) * inv + b4.w) * invbn * bg.w + bb4.w);
    *reinterpret_cast<uint2*>(&z0h[(size_t)bb * DMODEL + c]) = *reinterpret_cast<uint2*>(h4);
    const float4 zz = {0.f, 0.f, 0.f, 0.f};
    *reinterpret_cast<float4*>(&z1[(size_t)bb * DMODEL + c]) = zz;
}

// ---------------- final fc: relu(z1) -> bn2 scale -> @fc_w + fc_b ----------------
__global__ void __launch_bounds__(128) fc_kernel(
    const float* __restrict__ z1, const float* __restrict__ bn_g,
    const float* __restrict__ bn_b, const float* __restrict__ W,
    const float* __restrict__ bias, float* __restrict__ out)
{
    __shared__ float zs[DMODEL];
    const int bb = blockIdx.x;
    const float invbn = 1.f / sqrtf(1.0f + 1e-5f);
    for (int i = threadIdx.x; i < DMODEL; i += 128)
        zs[i] = fmaxf(z1[(size_t)bb * DMODEL + i], 0.f) * invbn * bn_g[i] + bn_b[i];
    __syncthreads();
    const int c = threadIdx.x;
    if (c < NCLS) {
        float acc = bias[c];
        for (int k = 0; k < DMODEL; k++) acc = fmaf(zs[k], W[(size_t)k * NCLS + c], acc);
        out[(size_t)bb * NCLS + c] = acc;
    }
}

// ---------------- host launcher ----------------
extern "C" void kernel_launch(void* const* d_in, const int* in_sizes, int n_in,
                              void* d_out, int out_size)
{
    const float* x        = (const float*)d_in[0];
    const float* embed_w  = (const float*)d_in[1];
    const float* attn_w   = (const float*)d_in[2];
    const float* attn_b   = (const float*)d_in[3];
    const float* ff_w1    = (const float*)d_in[4];
    const float* ff_b1    = (const float*)d_in[5];
    const float* ff_w2    = (const float*)d_in[6];
    const float* ff_b2    = (const float*)d_in[7];
    const float* ln_g     = (const float*)d_in[8];
    const float* ln_b     = (const float*)d_in[9];
    const float* fin_g    = (const float*)d_in[10];
    const float* fin_b    = (const float*)d_in[11];
    const float* cf_bn_g  = (const float*)d_in[12];
    const float* cf_bn_b  = (const float*)d_in[13];
    const float* cf_w     = (const float*)d_in[14];
    const float* cf_b     = (const float*)d_in[15];
    const float* fc_bn_g  = (const float*)d_in[16];
    const float* fc_bn_b  = (const float*)d_in[17];
    const float* fc_w     = (const float*)d_in[18];
    const float* fc_b     = (const float*)d_in[19];

    cudaFuncSetAttribute(tgemm_kernel, cudaFuncAttributeMaxDynamicSharedMemorySize, TGSMEM);
    cudaFuncSetAttribute(tgemm_atomic_kernel, cudaFuncAttributeMaxDynamicSharedMemorySize, TGSMEM);

    float *g_h, *g_hc, *g_z1;
    __half *g_qkv, *g_kv, *g_xh, *g_a, *g_o, *g_f, *g_wt;
    __half *g_aq, *g_qc, *g_oc, *g_ac, *g_fc, *g_z0h;
    cudaGetSymbolAddress((void**)&g_h,   d_h);
    cudaGetSymbolAddress((void**)&g_qkv, d_qkv);
    cudaGetSymbolAddress((void**)&g_kv,  d_kv);
    cudaGetSymbolAddress((void**)&g_hc,  d_hc);
    cudaGetSymbolAddress((void**)&g_z1,  d_z1);
    cudaGetSymbolAddress((void**)&g_xh,  d_xh);
    cudaGetSymbolAddress((void**)&g_a,   d_a);
    cudaGetSymbolAddress((void**)&g_o,   d_o);
    cudaGetSymbolAddress((void**)&g_f,   d_f);
    cudaGetSymbolAddress((void**)&g_wt,  d_wt);
    cudaGetSymbolAddress((void**)&g_aq,  d_aq);
    cudaGetSymbolAddress((void**)&g_qc,  d_qc);
    cudaGetSymbolAddress((void**)&g_oc,  d_oc);
    cudaGetSymbolAddress((void**)&g_ac,  d_ac);
    cudaGetSymbolAddress((void**)&g_fc,  d_fc);
    cudaGetSymbolAddress((void**)&g_z0h, d_z0h);

    dim3 blk(32, 8);

    // converts
    cvt_x_kernel<<<(NTOK * KEMBP / 2 + 255) / 256, 256>>>(x, g_xh);
    cvt_wT_batch_kernel<<<dim3(1024 / 32, (KEMBP + 255) / 256, 1), blk>>>(
        embed_w, g_wt, KEMB, DMODEL, KEMBP, 0, 0, 0, 1);
    cvt_wT_batch_kernel<<<dim3(32, 4, 20), blk>>>(
        attn_w, g_wt + WT_EMB_SZ, DMODEL, DMODEL, DMODEL,
        (size_t)DMODEL * DMODEL, (size_t)WT_LAYER, (size_t)1048576u, 4);
    cvt_wT_batch_kernel<<<dim3(DFF / 32, 4, 5), blk>>>(
        ff_w1, g_wt + WT_EMB_SZ + 4u * 1048576u,
        DMODEL, DFF, DMODEL, (size_t)DMODEL * DFF, (size_t)WT_LAYER, 0, 1);
    cvt_wT_batch_kernel<<<dim3(32, 16, 5), blk>>>(
        ff_w2, g_wt + WT_EMB_SZ + 8u * 1048576u,
        DFF, DMODEL, DFF, (size_t)DFF * DMODEL, (size_t)WT_LAYER, 0, 1);
    cvt_wT_batch_kernel<<<dim3(32, 4, 1), blk>>>(
        cf_w, g_wt + WT_CF, DMODEL, DMODEL, DMODEL, 0, 0, 0, 1);
    // embed GEMM, h = X @ We + PE
    {
        dim3 grid(DMODEL / 128, NTOK / 128);
        tgemm_kernel<<<grid, 128, TGSMEM>>>(
            g_xh, g_wt, nullptr, g_h, nullptr, KEMBP, DMODEL, 3);
    }

    // ---- layers 0..3 (full) ----
    for (int l = 0; l < NLAYER - 1; l++) {
        const size_t lw = (size_t)WT_EMB_SZ + (size_t)l * WT_LAYER;
        const __half* wq = g_wt + lw;
        const float* bq = attn_b + (size_t)l * 4 * DMODEL;

        ln_kernel<<<NTOK, 256>>>(g_h, ln_g + (size_t)(l * 2) * DMODEL,
                                 ln_b + (size_t)(l * 2) * DMODEL, g_a);
        {
            dim3 grid(NQKV / 128, NTOK / 128);
            tgemm_kernel<<<grid, 128, TGSMEM>>>(
                g_a, wq, bq, nullptr, g_qkv, DMODEL, NQKV, 0);
        }
        attn_kernel<<<BATCH * NHEAD, 256>>>(g_qkv, g_o);
        {
            dim3 grid(DMODEL / 128, NTOK / 128, 2);
            tgemm_atomic_kernel<<<grid, 128, TGSMEM>>>(
                g_o, wq + 3u * 1048576u, bq + 3 * DMODEL, g_h, DMODEL, DMODEL / 2, DMODEL);
        }
        ln_kernel<<<NTOK, 256>>>(g_h, ln_g + (size_t)(l * 2 + 1) * DMODEL,
                                 ln_b + (size_t)(l * 2 + 1) * DMODEL, g_a);
        {
            dim3 grid(DFF / 128, NTOK / 128);
            tgemm_kernel<<<grid, 128, TGSMEM>>>(
                g_a, g_wt + lw + 4u * 1048576u,
                ff_b1 + (size_t)l * DFF, nullptr, g_f, DMODEL, DFF, 1);
        }
        {
            dim3 grid(DMODEL / 128, NTOK / 128, 2);
            tgemm_atomic_kernel<<<grid, 128, TGSMEM>>>(
                g_f, g_wt + lw + 8u * 1048576u, ff_b2 + (size_t)l * DMODEL,
                g_h, DFF, DFF / 2, DMODEL);
        }
    }

    // ---- layer 4 (last): KV for all tokens, Q/attention/tail on 128 rows ----
    {
        const int l = NLAYER - 1;
        const size_t lw = (size_t)WT_EMB_SZ + (size_t)l * WT_LAYER;
        const __half* wq = g_wt + lw;
        const float* bq = attn_b + (size_t)l * 4 * DMODEL;

        ln_kernel<<<NTOK, 256>>>(g_h, ln_g + (size_t)(l * 2) * DMODEL,
                                 ln_b + (size_t)(l * 2) * DMODEL, g_a);
        // gather last-token LN output and residual h
        gather2_kernel<<<BATCH, 256>>>(g_h, g_a, g_hc, g_aq);
        // KV GEMM: all tokens, N=2048 (K,V weight rows)
        {
            dim3 grid(NKV / 128, NTOK / 128);
            tgemm_kernel<<<grid, 128, TGSMEM>>>(
                g_a, wq + 1u * 1048576u, bq + DMODEL, nullptr, g_kv, DMODEL, NKV, 0);
        }
        // Q GEMM: 128 last-token rows only
        {
            dim3 grid(DMODEL / 128, 1);
            tgemm_kernel<<<grid, 128, TGSMEM>>>(
                g_aq, wq, bq, nullptr, g_qc, DMODEL, DMODEL, 0);
        }
        attn_last_kernel<<<BATCH * NHEAD, 64>>>(g_qc, g_kv, g_oc);
        // out-proj on 128 rows: hc += oc @ Wo + bo (split-K=8)
        {
            dim3 grid(DMODEL / 128, 1, 8);
            tgemm_atomic_kernel<<<grid, 128, TGSMEM>>>(
                g_oc, wq + 3u * 1048576u, bq + 3 * DMODEL, g_hc, DMODEL, DMODEL / 8, DMODEL);
        }
        ln_kernel<<<BATCH, 256>>>(g_hc, ln_g + (size_t)(l * 2 + 1) * DMODEL,
                                  ln_b + (size_t)(l * 2 + 1) * DMODEL, g_ac);
        {
            dim3 grid(DFF / 128, 1);
            tgemm_kernel<<<grid, 128, TGSMEM>>>(
                g_ac, g_wt + lw + 4u * 1048576u,
                ff_b1 + (size_t)l * DFF, nullptr, g_fc, DMODEL, DFF, 1);
        }
        {
            dim3 grid(DMODEL / 128, 1, 8);
            tgemm_atomic_kernel<<<grid, 128, TGSMEM>>>(
                g_fc, g_wt + lw + 8u * 1048576u, ff_b2 + (size_t)l * DMODEL,
                g_hc, DFF, DFF / 8, DMODEL);
        }
    }

    // ---- classifier head (fp16 tensor path) ----
    pool_ln_scale_kernel<<<BATCH, 256>>>(g_hc, fin_g, fin_b, cf_bn_g, cf_bn_b, g_z0h, g_z1);
    {
        dim3 grid(DMODEL / 128, 1, 8);
        tgemm_atomic_kernel<<<grid, 128, TGSMEM>>>(
            g_z0h, g_wt + WT_CF, cf_b, g_z1, DMODEL, DMODEL / 8, DMODEL);
    }
    fc_kernel<<<BATCH, 128>>>(g_z1, fc_bn_g, fc_bn_b, fc_w, fc_b, (float*)d_out);
}

// round 16
// speedup vs baseline: 1.1460x; 1.0052x over previous
#include <cuda_runtime.h>
#include <cuda_fp16.h>
#include <math.h>
#include <stdint.h>

// ---------------- problem constants ----------------
#define BATCH 128
#define SEQ   50
#define DMODEL 1024
#define DFF   4096
#define NHEAD 16
#define DK    64
#define NLAYER 5
#define KEMB  1200
#define KEMBP 1216
#define NTOK  6400
#define NCLS  71
#define NQKV  3072
#define NKV   2048

#define GBK 32

// ---------------- weight scratch layout (transposed fp16) ----------------
#define WT_EMB_SZ (1024u*1216u)
#define WT_LAYER  (12u*1024u*1024u)
#define WT_CF     (WT_EMB_SZ + 5u*WT_LAYER)
#define WT_TOTAL  (WT_CF + 1048576u)

// ---------------- scratch (device globals) ----------------
__device__ float d_h  [NTOK * DMODEL];
__device__ float d_hc [BATCH * DMODEL];
__device__ float d_z1 [BATCH * DMODEL];

__device__ __align__(16) __half d_qkv[NTOK * NQKV];
__device__ __align__(16) __half d_kv [NTOK * NKV];
__device__ __align__(16) __half d_xh[NTOK * KEMBP];
__device__ __align__(16) __half d_a [NTOK * DMODEL];
__device__ __align__(16) __half d_o [NTOK * DMODEL];
__device__ __align__(16) __half d_f [NTOK * DFF];
__device__ __align__(16) __half d_wt[WT_TOTAL];
// compact (128-row) buffers for last-layer tail + head
__device__ __align__(16) __half d_aq[BATCH * DMODEL];
__device__ __align__(16) __half d_qc[BATCH * DMODEL];
__device__ __align__(16) __half d_oc[BATCH * DMODEL];
__device__ __align__(16) __half d_ac[BATCH * DMODEL];
__device__ __align__(16) __half d_fc[BATCH * DFF];
__device__ __align__(16) __half d_z0h[BATCH * DMODEL];

// ---------------- PTX helpers ----------------
__device__ __forceinline__ uint32_t smem_u32(const void* p) {
    uint32_t a;
    asm("{ .reg .u64 t; cvta.to.shared.u64 t, %1; cvt.u32.u64 %0, t; }" : "=r"(a) : "l"(p));
    return a;
}
__device__ __forceinline__ void cpa16(uint32_t dst, const void* src) {
    asm volatile("cp.async.cg.shared.global [%0], [%1], 16;" :: "r"(dst), "l"(src));
}
#define CP_COMMIT() asm volatile("cp.async.commit_group;" ::: "memory")
#define CP_WAIT2()  asm volatile("cp.async.wait_group 2;" ::: "memory")
#define CP_WAIT1()  asm volatile("cp.async.wait_group 1;" ::: "memory")
#define CP_WAIT0()  asm volatile("cp.async.wait_group 0;" ::: "memory")
#define LDSM4(r, a) \
    asm volatile("ldmatrix.sync.aligned.m8n8.x4.shared.b16 {%0,%1,%2,%3}, [%4];" \
        : "=r"((r)[0]), "=r"((r)[1]), "=r"((r)[2]), "=r"((r)[3]) : "r"(a))
#define MMA16816(c, a, b) \
    asm volatile("mma.sync.aligned.m16n8k16.row.col.f32.f16.f16.f32 " \
        "{%0,%1,%2,%3}, {%4,%5,%6,%7}, {%8,%9}, {%0,%1,%2,%3};" \
        : "+f"((c)[0]), "+f"((c)[1]), "+f"((c)[2]), "+f"((c)[3]) \
        : "r"((a)[0]), "r"((a)[1]), "r"((a)[2]), "r"((a)[3]), "r"((b)[0]), "r"((b)[1]))
__device__ __forceinline__ void red_add_f32(float* p, float v) {
    asm volatile("red.global.add.f32 [%0], %1;" :: "l"(p), "f"(v) : "memory");
}

// ================= HMMA GEMM core: 128x128 CTA tile, 128 thr, 4 warps (2x2, 64x64 warp tile)
#define OFFB  8192u
#define STAGE 16384u
#define TGSMEM (4u * STAGE)

#define TG_LOAD_STAGE(sb, k0)                                                  \
    do {                                                                       \
        _Pragma("unroll")                                                      \
        for (int i_ = 0; i_ < 4; i_++) {                                       \
            const int id_ = tid + i_ * 128;                                    \
            const int row_ = id_ >> 2, cc_ = id_ & 3;                          \
            const uint32_t off_ = (uint32_t)((row_ << 6) + ((cc_ ^ ((row_ >> 1) & 3)) << 4)); \
            const size_t ka_ = (size_t)(m0 + row_) * Kp + (k0) + cc_ * 8;      \
            const size_t kb_ = (size_t)(n0 + row_) * Kp + (k0) + cc_ * 8;      \
            cpa16((sb) + off_, A + ka_);                                       \
            cpa16((sb) + OFFB + off_, B + kb_);                                \
        }                                                                      \
    } while (0)

#define TG_COMPUTE(sb)                                                         \
    do {                                                                       \
        _Pragma("unroll")                                                      \
        for (int ks = 0; ks < 2; ks++) {                                       \
            uint32_t aF[4][4];                                                 \
            _Pragma("unroll")                                                  \
            for (int mt = 0; mt < 4; mt++) {                                   \
                const int r = wm * 64 + mt * 16 + (lane & 15);                 \
                const int ch = ks * 2 + (lane >> 4);                           \
                const uint32_t off = (uint32_t)((r << 6) + ((ch ^ ((r >> 1) & 3)) << 4)); \
                LDSM4(aF[mt], (sb) + off);                                     \
            }                                                                  \
            _Pragma("unroll")                                                  \
            for (int half = 0; half < 2; half++) {                             \
                uint32_t bF[4][2];                                             \
                _Pragma("unroll")                                              \
                for (int p = 0; p < 2; p++) {                                  \
                    const int r = wn * 64 + half * 32 + p * 16 + (lane & 7) + ((lane & 16) >> 1); \
                    const int ch = ks * 2 + ((lane >> 3) & 1);                 \
                    const uint32_t off = (uint32_t)((r << 6) + ((ch ^ ((r >> 1) & 3)) << 4)); \
                    uint32_t q[4];                                             \
                    LDSM4(q, (sb) + OFFB + off);                               \
                    bF[p*2][0] = q[0]; bF[p*2][1] = q[1];                      \
                    bF[p*2+1][0] = q[2]; bF[p*2+1][1] = q[3];                  \
                }                                                              \
                _Pragma("unroll")                                              \
                for (int mt = 0; mt < 4; mt++)                                 \
                    _Pragma("unroll")                                          \
                    for (int nt = 0; nt < 4; nt++) MMA16816(acc[mt][half*4+nt], aF[mt], bF[nt]); \
            }                                                                  \
        }                                                                      \
    } while (0)

#define TG_MAINLOOP(kbase, nchunk)                                             \
    do {                                                                       \
        TG_LOAD_STAGE(smb, (kbase));                                           \
        CP_COMMIT();                                                           \
        if ((nchunk) > 1) { TG_LOAD_STAGE(smb + STAGE, (kbase) + GBK); CP_COMMIT(); } \
        if ((nchunk) > 2) { TG_LOAD_STAGE(smb + 2u * STAGE, (kbase) + 2 * GBK); CP_COMMIT(); } \
        int s_c = 0, s_ld = 3;                                                 \
        for (int c = 0; c < (nchunk); c++) {                                   \
            const int wg_ = (nchunk) - c - 1;                                  \
            if (wg_ >= 2) CP_WAIT2(); else if (wg_ == 1) CP_WAIT1(); else CP_WAIT0(); \
            __syncthreads();                                                   \
            if (c + 3 < (nchunk)) { TG_LOAD_STAGE(smb + (uint32_t)s_ld * STAGE, (kbase) + (c + 3) * GBK); CP_COMMIT(); } \
            TG_COMPUTE(smb + (uint32_t)s_c * STAGE);                           \
            s_c = (s_c + 1) & 3; s_ld = (s_ld + 1) & 3;                        \
        }                                                                      \
    } while (0)

// ---------------- standard GEMM with fused epilogue ----------------
// epi: 0 = +bias -> Ch (fp16); 1 = relu(+bias) -> Ch (fp16); 3 = +PE -> Cf
__global__ void __launch_bounds__(128, 2) tgemm_kernel(
    const __half* __restrict__ A, const __half* __restrict__ B,
    const float* __restrict__ bias,
    float* __restrict__ Cf, __half* __restrict__ Ch,
    int Kp, int N, int epi)
{
    extern __shared__ char sm[];
    const uint32_t smb = smem_u32(sm);
    const int tid  = threadIdx.x;
    const int lane = tid & 31;
    const int wid  = tid >> 5;
    const int wm   = wid & 1;
    const int wn   = wid >> 1;
    const int m0 = blockIdx.y * 128;
    const int n0 = blockIdx.x * 128;

    float acc[4][8][4];
#pragma unroll
    for (int i = 0; i < 4; i++)
#pragma unroll
        for (int j = 0; j < 8; j++)
#pragma unroll
            for (int t = 0; t < 4; t++) acc[i][j][t] = 0.f;

    TG_MAINLOOP(0, Kp / GBK);

#pragma unroll
    for (int mt = 0; mt < 4; mt++) {
        const int r0 = m0 + wm * 64 + mt * 16 + (lane >> 2);
#pragma unroll
        for (int nt = 0; nt < 8; nt++) {
            const int col = n0 + wn * 64 + nt * 8 + (lane & 3) * 2;
            const float* a = acc[mt][nt];
            if (epi == 3) {
                const float dv = expf((float)(col & ~1) * (-9.210340371976184f / (float)DMODEL));
#pragma unroll
                for (int rr = 0; rr < 2; rr++) {
                    const int row = r0 + rr * 8;
                    const int srow = row % SEQ;
                    float sn, cs;
                    sincosf((float)srow * dv, &sn, &cs);
                    float2 o;
                    o.x = a[rr * 2 + 0] + sn;
                    o.y = a[rr * 2 + 1] + cs;
                    *reinterpret_cast<float2*>(&Cf[(size_t)row * N + col]) = o;
                }
            } else {
                const float b0 = __ldg(&bias[col]);
                const float b1 = __ldg(&bias[col + 1]);
#pragma unroll
                for (int rr = 0; rr < 2; rr++) {
                    const int row = r0 + rr * 8;
                    float v0 = a[rr * 2 + 0] + b0;
                    float v1 = a[rr * 2 + 1] + b1;
                    if (epi == 1) { v0 = fmaxf(v0, 0.f); v1 = fmaxf(v1, 0.f); }
                    *reinterpret_cast<__half2*>(&Ch[(size_t)row * N + col]) =
                        __halves2half2(__float2half_rn(v0), __float2half_rn(v1));
                }
            }
        }
    }
}

// ---------------- split-K GEMM: partial sums atomically added into C ----------------
__global__ void __launch_bounds__(128, 2) tgemm_atomic_kernel(
    const __half* __restrict__ A, const __half* __restrict__ B,
    const float* __restrict__ bias,
    float* __restrict__ Cf, int Kp, int Kz, int N)
{
    extern __shared__ char sm[];
    const uint32_t smb = smem_u32(sm);
    const int tid  = threadIdx.x;
    const int lane = tid & 31;
    const int wid  = tid >> 5;
    const int wm   = wid & 1;
    const int wn   = wid >> 1;
    const int m0 = blockIdx.y * 128;
    const int n0 = blockIdx.x * 128;
    const int kbase = blockIdx.z * Kz;
    const bool addb = (bias != nullptr) && (blockIdx.z == 0);

    float acc[4][8][4];
#pragma unroll
    for (int i = 0; i < 4; i++)
#pragma unroll
        for (int j = 0; j < 8; j++)
#pragma unroll
            for (int t = 0; t < 4; t++) acc[i][j][t] = 0.f;

    TG_MAINLOOP(kbase, Kz / GBK);

#pragma unroll
    for (int mt = 0; mt < 4; mt++) {
        const int r0 = m0 + wm * 64 + mt * 16 + (lane >> 2);
#pragma unroll
        for (int nt = 0; nt < 8; nt++) {
            const int col = n0 + wn * 64 + nt * 8 + (lane & 3) * 2;
            const float* a = acc[mt][nt];
            const float b0 = addb ? __ldg(&bias[col])     : 0.f;
            const float b1 = addb ? __ldg(&bias[col + 1]) : 0.f;
#pragma unroll
            for (int rr = 0; rr < 2; rr++) {
                const int row = r0 + rr * 8;
                float* p = &Cf[(size_t)row * N + col];
                red_add_f32(p,     a[rr * 2 + 0] + b0);
                red_add_f32(p + 1, a[rr * 2 + 1] + b1);
            }
        }
    }
}

// ---------------- converters ----------------
__global__ void __launch_bounds__(256) cvt_x_kernel(
    const float* __restrict__ x, __half* __restrict__ xh)
{
    const int idx = blockIdx.x * 256 + threadIdx.x;
    if (idx >= NTOK * KEMBP / 2) return;
    const int c = (idx * 2) % KEMBP;
    const int r = (idx * 2) / KEMBP;
    float v0 = 0.f, v1 = 0.f;
    if (c < KEMB) {
        const float2 xv = *reinterpret_cast<const float2*>(&x[(size_t)r * KEMB + c]);
        v0 = xv.x; v1 = xv.y;
    }
    reinterpret_cast<__half2*>(xh)[idx] = __halves2half2(__float2half_rn(v0), __float2half_rn(v1));
}

// W [K][N] fp32 -> transposed fp16 [N][Kp]; 256(k) x 32(n) tile, XOR-swizzled smem (conflict-free)
__global__ void cvt_wT_batch_kernel(
    const float* __restrict__ W, __half* __restrict__ Th,
    int K, int N, int Kp,
    size_t w_stride, size_t o_outer, size_t o_inner, int inner_mod)
{
    const int z = blockIdx.z;
    const float* Wz = W + (size_t)z * w_stride;
    const size_t ooff = (size_t)(z / inner_mod) * o_outer + (size_t)(z % inner_mod) * o_inner;
    __shared__ float t[256 * 32];
    const int k0 = blockIdx.y * 256, n0 = blockIdx.x * 32;
    const int tx = threadIdx.x, ty = threadIdx.y;   // block (32, 8)
    // load: row = k index (0..255), col = n index (0..31); swizzle col ^= (row>>3)
#pragma unroll
    for (int i = 0; i < 256; i += 8) {
        const int row = ty + i;
        const int k = k0 + row;
        t[row * 32 + (tx ^ (row >> 3))] = (k < K) ? Wz[(size_t)k * N + n0 + tx] : 0.f;
    }
    __syncthreads();
    // store: thread tx owns rows tx*8..tx*8+7 (k), cols ty*4..ty*4+3 (n)
    const int kk = k0 + tx * 8;
    if (kk < Kp) {
#pragma unroll
        for (int i = 0; i < 4; i++) {
            const int nn = ty * 4 + i;
            __half h8[8];
#pragma unroll
            for (int j = 0; j < 8; j++) {
                const int row = tx * 8 + j;
                h8[j] = __float2half_rn(t[row * 32 + (nn ^ (row >> 3))]);
            }
            *reinterpret_cast<uint4*>(&Th[ooff + (size_t)(n0 + nn) * Kp + kk]) =
                *reinterpret_cast<uint4*>(h8);
        }
    }
}

// ---------------- LayerNorm (ddof=1, eps on std) -> fp16; optional last-token gather ----------------
// If hc/aq non-null: rows with (row % SEQ == SEQ-1) also write hc (raw h) and aq (LN out).
__global__ void __launch_bounds__(256) ln_kernel(
    const float* __restrict__ hio, const float* __restrict__ g,
    const float* __restrict__ b, __half* __restrict__ outh,
    float* __restrict__ hc, __half* __restrict__ aq)
{
    const int row = blockIdx.x;
    const int c = threadIdx.x * 4;
    const float4 v = *reinterpret_cast<const float4*>(&hio[(size_t)row * DMODEL + c]);
    float s  = v.x + v.y + v.z + v.w;
    float s2 = v.x * v.x + v.y * v.y + v.z * v.z + v.w * v.w;
#pragma unroll
    for (int o = 16; o; o >>= 1) {
        s  += __shfl_xor_sync(0xffffffffu, s, o);
        s2 += __shfl_xor_sync(0xffffffffu, s2, o);
    }
    __shared__ float sh[2][8];
    const int w = threadIdx.x >> 5;
    if ((threadIdx.x & 31) == 0) { sh[0][w] = s; sh[1][w] = s2; }
    __syncthreads();
    if (threadIdx.x < 32) {
        s  = (threadIdx.x < 8) ? sh[0][threadIdx.x] : 0.f;
        s2 = (threadIdx.x < 8) ? sh[1][threadIdx.x] : 0.f;
#pragma unroll
        for (int o = 4; o; o >>= 1) {
            s  += __shfl_xor_sync(0xffffffffu, s, o);
            s2 += __shfl_xor_sync(0xffffffffu, s2, o);
        }
        if (threadIdx.x == 0) { sh[0][0] = s; sh[1][0] = s2; }
    }
    __syncthreads();
    const float mean = sh[0][0] * (1.f / (float)DMODEL);
    float var = (sh[1][0] - (float)DMODEL * mean * mean) * (1.f / (float)(DMODEL - 1));
    var = fmaxf(var, 0.f);
    const float inv = 1.f / (sqrtf(var) + 1e-6f);
    const float4 g4 = *reinterpret_cast<const float4*>(&g[c]);
    const float4 b4 = *reinterpret_cast<const float4*>(&b[c]);
    __half h4[4];
    h4[0] = __float2half_rn(g4.x * (v.x - mean) * inv + b4.x);
    h4[1] = __float2half_rn(g4.y * (v.y - mean) * inv + b4.y);
    h4[2] = __float2half_rn(g4.z * (v.z - mean) * inv + b4.z);
    h4[3] = __float2half_rn(g4.w * (v.w - mean) * inv + b4.w);
    *reinterpret_cast<uint2*>(&outh[(size_t)row * DMODEL + c]) = *reinterpret_cast<uint2*>(h4);
    if (hc && (row % SEQ) == SEQ - 1) {
        const int bb = row / SEQ;
        *reinterpret_cast<float4*>(&hc[(size_t)bb * DMODEL + c]) = v;
        *reinterpret_cast<uint2*>(&aq[(size_t)bb * DMODEL + c]) = *reinterpret_cast<uint2*>(h4);
    }
}

// ---------------- attention on fused fp16 QKV buffer (layers 0..3) ----------------
__global__ void __launch_bounds__(256) attn_kernel(
    const __half* __restrict__ QKV, __half* __restrict__ O)
{
    const int bh = blockIdx.x;
    const int b = bh >> 4;
    const int h = bh & 15;

    __shared__ float qs[SEQ][DK];
    __shared__ float ks[SEQ][DK + 1];
    __shared__ float vs[SEQ][DK];
    __shared__ float sc[SEQ][SEQ + 2];

    const int tid = threadIdx.x;
    const int lane = tid & 31;
    const int wid = tid >> 5;

    for (int e = tid; e < SEQ * DK / 2; e += 256) {
        const int s = e >> 5;
        const int d = (e & 31) * 2;
        const size_t gbase = (size_t)(b * SEQ + s) * NQKV + h * DK + d;
        const float2 q2 = __half22float2(*reinterpret_cast<const __half2*>(&QKV[gbase]));
        const float2 k2 = __half22float2(*reinterpret_cast<const __half2*>(&QKV[gbase + DMODEL]));
        const float2 v2 = __half22float2(*reinterpret_cast<const __half2*>(&QKV[gbase + 2 * DMODEL]));
        qs[s][d] = q2.x; qs[s][d + 1] = q2.y;
        ks[s][d] = k2.x; ks[s][d + 1] = k2.y;
        vs[s][d] = v2.x; vs[s][d + 1] = v2.y;
    }
    __syncthreads();

    for (int e = tid; e < SEQ * SEQ; e += 256) {
        const int i = e / SEQ;
        const int j = e % SEQ;
        float acc = 0.f;
#pragma unroll
        for (int d = 0; d < DK; d++) acc = fmaf(qs[i][d], ks[j][d], acc);
        sc[i][j] = acc * 0.125f;
    }
    __syncthreads();

    for (int r = wid; r < SEQ; r += 8) {
        const float v0 = (lane < SEQ) ? sc[r][lane] : -1e30f;
        const float v1 = (lane + 32 < SEQ) ? sc[r][lane + 32] : -1e30f;
        float mx = fmaxf(v0, v1);
#pragma unroll
        for (int o = 16; o; o >>= 1) mx = fmaxf(mx, __shfl_xor_sync(0xffffffffu, mx, o));
        const float e0 = (lane < SEQ) ? expf(v0 - mx) : 0.f;
        const float e1 = (lane + 32 < SEQ) ? expf(v1 - mx) : 0.f;
        float sum = e0 + e1;
#pragma unroll
        for (int o = 16; o; o >>= 1) sum += __shfl_xor_sync(0xffffffffu, sum, o);
        const float rinv = 1.f / sum;
        if (lane < SEQ) sc[r][lane] = e0 * rinv;
        if (lane + 32 < SEQ) sc[r][lane + 32] = e1 * rinv;
    }
    __syncthreads();

    for (int e = tid; e < SEQ * DK; e += 256) {
        const int i = e >> 6;
        const int d = e & 63;
        float acc = 0.f;
#pragma unroll
        for (int j = 0; j < SEQ; j++) acc = fmaf(sc[i][j], vs[j][d], acc);
        const size_t gidx = (size_t)(b * SEQ + i) * DMODEL + h * DK + d;
        O[gidx] = __float2half_rn(acc);
    }
}

// ---------------- last-layer attention: single query row per (b,h) ----------------
__global__ void __launch_bounds__(64) attn_last_kernel(
    const __half* __restrict__ qc, const __half* __restrict__ kv,
    __half* __restrict__ oc)
{
    const int bh = blockIdx.x;
    const int b = bh >> 4;
    const int h = bh & 15;
    const int tid = threadIdx.x;

    __shared__ float qsh[DK];
    __shared__ float red[64];
    __shared__ float p[SEQ];

    qsh[tid] = __half2float(qc[(size_t)b * DMODEL + h * DK + tid]);
    __syncthreads();

    float sc = -1e30f;
    if (tid < SEQ) {
        const __half* kr = kv + (size_t)(b * SEQ + tid) * NKV + h * DK;
        float acc = 0.f;
#pragma unroll
        for (int d = 0; d < DK; d++) acc = fmaf(qsh[d], __half2float(kr[d]), acc);
        sc = acc * 0.125f;
    }
    red[tid] = sc;
    __syncthreads();
    float mx = -1e30f;
#pragma unroll 1
    for (int j = 0; j < SEQ; j++) mx = fmaxf(mx, red[j]);
    const float e = (tid < SEQ) ? expf(sc - mx) : 0.f;
    red[tid] = e;
    __syncthreads();
    float sum = 0.f;
#pragma unroll 1
    for (int j = 0; j < SEQ; j++) sum += red[j];
    if (tid < SEQ) p[tid] = e / sum;
    __syncthreads();

    float acc = 0.f;
#pragma unroll 1
    for (int j = 0; j < SEQ; j++)
        acc = fmaf(p[j], __half2float(kv[(size_t)(b * SEQ + j) * NKV + DMODEL + h * DK + tid]), acc);
    oc[(size_t)b * DMODEL + h * DK + tid] = __float2half_rn(acc);
}

// ---------------- head: final LN + bn scale -> z0h; zero z1 ----------------
__global__ void __launch_bounds__(256) pool_ln_scale_kernel(
    const float* __restrict__ hc,
    const float* __restrict__ fin_g, const float* __restrict__ fin_b,
    const float* __restrict__ bn_g, const float* __restrict__ bn_b,
    __half* __restrict__ z0h, float* __restrict__ z1)
{
    const int bb = blockIdx.x;
    const int c = threadIdx.x * 4;
    const float4 v = *reinterpret_cast<const float4*>(&hc[(size_t)bb * DMODEL + c]);
    float s  = v.x + v.y + v.z + v.w;
    float s2 = v.x * v.x + v.y * v.y + v.z * v.z + v.w * v.w;
#pragma unroll
    for (int o = 16; o; o >>= 1) {
        s  += __shfl_xor_sync(0xffffffffu, s, o);
        s2 += __shfl_xor_sync(0xffffffffu, s2, o);
    }
    __shared__ float sh[2][8];
    const int w = threadIdx.x >> 5;
    if ((threadIdx.x & 31) == 0) { sh[0][w] = s; sh[1][w] = s2; }
    __syncthreads();
    if (threadIdx.x < 32) {
        s  = (threadIdx.x < 8) ? sh[0][threadIdx.x] : 0.f;
        s2 = (threadIdx.x < 8) ? sh[1][threadIdx.x] : 0.f;
#pragma unroll
        for (int o = 4; o; o >>= 1) {
            s  += __shfl_xor_sync(0xffffffffu, s, o);
            s2 += __shfl_xor_sync(0xffffffffu, s2, o);
        }
        if (threadIdx.x == 0) { sh[0][0] = s; sh[1][0] = s2; }
    }
    __syncthreads();
    const float mean = sh[0][0] * (1.f / (float)DMODEL);
    float var = (sh[1][0] - (float)DMODEL * mean * mean) * (1.f / (float)(DMODEL - 1));
    var = fmaxf(var, 0.f);
    const float inv = 1.f / (sqrtf(var) + 1e-6f);
    const float invbn = 1.f / sqrtf(1.0f + 1e-5f);
    const float4 g4 = *reinterpret_cast<const float4*>(&fin_g[c]);
    const float4 b4 = *reinterpret_cast<const float4*>(&fin_b[c]);
    const float4 bg = *reinterpret_cast<const float4*>(&bn_g[c]);
    const float4 bb4 = *reinterpret_cast<const float4*>(&bn_b[c]);
    __half h4[4];
    h4[0] = __float2half_rn((g4.x * (v.x - mean) * inv + b4.x) * invbn * bg.x + bb4.x);
    h4[1] = __float2half_rn((g4.y * (v.y - mean) * inv + b4.y) * invbn * bg.y + bb4.y);
    h4[2] = __float2half_rn((g4.z * (v.z - mean) * inv + b4.z) * invbn * bg.z + bb4.z);
    h4[3] = __float2half_rn((g4.w * (v.w - mean) * inv + b4.w) * invbn * bg.w + bb4.w);
    *reinterpret_cast<uint2*>(&z0h[(size_t)bb * DMODEL + c]) = *reinterpret_cast<uint2*>(h4);
    const float4 zz = {0.f, 0.f, 0.f, 0.f};
    *reinterpret_cast<float4*>(&z1[(size_t)bb * DMODEL + c]) = zz;
}

// ---------------- final fc: relu(z1) -> bn2 scale -> @fc_w + fc_b ----------------
__global__ void __launch_bounds__(128) fc_kernel(
    const float* __restrict__ z1, const float* __restrict__ bn_g,
    const float* __restrict__ bn_b, const float* __restrict__ W,
    const float* __restrict__ bias, float* __restrict__ out)
{
    __shared__ float zs[DMODEL];
    const int bb = blockIdx.x;
    const float invbn = 1.f / sqrtf(1.0f + 1e-5f);
    for (int i = threadIdx.x; i < DMODEL; i += 128)
        zs[i] = fmaxf(z1[(size_t)bb * DMODEL + i], 0.f) * invbn * bn_g[i] + bn_b[i];
    __syncthreads();
    const int c = threadIdx.x;
    if (c < NCLS) {
        float acc = bias[c];
        for (int k = 0; k < DMODEL; k++) acc = fmaf(zs[k], W[(size_t)k * NCLS + c], acc);
        out[(size_t)bb * NCLS + c] = acc;
    }
}

// ---------------- host launcher ----------------
extern "C" void kernel_launch(void* const* d_in, const int* in_sizes, int n_in,
                              void* d_out, int out_size)
{
    const float* x        = (const float*)d_in[0];
    const float* embed_w  = (const float*)d_in[1];
    const float* attn_w   = (const float*)d_in[2];
    const float* attn_b   = (const float*)d_in[3];
    const float* ff_w1    = (const float*)d_in[4];
    const float* ff_b1    = (const float*)d_in[5];
    const float* ff_w2    = (const float*)d_in[6];
    const float* ff_b2    = (const float*)d_in[7];
    const float* ln_g     = (const float*)d_in[8];
    const float* ln_b     = (const float*)d_in[9];
    const float* fin_g    = (const float*)d_in[10];
    const float* fin_b    = (const float*)d_in[11];
    const float* cf_bn_g  = (const float*)d_in[12];
    const float* cf_bn_b  = (const float*)d_in[13];
    const float* cf_w     = (const float*)d_in[14];
    const float* cf_b     = (const float*)d_in[15];
    const float* fc_bn_g  = (const float*)d_in[16];
    const float* fc_bn_b  = (const float*)d_in[17];
    const float* fc_w     = (const float*)d_in[18];
    const float* fc_b     = (const float*)d_in[19];

    cudaFuncSetAttribute(tgemm_kernel, cudaFuncAttributeMaxDynamicSharedMemorySize, TGSMEM);
    cudaFuncSetAttribute(tgemm_atomic_kernel, cudaFuncAttributeMaxDynamicSharedMemorySize, TGSMEM);

    float *g_h, *g_hc, *g_z1;
    __half *g_qkv, *g_kv, *g_xh, *g_a, *g_o, *g_f, *g_wt;
    __half *g_aq, *g_qc, *g_oc, *g_ac, *g_fc, *g_z0h;
    cudaGetSymbolAddress((void**)&g_h,   d_h);
    cudaGetSymbolAddress((void**)&g_qkv, d_qkv);
    cudaGetSymbolAddress((void**)&g_kv,  d_kv);
    cudaGetSymbolAddress((void**)&g_hc,  d_hc);
    cudaGetSymbolAddress((void**)&g_z1,  d_z1);
    cudaGetSymbolAddress((void**)&g_xh,  d_xh);
    cudaGetSymbolAddress((void**)&g_a,   d_a);
    cudaGetSymbolAddress((void**)&g_o,   d_o);
    cudaGetSymbolAddress((void**)&g_f,   d_f);
    cudaGetSymbolAddress((void**)&g_wt,  d_wt);
    cudaGetSymbolAddress((void**)&g_aq,  d_aq);
    cudaGetSymbolAddress((void**)&g_qc,  d_qc);
    cudaGetSymbolAddress((void**)&g_oc,  d_oc);
    cudaGetSymbolAddress((void**)&g_ac,  d_ac);
    cudaGetSymbolAddress((void**)&g_fc,  d_fc);
    cudaGetSymbolAddress((void**)&g_z0h, d_z0h);

    dim3 blk(32, 8);

    // converts
    cvt_x_kernel<<<(NTOK * KEMBP / 2 + 255) / 256, 256>>>(x, g_xh);
    cvt_wT_batch_kernel<<<dim3(1024 / 32, (KEMBP + 255) / 256, 1), blk>>>(
        embed_w, g_wt, KEMB, DMODEL, KEMBP, 0, 0, 0, 1);
    cvt_wT_batch_kernel<<<dim3(32, 4, 20), blk>>>(
        attn_w, g_wt + WT_EMB_SZ, DMODEL, DMODEL, DMODEL,
        (size_t)DMODEL * DMODEL, (size_t)WT_LAYER, (size_t)1048576u, 4);
    cvt_wT_batch_kernel<<<dim3(DFF / 32, 4, 5), blk>>>(
        ff_w1, g_wt + WT_EMB_SZ + 4u * 1048576u,
        DMODEL, DFF, DMODEL, (size_t)DMODEL * DFF, (size_t)WT_LAYER, 0, 1);
    cvt_wT_batch_kernel<<<dim3(32, 16, 5), blk>>>(
        ff_w2, g_wt + WT_EMB_SZ + 8u * 1048576u,
        DFF, DMODEL, DFF, (size_t)DFF * DMODEL, (size_t)WT_LAYER, 0, 1);
    cvt_wT_batch_kernel<<<dim3(32, 4, 1), blk>>>(
        cf_w, g_wt + WT_CF, DMODEL, DMODEL, DMODEL, 0, 0, 0, 1);
    // embed GEMM, h = X @ We + PE
    {
        dim3 grid(DMODEL / 128, NTOK / 128);
        tgemm_kernel<<<grid, 128, TGSMEM>>>(
            g_xh, g_wt, nullptr, g_h, nullptr, KEMBP, DMODEL, 3);
    }

    // ---- layers 0..3 (full) ----
    for (int l = 0; l < NLAYER - 1; l++) {
        const size_t lw = (size_t)WT_EMB_SZ + (size_t)l * WT_LAYER;
        const __half* wq = g_wt + lw;
        const float* bq = attn_b + (size_t)l * 4 * DMODEL;

        ln_kernel<<<NTOK, 256>>>(g_h, ln_g + (size_t)(l * 2) * DMODEL,
                                 ln_b + (size_t)(l * 2) * DMODEL, g_a, nullptr, nullptr);
        {
            dim3 grid(NQKV / 128, NTOK / 128);
            tgemm_kernel<<<grid, 128, TGSMEM>>>(
                g_a, wq, bq, nullptr, g_qkv, DMODEL, NQKV, 0);
        }
        attn_kernel<<<BATCH * NHEAD, 256>>>(g_qkv, g_o);
        {
            dim3 grid(DMODEL / 128, NTOK / 128, 2);
            tgemm_atomic_kernel<<<grid, 128, TGSMEM>>>(
                g_o, wq + 3u * 1048576u, bq + 3 * DMODEL, g_h, DMODEL, DMODEL / 2, DMODEL);
        }
        ln_kernel<<<NTOK, 256>>>(g_h, ln_g + (size_t)(l * 2 + 1) * DMODEL,
                                 ln_b + (size_t)(l * 2 + 1) * DMODEL, g_a, nullptr, nullptr);
        {
            dim3 grid(DFF / 128, NTOK / 128);
            tgemm_kernel<<<grid, 128, TGSMEM>>>(
                g_a, g_wt + lw + 4u * 1048576u,
                ff_b1 + (size_t)l * DFF, nullptr, g_f, DMODEL, DFF, 1);
        }
        {
            dim3 grid(DMODEL / 128, NTOK / 128, 2);
            tgemm_atomic_kernel<<<grid, 128, TGSMEM>>>(
                g_f, g_wt + lw + 8u * 1048576u, ff_b2 + (size_t)l * DMODEL,
                g_h, DFF, DFF / 2, DMODEL);
        }
    }

    // ---- layer 4 (last): KV for all tokens, Q/attention/tail on 128 rows ----
    {
        const int l = NLAYER - 1;
        const size_t lw = (size_t)WT_EMB_SZ + (size_t)l * WT_LAYER;
        const __half* wq = g_wt + lw;
        const float* bq = attn_b + (size_t)l * 4 * DMODEL;

        // LN1 with fused last-token gather (hc = raw h, aq = LN output)
        ln_kernel<<<NTOK, 256>>>(g_h, ln_g + (size_t)(l * 2) * DMODEL,
                                 ln_b + (size_t)(l * 2) * DMODEL, g_a, g_hc, g_aq);
        // KV GEMM: all tokens, N=2048
        {
            dim3 grid(NKV / 128, NTOK / 128);
            tgemm_kernel<<<grid, 128, TGSMEM>>>(
                g_a, wq + 1u * 1048576u, bq + DMODEL, nullptr, g_kv, DMODEL, NKV, 0);
        }
        // Q GEMM: 128 last-token rows only
        {
            dim3 grid(DMODEL / 128, 1);
            tgemm_kernel<<<grid, 128, TGSMEM>>>(
                g_aq, wq, bq, nullptr, g_qc, DMODEL, DMODEL, 0);
        }
        attn_last_kernel<<<BATCH * NHEAD, 64>>>(g_qc, g_kv, g_oc);
        {
            dim3 grid(DMODEL / 128, 1, 8);
            tgemm_atomic_kernel<<<grid, 128, TGSMEM>>>(
                g_oc, wq + 3u * 1048576u, bq + 3 * DMODEL, g_hc, DMODEL, DMODEL / 8, DMODEL);
        }
        ln_kernel<<<BATCH, 256>>>(g_hc, ln_g + (size_t)(l * 2 + 1) * DMODEL,
                                  ln_b + (size_t)(l * 2 + 1) * DMODEL, g_ac, nullptr, nullptr);
        {
            dim3 grid(DFF / 128, 1);
            tgemm_kernel<<<grid, 128, TGSMEM>>>(
                g_ac, g_wt + lw + 4u * 1048576u,
                ff_b1 + (size_t)l * DFF, nullptr, g_fc, DMODEL, DFF, 1);
        }
        {
            dim3 grid(DMODEL / 128, 1, 8);
            tgemm_atomic_kernel<<<grid, 128, TGSMEM>>>(
                g_fc, g_wt + lw + 8u * 1048576u, ff_b2 + (size_t)l * DMODEL,
                g_hc, DFF, DFF / 8, DMODEL);
        }
    }

    // ---- classifier head (fp16 tensor path) ----
    pool_ln_scale_kernel<<<BATCH, 256>>>(g_hc, fin_g, fin_b, cf_bn_g, cf_bn_b, g_z0h, g_z1);
    {
        dim3 grid(DMODEL / 128, 1, 8);
        tgemm_atomic_kernel<<<grid, 128, TGSMEM>>>(
            g_z0h, g_wt + WT_CF, cf_b, g_z1, DMODEL, DMODEL / 8, DMODEL);
    }
    fc_kernel<<<BATCH, 128>>>(g_z1, fc_bn_g, fc_bn_b, fc_w, fc_b, (float*)d_out);
}

// round 17
// speedup vs baseline: 1.1804x; 1.0301x over previous
#include <cuda_runtime.h>
#include <cuda_fp16.h>
#include <math.h>
#include <stdint.h>

// ---------------- problem constants ----------------
#define BATCH 128
#define SEQ   50
#define DMODEL 1024
#define DFF   4096
#define NHEAD 16
#define DK    64
#define NLAYER 5
#define KEMB  1200
#define KEMBP 1216
#define NTOK  6400
#define NCLS  71
#define NQKV  3072
#define NKV   2048

#define GBK 32

// ---------------- weight scratch layout (transposed fp16) ----------------
#define WT_EMB_SZ (1024u*1216u)
#define WT_LAYER  (12u*1024u*1024u)
#define WT_CF     (WT_EMB_SZ + 5u*WT_LAYER)
#define WT_TOTAL  (WT_CF + 1048576u)

// ---------------- scratch (device globals) ----------------
__device__ float d_h  [NTOK * DMODEL];
__device__ float d_hc [BATCH * DMODEL];
__device__ float d_z1 [BATCH * DMODEL];

__device__ __align__(16) __half d_qkv[NTOK * NQKV];
__device__ __align__(16) __half d_kv [NTOK * NKV];
__device__ __align__(16) __half d_xh[NTOK * KEMBP];
__device__ __align__(16) __half d_a [NTOK * DMODEL];
__device__ __align__(16) __half d_o [NTOK * DMODEL];
__device__ __align__(16) __half d_f [NTOK * DFF];
__device__ __align__(16) __half d_wt[WT_TOTAL];
// compact (128-row) buffers for last-layer tail + head
__device__ __align__(16) __half d_aq[BATCH * DMODEL];
__device__ __align__(16) __half d_qc[BATCH * DMODEL];
__device__ __align__(16) __half d_oc[BATCH * DMODEL];
__device__ __align__(16) __half d_ac[BATCH * DMODEL];
__device__ __align__(16) __half d_fc[BATCH * DFF];
__device__ __align__(16) __half d_z0h[BATCH * DMODEL];

// ---------------- PTX helpers ----------------
__device__ __forceinline__ uint32_t smem_u32(const void* p) {
    uint32_t a;
    asm("{ .reg .u64 t; cvta.to.shared.u64 t, %1; cvt.u32.u64 %0, t; }" : "=r"(a) : "l"(p));
    return a;
}
__device__ __forceinline__ void cpa16(uint32_t dst, const void* src) {
    asm volatile("cp.async.cg.shared.global [%0], [%1], 16;" :: "r"(dst), "l"(src));
}
#define CP_COMMIT() asm volatile("cp.async.commit_group;" ::: "memory")
#define CP_WAIT2()  asm volatile("cp.async.wait_group 2;" ::: "memory")
#define CP_WAIT1()  asm volatile("cp.async.wait_group 1;" ::: "memory")
#define CP_WAIT0()  asm volatile("cp.async.wait_group 0;" ::: "memory")
#define LDSM4(r, a) \
    asm volatile("ldmatrix.sync.aligned.m8n8.x4.shared.b16 {%0,%1,%2,%3}, [%4];" \
        : "=r"((r)[0]), "=r"((r)[1]), "=r"((r)[2]), "=r"((r)[3]) : "r"(a))
#define MMA16816(c, a, b) \
    asm volatile("mma.sync.aligned.m16n8k16.row.col.f32.f16.f16.f32 " \
        "{%0,%1,%2,%3}, {%4,%5,%6,%7}, {%8,%9}, {%0,%1,%2,%3};" \
        : "+f"((c)[0]), "+f"((c)[1]), "+f"((c)[2]), "+f"((c)[3]) \
        : "r"((a)[0]), "r"((a)[1]), "r"((a)[2]), "r"((a)[3]), "r"((b)[0]), "r"((b)[1]))
__device__ __forceinline__ void red_add_f32(float* p, float v) {
    asm volatile("red.global.add.f32 [%0], %1;" :: "l"(p), "f"(v) : "memory");
}

// ================= HMMA GEMM core: 128x128 CTA tile, 128 thr, 4 warps (2x2, 64x64 warp tile)
#define OFFB  8192u
#define STAGE 16384u
#define TGSMEM (4u * STAGE)

#define TG_LOAD_STAGE(sb, k0)                                                  \
    do {                                                                       \
        _Pragma("unroll")                                                      \
        for (int i_ = 0; i_ < 4; i_++) {                                       \
            const int id_ = tid + i_ * 128;                                    \
            const int row_ = id_ >> 2, cc_ = id_ & 3;                          \
            const uint32_t off_ = (uint32_t)((row_ << 6) + ((cc_ ^ ((row_ >> 1) & 3)) << 4)); \
            const size_t ka_ = (size_t)(m0 + row_) * Kp + (k0) + cc_ * 8;      \
            const size_t kb_ = (size_t)(n0 + row_) * Kp + (k0) + cc_ * 8;      \
            cpa16((sb) + off_, A + ka_);                                       \
            cpa16((sb) + OFFB + off_, B + kb_);                                \
        }                                                                      \
    } while (0)

#define TG_COMPUTE(sb)                                                         \
    do {                                                                       \
        _Pragma("unroll")                                                      \
        for (int ks = 0; ks < 2; ks++) {                                       \
            uint32_t aF[4][4];                                                 \
            _Pragma("unroll")                                                  \
            for (int mt = 0; mt < 4; mt++) {                                   \
                const int r = wm * 64 + mt * 16 + (lane & 15);                 \
                const int ch = ks * 2 + (lane >> 4);                           \
                const uint32_t off = (uint32_t)((r << 6) + ((ch ^ ((r >> 1) & 3)) << 4)); \
                LDSM4(aF[mt], (sb) + off);                                     \
            }                                                                  \
            _Pragma("unroll")                                                  \
            for (int half = 0; half < 2; half++) {                             \
                uint32_t bF[4][2];                                             \
                _Pragma("unroll")                                              \
                for (int p = 0; p < 2; p++) {                                  \
                    const int r = wn * 64 + half * 32 + p * 16 + (lane & 7) + ((lane & 16) >> 1); \
                    const int ch = ks * 2 + ((lane >> 3) & 1);                 \
                    const uint32_t off = (uint32_t)((r << 6) + ((ch ^ ((r >> 1) & 3)) << 4)); \
                    uint32_t q[4];                                             \
                    LDSM4(q, (sb) + OFFB + off);                               \
                    bF[p*2][0] = q[0]; bF[p*2][1] = q[1];                      \
                    bF[p*2+1][0] = q[2]; bF[p*2+1][1] = q[3];                  \
                }                                                              \
                _Pragma("unroll")                                              \
                for (int mt = 0; mt < 4; mt++)                                 \
                    _Pragma("unroll")                                          \
                    for (int nt = 0; nt < 4; nt++) MMA16816(acc[mt][half*4+nt], aF[mt], bF[nt]); \
            }                                                                  \
        }                                                                      \
    } while (0)

#define TG_MAINLOOP(kbase, nchunk)                                             \
    do {                                                                       \
        TG_LOAD_STAGE(smb, (kbase));                                           \
        CP_COMMIT();                                                           \
        if ((nchunk) > 1) { TG_LOAD_STAGE(smb + STAGE, (kbase) + GBK); CP_COMMIT(); } \
        if ((nchunk) > 2) { TG_LOAD_STAGE(smb + 2u * STAGE, (kbase) + 2 * GBK); CP_COMMIT(); } \
        int s_c = 0, s_ld = 3;                                                 \
        for (int c = 0; c < (nchunk); c++) {                                   \
            const int wg_ = (nchunk) - c - 1;                                  \
            if (wg_ >= 2) CP_WAIT2(); else if (wg_ == 1) CP_WAIT1(); else CP_WAIT0(); \
            __syncthreads();                                                   \
            if (c + 3 < (nchunk)) { TG_LOAD_STAGE(smb + (uint32_t)s_ld * STAGE, (kbase) + (c + 3) * GBK); CP_COMMIT(); } \
            TG_COMPUTE(smb + (uint32_t)s_c * STAGE);                           \
            s_c = (s_c + 1) & 3; s_ld = (s_ld + 1) & 3;                        \
        }                                                                      \
    } while (0)

// epilogue for the plain-bias fp16 path (epi 0/1), shared by kernels below
#define TG_EPI_BIAS_F16(biasp, Chp, Np, relu)                                  \
    do {                                                                       \
        _Pragma("unroll")                                                      \
        for (int mt = 0; mt < 4; mt++) {                                       \
            const int r0 = m0 + wm * 64 + mt * 16 + (lane >> 2);               \
            _Pragma("unroll")                                                  \
            for (int nt = 0; nt < 8; nt++) {                                   \
                const int col = n0 + wn * 64 + nt * 8 + (lane & 3) * 2;        \
                const float* a = acc[mt][nt];                                  \
                const float b0 = __ldg(&(biasp)[col]);                         \
                const float b1 = __ldg(&(biasp)[col + 1]);                     \
                _Pragma("unroll")                                              \
                for (int rr = 0; rr < 2; rr++) {                               \
                    const int row = r0 + rr * 8;                               \
                    float v0 = a[rr * 2 + 0] + b0;                             \
                    float v1 = a[rr * 2 + 1] + b1;                             \
                    if (relu) { v0 = fmaxf(v0, 0.f); v1 = fmaxf(v1, 0.f); }    \
                    *reinterpret_cast<__half2*>(&(Chp)[(size_t)row * (Np) + col]) = \
                        __halves2half2(__float2half_rn(v0), __float2half_rn(v1)); \
                }                                                              \
            }                                                                  \
        }                                                                      \
    } while (0)

// ---------------- standard GEMM with fused epilogue ----------------
// epi: 0 = +bias -> Ch (fp16); 1 = relu(+bias) -> Ch (fp16); 3 = +PE -> Cf
__global__ void __launch_bounds__(128, 2) tgemm_kernel(
    const __half* __restrict__ A, const __half* __restrict__ B,
    const float* __restrict__ bias,
    float* __restrict__ Cf, __half* __restrict__ Ch,
    int Kp, int N, int epi)
{
    extern __shared__ char sm[];
    const uint32_t smb = smem_u32(sm);
    const int tid  = threadIdx.x;
    const int lane = tid & 31;
    const int wid  = tid >> 5;
    const int wm   = wid & 1;
    const int wn   = wid >> 1;
    const int m0 = blockIdx.y * 128;
    const int n0 = blockIdx.x * 128;

    float acc[4][8][4];
#pragma unroll
    for (int i = 0; i < 4; i++)
#pragma unroll
        for (int j = 0; j < 8; j++)
#pragma unroll
            for (int t = 0; t < 4; t++) acc[i][j][t] = 0.f;

    TG_MAINLOOP(0, Kp / GBK);

    if (epi == 3) {
#pragma unroll
        for (int mt = 0; mt < 4; mt++) {
            const int r0 = m0 + wm * 64 + mt * 16 + (lane >> 2);
#pragma unroll
            for (int nt = 0; nt < 8; nt++) {
                const int col = n0 + wn * 64 + nt * 8 + (lane & 3) * 2;
                const float* a = acc[mt][nt];
                const float dv = expf((float)(col & ~1) * (-9.210340371976184f / (float)DMODEL));
#pragma unroll
                for (int rr = 0; rr < 2; rr++) {
                    const int row = r0 + rr * 8;
                    const int srow = row % SEQ;
                    float sn, cs;
                    sincosf((float)srow * dv, &sn, &cs);
                    float2 o;
                    o.x = a[rr * 2 + 0] + sn;
                    o.y = a[rr * 2 + 1] + cs;
                    *reinterpret_cast<float2*>(&Cf[(size_t)row * N + col]) = o;
                }
            }
        }
    } else if (epi == 1) {
        TG_EPI_BIAS_F16(bias, Ch, N, true);
    } else {
        TG_EPI_BIAS_F16(bias, Ch, N, false);
    }
}

// ---------------- merged last-layer KV + Q GEMM ----------------
// grid (16, 51): y < 50 -> KV tile (A=a6400, B=wkv, N=2048);
//                y == 50 -> Q tile on 128 gathered rows (A=aq, B=wq, N=1024; x<8 only)
__global__ void __launch_bounds__(128, 2) tgemm_kvq_kernel(
    const __half* __restrict__ Afull, const __half* __restrict__ Aq,
    const __half* __restrict__ Wq,    const __half* __restrict__ Wkv,
    const float* __restrict__ bq,
    __half* __restrict__ Qc, __half* __restrict__ KV)
{
    const bool isq = (blockIdx.y == 50);
    if (isq && blockIdx.x >= 8) return;

    extern __shared__ char sm[];
    const uint32_t smb = smem_u32(sm);
    const int tid  = threadIdx.x;
    const int lane = tid & 31;
    const int wid  = tid >> 5;
    const int wm   = wid & 1;
    const int wn   = wid >> 1;
    const int m0 = isq ? 0 : blockIdx.y * 128;
    const int n0 = blockIdx.x * 128;
    const __half* A = isq ? Aq : Afull;
    const __half* B = isq ? Wq : Wkv;
    const float* bias = isq ? bq : (bq + DMODEL);
    const int Kp = DMODEL;

    float acc[4][8][4];
#pragma unroll
    for (int i = 0; i < 4; i++)
#pragma unroll
        for (int j = 0; j < 8; j++)
#pragma unroll
            for (int t = 0; t < 4; t++) acc[i][j][t] = 0.f;

    TG_MAINLOOP(0, Kp / GBK);

    if (isq) {
        TG_EPI_BIAS_F16(bias, Qc, DMODEL, false);
    } else {
        TG_EPI_BIAS_F16(bias, KV, NKV, false);
    }
}

// ---------------- split-K GEMM: partial sums atomically added into C ----------------
__global__ void __launch_bounds__(128, 2) tgemm_atomic_kernel(
    const __half* __restrict__ A, const __half* __restrict__ B,
    const float* __restrict__ bias,
    float* __restrict__ Cf, int Kp, int Kz, int N)
{
    extern __shared__ char sm[];
    const uint32_t smb = smem_u32(sm);
    const int tid  = threadIdx.x;
    const int lane = tid & 31;
    const int wid  = tid >> 5;
    const int wm   = wid & 1;
    const int wn   = wid >> 1;
    const int m0 = blockIdx.y * 128;
    const int n0 = blockIdx.x * 128;
    const int kbase = blockIdx.z * Kz;
    const bool addb = (bias != nullptr) && (blockIdx.z == 0);

    float acc[4][8][4];
#pragma unroll
    for (int i = 0; i < 4; i++)
#pragma unroll
        for (int j = 0; j < 8; j++)
#pragma unroll
            for (int t = 0; t < 4; t++) acc[i][j][t] = 0.f;

    TG_MAINLOOP(kbase, Kz / GBK);

#pragma unroll
    for (int mt = 0; mt < 4; mt++) {
        const int r0 = m0 + wm * 64 + mt * 16 + (lane >> 2);
#pragma unroll
        for (int nt = 0; nt < 8; nt++) {
            const int col = n0 + wn * 64 + nt * 8 + (lane & 3) * 2;
            const float* a = acc[mt][nt];
            const float b0 = addb ? __ldg(&bias[col])     : 0.f;
            const float b1 = addb ? __ldg(&bias[col + 1]) : 0.f;
#pragma unroll
            for (int rr = 0; rr < 2; rr++) {
                const int row = r0 + rr * 8;
                float* p = &Cf[(size_t)row * N + col];
                red_add_f32(p,     a[rr * 2 + 0] + b0);
                red_add_f32(p + 1, a[rr * 2 + 1] + b1);
            }
        }
    }
}

// ---------------- converters ----------------
__global__ void __launch_bounds__(256) cvt_x_kernel(
    const float* __restrict__ x, __half* __restrict__ xh)
{
    const int idx = blockIdx.x * 256 + threadIdx.x;
    if (idx >= NTOK * KEMBP / 2) return;
    const int c = (idx * 2) % KEMBP;
    const int r = (idx * 2) / KEMBP;
    float v0 = 0.f, v1 = 0.f;
    if (c < KEMB) {
        const float2 xv = *reinterpret_cast<const float2*>(&x[(size_t)r * KEMB + c]);
        v0 = xv.x; v1 = xv.y;
    }
    reinterpret_cast<__half2*>(xh)[idx] = __halves2half2(__float2half_rn(v0), __float2half_rn(v1));
}

// W [K][N] fp32 -> transposed fp16 [N][Kp]; 256(k) x 32(n) tile, XOR-swizzled smem
__global__ void cvt_wT_batch_kernel(
    const float* __restrict__ W, __half* __restrict__ Th,
    int K, int N, int Kp,
    size_t w_stride, size_t o_outer, size_t o_inner, int inner_mod)
{
    const int z = blockIdx.z;
    const float* Wz = W + (size_t)z * w_stride;
    const size_t ooff = (size_t)(z / inner_mod) * o_outer + (size_t)(z % inner_mod) * o_inner;
    __shared__ float t[256 * 32];
    const int k0 = blockIdx.y * 256, n0 = blockIdx.x * 32;
    const int tx = threadIdx.x, ty = threadIdx.y;
#pragma unroll
    for (int i = 0; i < 256; i += 8) {
        const int row = ty + i;
        const int k = k0 + row;
        t[row * 32 + (tx ^ (row >> 3))] = (k < K) ? Wz[(size_t)k * N + n0 + tx] : 0.f;
    }
    __syncthreads();
    const int kk = k0 + tx * 8;
    if (kk < Kp) {
#pragma unroll
        for (int i = 0; i < 4; i++) {
            const int nn = ty * 4 + i;
            __half h8[8];
#pragma unroll
            for (int j = 0; j < 8; j++) {
                const int row = tx * 8 + j;
                h8[j] = __float2half_rn(t[row * 32 + (nn ^ (row >> 3))]);
            }
            *reinterpret_cast<uint4*>(&Th[ooff + (size_t)(n0 + nn) * Kp + kk]) =
                *reinterpret_cast<uint4*>(h8);
        }
    }
}

// ---------------- LayerNorm (ddof=1, eps on std) -> fp16; optional last-token gather ----------------
__global__ void __launch_bounds__(256) ln_kernel(
    const float* __restrict__ hio, const float* __restrict__ g,
    const float* __restrict__ b, __half* __restrict__ outh,
    float* __restrict__ hc, __half* __restrict__ aq)
{
    const int row = blockIdx.x;
    const int c = threadIdx.x * 4;
    const float4 v = *reinterpret_cast<const float4*>(&hio[(size_t)row * DMODEL + c]);
    float s  = v.x + v.y + v.z + v.w;
    float s2 = v.x * v.x + v.y * v.y + v.z * v.z + v.w * v.w;
#pragma unroll
    for (int o = 16; o; o >>= 1) {
        s  += __shfl_xor_sync(0xffffffffu, s, o);
        s2 += __shfl_xor_sync(0xffffffffu, s2, o);
    }
    __shared__ float sh[2][8];
    const int w = threadIdx.x >> 5;
    if ((threadIdx.x & 31) == 0) { sh[0][w] = s; sh[1][w] = s2; }
    __syncthreads();
    if (threadIdx.x < 32) {
        s  = (threadIdx.x < 8) ? sh[0][threadIdx.x] : 0.f;
        s2 = (threadIdx.x < 8) ? sh[1][threadIdx.x] : 0.f;
#pragma unroll
        for (int o = 4; o; o >>= 1) {
            s  += __shfl_xor_sync(0xffffffffu, s, o);
            s2 += __shfl_xor_sync(0xffffffffu, s2, o);
        }
        if (threadIdx.x == 0) { sh[0][0] = s; sh[1][0] = s2; }
    }
    __syncthreads();
    const float mean = sh[0][0] * (1.f / (float)DMODEL);
    float var = (sh[1][0] - (float)DMODEL * mean * mean) * (1.f / (float)(DMODEL - 1));
    var = fmaxf(var, 0.f);
    const float inv = 1.f / (sqrtf(var) + 1e-6f);
    const float4 g4 = *reinterpret_cast<const float4*>(&g[c]);
    const float4 b4 = *reinterpret_cast<const float4*>(&b[c]);
    __half h4[4];
    h4[0] = __float2half_rn(g4.x * (v.x - mean) * inv + b4.x);
    h4[1] = __float2half_rn(g4.y * (v.y - mean) * inv + b4.y);
    h4[2] = __float2half_rn(g4.z * (v.z - mean) * inv + b4.z);
    h4[3] = __float2half_rn(g4.w * (v.w - mean) * inv + b4.w);
    *reinterpret_cast<uint2*>(&outh[(size_t)row * DMODEL + c]) = *reinterpret_cast<uint2*>(h4);
    if (hc && (row % SEQ) == SEQ - 1) {
        const int bb = row / SEQ;
        *reinterpret_cast<float4*>(&hc[(size_t)bb * DMODEL + c]) = v;
        *reinterpret_cast<uint2*>(&aq[(size_t)bb * DMODEL + c]) = *reinterpret_cast<uint2*>(h4);
    }
}

// ---------------- attention on fused fp16 QKV buffer (layers 0..3) ----------------
__global__ void __launch_bounds__(256) attn_kernel(
    const __half* __restrict__ QKV, __half* __restrict__ O)
{
    const int bh = blockIdx.x;
    const int b = bh >> 4;
    const int h = bh & 15;

    __shared__ float qs[SEQ][DK];
    __shared__ float ks[SEQ][DK + 1];
    __shared__ float vs[SEQ][DK];
    __shared__ float sc[SEQ][SEQ + 2];

    const int tid = threadIdx.x;
    const int lane = tid & 31;
    const int wid = tid >> 5;

    for (int e = tid; e < SEQ * DK / 2; e += 256) {
        const int s = e >> 5;
        const int d = (e & 31) * 2;
        const size_t gbase = (size_t)(b * SEQ + s) * NQKV + h * DK + d;
        const float2 q2 = __half22float2(*reinterpret_cast<const __half2*>(&QKV[gbase]));
        const float2 k2 = __half22float2(*reinterpret_cast<const __half2*>(&QKV[gbase + DMODEL]));
        const float2 v2 = __half22float2(*reinterpret_cast<const __half2*>(&QKV[gbase + 2 * DMODEL]));
        qs[s][d] = q2.x; qs[s][d + 1] = q2.y;
        ks[s][d] = k2.x; ks[s][d + 1] = k2.y;
        vs[s][d] = v2.x; vs[s][d + 1] = v2.y;
    }
    __syncthreads();

    for (int e = tid; e < SEQ * SEQ; e += 256) {
        const int i = e / SEQ;
        const int j = e % SEQ;
        float acc = 0.f;
#pragma unroll
        for (int d = 0; d < DK; d++) acc = fmaf(qs[i][d], ks[j][d], acc);
        sc[i][j] = acc * 0.125f;
    }
    __syncthreads();

    for (int r = wid; r < SEQ; r += 8) {
        const float v0 = (lane < SEQ) ? sc[r][lane] : -1e30f;
        const float v1 = (lane + 32 < SEQ) ? sc[r][lane + 32] : -1e30f;
        float mx = fmaxf(v0, v1);
#pragma unroll
        for (int o = 16; o; o >>= 1) mx = fmaxf(mx, __shfl_xor_sync(0xffffffffu, mx, o));
        const float e0 = (lane < SEQ) ? expf(v0 - mx) : 0.f;
        const float e1 = (lane + 32 < SEQ) ? expf(v1 - mx) : 0.f;
        float sum = e0 + e1;
#pragma unroll
        for (int o = 16; o; o >>= 1) sum += __shfl_xor_sync(0xffffffffu, sum, o);
        const float rinv = 1.f / sum;
        if (lane < SEQ) sc[r][lane] = e0 * rinv;
        if (lane + 32 < SEQ) sc[r][lane + 32] = e1 * rinv;
    }
    __syncthreads();

    for (int e = tid; e < SEQ * DK; e += 256) {
        const int i = e >> 6;
        const int d = e & 63;
        float acc = 0.f;
#pragma unroll
        for (int j = 0; j < SEQ; j++) acc = fmaf(sc[i][j], vs[j][d], acc);
        const size_t gidx = (size_t)(b * SEQ + i) * DMODEL + h * DK + d;
        O[gidx] = __float2half_rn(acc);
    }
}

// ---------------- last-layer attention: single query row per (b,h) ----------------
__global__ void __launch_bounds__(64) attn_last_kernel(
    const __half* __restrict__ qc, const __half* __restrict__ kv,
    __half* __restrict__ oc)
{
    const int bh = blockIdx.x;
    const int b = bh >> 4;
    const int h = bh & 15;
    const int tid = threadIdx.x;

    __shared__ float qsh[DK];
    __shared__ float red[64];
    __shared__ float p[SEQ];

    qsh[tid] = __half2float(qc[(size_t)b * DMODEL + h * DK + tid]);
    __syncthreads();

    float sc = -1e30f;
    if (tid < SEQ) {
        const __half* kr = kv + (size_t)(b * SEQ + tid) * NKV + h * DK;
        float acc = 0.f;
#pragma unroll
        for (int d = 0; d < DK; d++) acc = fmaf(qsh[d], __half2float(kr[d]), acc);
        sc = acc * 0.125f;
    }
    red[tid] = sc;
    __syncthreads();
    float mx = -1e30f;
#pragma unroll 1
    for (int j = 0; j < SEQ; j++) mx = fmaxf(mx, red[j]);
    const float e = (tid < SEQ) ? expf(sc - mx) : 0.f;
    red[tid] = e;
    __syncthreads();
    float sum = 0.f;
#pragma unroll 1
    for (int j = 0; j < SEQ; j++) sum += red[j];
    if (tid < SEQ) p[tid] = e / sum;
    __syncthreads();

    float acc = 0.f;
#pragma unroll 1
    for (int j = 0; j < SEQ; j++)
        acc = fmaf(p[j], __half2float(kv[(size_t)(b * SEQ + j) * NKV + DMODEL + h * DK + tid]), acc);
    oc[(size_t)b * DMODEL + h * DK + tid] = __float2half_rn(acc);
}

// ---------------- head: final LN + bn scale -> z0h; zero z1 ----------------
__global__ void __launch_bounds__(256) pool_ln_scale_kernel(
    const float* __restrict__ hc,
    const float* __restrict__ fin_g, const float* __restrict__ fin_b,
    const float* __restrict__ bn_g, const float* __restrict__ bn_b,
    __half* __restrict__ z0h, float* __restrict__ z1)
{
    const int bb = blockIdx.x;
    const int c = threadIdx.x * 4;
    const float4 v = *reinterpret_cast<const float4*>(&hc[(size_t)bb * DMODEL + c]);
    float s  = v.x + v.y + v.z + v.w;
    float s2 = v.x * v.x + v.y * v.y + v.z * v.z + v.w * v.w;
#pragma unroll
    for (int o = 16; o; o >>= 1) {
        s  += __shfl_xor_sync(0xffffffffu, s, o);
        s2 += __shfl_xor_sync(0xffffffffu, s2, o);
    }
    __shared__ float sh[2][8];
    const int w = threadIdx.x >> 5;
    if ((threadIdx.x & 31) == 0) { sh[0][w] = s; sh[1][w] = s2; }
    __syncthreads();
    if (threadIdx.x < 32) {
        s  = (threadIdx.x < 8) ? sh[0][threadIdx.x] : 0.f;
        s2 = (threadIdx.x < 8) ? sh[1][threadIdx.x] : 0.f;
#pragma unroll
        for (int o = 4; o; o >>= 1) {
            s  += __shfl_xor_sync(0xffffffffu, s, o);
            s2 += __shfl_xor_sync(0xffffffffu, s2, o);
        }
        if (threadIdx.x == 0) { sh[0][0] = s; sh[1][0] = s2; }
    }
    __syncthreads();
    const float mean = sh[0][0] * (1.f / (float)DMODEL);
    float var = (sh[1][0] - (float)DMODEL * mean * mean) * (1.f / (float)(DMODEL - 1));
    var = fmaxf(var, 0.f);
    const float inv = 1.f / (sqrtf(var) + 1e-6f);
    const float invbn = 1.f / sqrtf(1.0f + 1e-5f);
    const float4 g4 = *reinterpret_cast<const float4*>(&fin_g[c]);
    const float4 b4 = *reinterpret_cast<const float4*>(&fin_b[c]);
    const float4 bg = *reinterpret_cast<const float4*>(&bn_g[c]);
    const float4 bb4 = *reinterpret_cast<const float4*>(&bn_b[c]);
    __half h4[4];
    h4[0] = __float2half_rn((g4.x * (v.x - mean) * inv + b4.x) * invbn * bg.x + bb4.x);
    h4[1] = __float2half_rn((g4.y * (v.y - mean) * inv + b4.y) * invbn * bg.y + bb4.y);
    h4[2] = __float2half_rn((g4.z * (v.z - mean) * inv + b4.z) * invbn * bg.z + bb4.z);
    h4[3] = __float2half_rn((g4.w * (v.w - mean) * inv + b4.w) * invbn * bg.w + bb4.w);
    *reinterpret_cast<uint2*>(&z0h[(size_t)bb * DMODEL + c]) = *reinterpret_cast<uint2*>(h4);
    const float4 zz = {0.f, 0.f, 0.f, 0.f};
    *reinterpret_cast<float4*>(&z1[(size_t)bb * DMODEL + c]) = zz;
}

// ---------------- final fc: relu(z1) -> bn2 scale -> @fc_w + fc_b ----------------
__global__ void __launch_bounds__(128) fc_kernel(
    const float* __restrict__ z1, const float* __restrict__ bn_g,
    const float* __restrict__ bn_b, const float* __restrict__ W,
    const float* __restrict__ bias, float* __restrict__ out)
{
    __shared__ float zs[DMODEL];
    const int bb = blockIdx.x;
    const float invbn = 1.f / sqrtf(1.0f + 1e-5f);
    for (int i = threadIdx.x; i < DMODEL; i += 128)
        zs[i] = fmaxf(z1[(size_t)bb * DMODEL + i], 0.f) * invbn * bn_g[i] + bn_b[i];
    __syncthreads();
    const int c = threadIdx.x;
    if (c < NCLS) {
        float acc = bias[c];
        for (int k = 0; k < DMODEL; k++) acc = fmaf(zs[k], W[(size_t)k * NCLS + c], acc);
        out[(size_t)bb * NCLS + c] = acc;
    }
}

// ---------------- host launcher ----------------
extern "C" void kernel_launch(void* const* d_in, const int* in_sizes, int n_in,
                              void* d_out, int out_size)
{
    const float* x        = (const float*)d_in[0];
    const float* embed_w  = (const float*)d_in[1];
    const float* attn_w   = (const float*)d_in[2];
    const float* attn_b   = (const float*)d_in[3];
    const float* ff_w1    = (const float*)d_in[4];
    const float* ff_b1    = (const float*)d_in[5];
    const float* ff_w2    = (const float*)d_in[6];
    const float* ff_b2    = (const float*)d_in[7];
    const float* ln_g     = (const float*)d_in[8];
    const float* ln_b     = (const float*)d_in[9];
    const float* fin_g    = (const float*)d_in[10];
    const float* fin_b    = (const float*)d_in[11];
    const float* cf_bn_g  = (const float*)d_in[12];
    const float* cf_bn_b  = (const float*)d_in[13];
    const float* cf_w     = (const float*)d_in[14];
    const float* cf_b     = (const float*)d_in[15];
    const float* fc_bn_g  = (const float*)d_in[16];
    const float* fc_bn_b  = (const float*)d_in[17];
    const float* fc_w     = (const float*)d_in[18];
    const float* fc_b     = (const float*)d_in[19];

    cudaFuncSetAttribute(tgemm_kernel, cudaFuncAttributeMaxDynamicSharedMemorySize, TGSMEM);
    cudaFuncSetAttribute(tgemm_kvq_kernel, cudaFuncAttributeMaxDynamicSharedMemorySize, TGSMEM);
    cudaFuncSetAttribute(tgemm_atomic_kernel, cudaFuncAttributeMaxDynamicSharedMemorySize, TGSMEM);

    float *g_h, *g_hc, *g_z1;
    __half *g_qkv, *g_kv, *g_xh, *g_a, *g_o, *g_f, *g_wt;
    __half *g_aq, *g_qc, *g_oc, *g_ac, *g_fc, *g_z0h;
    cudaGetSymbolAddress((void**)&g_h,   d_h);
    cudaGetSymbolAddress((void**)&g_qkv, d_qkv);
    cudaGetSymbolAddress((void**)&g_kv,  d_kv);
    cudaGetSymbolAddress((void**)&g_hc,  d_hc);
    cudaGetSymbolAddress((void**)&g_z1,  d_z1);
    cudaGetSymbolAddress((void**)&g_xh,  d_xh);
    cudaGetSymbolAddress((void**)&g_a,   d_a);
    cudaGetSymbolAddress((void**)&g_o,   d_o);
    cudaGetSymbolAddress((void**)&g_f,   d_f);
    cudaGetSymbolAddress((void**)&g_wt,  d_wt);
    cudaGetSymbolAddress((void**)&g_aq,  d_aq);
    cudaGetSymbolAddress((void**)&g_qc,  d_qc);
    cudaGetSymbolAddress((void**)&g_oc,  d_oc);
    cudaGetSymbolAddress((void**)&g_ac,  d_ac);
    cudaGetSymbolAddress((void**)&g_fc,  d_fc);
    cudaGetSymbolAddress((void**)&g_z0h, d_z0h);

    dim3 blk(32, 8);

    // converts
    cvt_x_kernel<<<(NTOK * KEMBP / 2 + 255) / 256, 256>>>(x, g_xh);
    cvt_wT_batch_kernel<<<dim3(1024 / 32, (KEMBP + 255) / 256, 1), blk>>>(
        embed_w, g_wt, KEMB, DMODEL, KEMBP, 0, 0, 0, 1);
    cvt_wT_batch_kernel<<<dim3(32, 4, 20), blk>>>(
        attn_w, g_wt + WT_EMB_SZ, DMODEL, DMODEL, DMODEL,
        (size_t)DMODEL * DMODEL, (size_t)WT_LAYER, (size_t)1048576u, 4);
    cvt_wT_batch_kernel<<<dim3(DFF / 32, 4, 5), blk>>>(
        ff_w1, g_wt + WT_EMB_SZ + 4u * 1048576u,
        DMODEL, DFF, DMODEL, (size_t)DMODEL * DFF, (size_t)WT_LAYER, 0, 1);
    cvt_wT_batch_kernel<<<dim3(32, 16, 5), blk>>>(
        ff_w2, g_wt + WT_EMB_SZ + 8u * 1048576u,
        DFF, DMODEL, DFF, (size_t)DFF * DMODEL, (size_t)WT_LAYER, 0, 1);
    cvt_wT_batch_kernel<<<dim3(32, 4, 1), blk>>>(
        cf_w, g_wt + WT_CF, DMODEL, DMODEL, DMODEL, 0, 0, 0, 1);
    // embed GEMM, h = X @ We + PE
    {
        dim3 grid(DMODEL / 128, NTOK / 128);
        tgemm_kernel<<<grid, 128, TGSMEM>>>(
            g_xh, g_wt, nullptr, g_h, nullptr, KEMBP, DMODEL, 3);
    }

    // ---- layers 0..3 (full) ----
    for (int l = 0; l < NLAYER - 1; l++) {
        const size_t lw = (size_t)WT_EMB_SZ + (size_t)l * WT_LAYER;
        const __half* wq = g_wt + lw;
        const float* bq = attn_b + (size_t)l * 4 * DMODEL;

        ln_kernel<<<NTOK, 256>>>(g_h, ln_g + (size_t)(l * 2) * DMODEL,
                                 ln_b + (size_t)(l * 2) * DMODEL, g_a, nullptr, nullptr);
        {
            dim3 grid(NQKV / 128, NTOK / 128);
            tgemm_kernel<<<grid, 128, TGSMEM>>>(
                g_a, wq, bq, nullptr, g_qkv, DMODEL, NQKV, 0);
        }
        attn_kernel<<<BATCH * NHEAD, 256>>>(g_qkv, g_o);
        {
            dim3 grid(DMODEL / 128, NTOK / 128, 2);
            tgemm_atomic_kernel<<<grid, 128, TGSMEM>>>(
                g_o, wq + 3u * 1048576u, bq + 3 * DMODEL, g_h, DMODEL, DMODEL / 2, DMODEL);
        }
        ln_kernel<<<NTOK, 256>>>(g_h, ln_g + (size_t)(l * 2 + 1) * DMODEL,
                                 ln_b + (size_t)(l * 2 + 1) * DMODEL, g_a, nullptr, nullptr);
        {
            dim3 grid(DFF / 128, NTOK / 128);
            tgemm_kernel<<<grid, 128, TGSMEM>>>(
                g_a, g_wt + lw + 4u * 1048576u,
                ff_b1 + (size_t)l * DFF, nullptr, g_f, DMODEL, DFF, 1);
        }
        {
            dim3 grid(DMODEL / 128, NTOK / 128, 2);
            tgemm_atomic_kernel<<<grid, 128, TGSMEM>>>(
                g_f, g_wt + lw + 8u * 1048576u, ff_b2 + (size_t)l * DMODEL,
                g_h, DFF, DFF / 2, DMODEL);
        }
    }

    // ---- layer 4 (last): merged KV+Q, single-query attention, compact tail ----
    {
        const int l = NLAYER - 1;
        const size_t lw = (size_t)WT_EMB_SZ + (size_t)l * WT_LAYER;
        const __half* wq = g_wt + lw;
        const float* bq = attn_b + (size_t)l * 4 * DMODEL;

        // LN1 with fused last-token gather (hc = raw h, aq = LN output)
        ln_kernel<<<NTOK, 256>>>(g_h, ln_g + (size_t)(l * 2) * DMODEL,
                                 ln_b + (size_t)(l * 2) * DMODEL, g_a, g_hc, g_aq);
        // merged KV (all tokens, N=2048) + Q (128 rows, N=1024) GEMM
        {
            dim3 grid(NKV / 128, NTOK / 128 + 1);
            tgemm_kvq_kernel<<<grid, 128, TGSMEM>>>(
                g_a, g_aq, wq, wq + 1u * 1048576u, bq, g_qc, g_kv);
        }
        attn_last_kernel<<<BATCH * NHEAD, 64>>>(g_qc, g_kv, g_oc);
        {
            dim3 grid(DMODEL / 128, 1, 8);
            tgemm_atomic_kernel<<<grid, 128, TGSMEM>>>(
                g_oc, wq + 3u * 1048576u, bq + 3 * DMODEL, g_hc, DMODEL, DMODEL / 8, DMODEL);
        }
        ln_kernel<<<BATCH, 256>>>(g_hc, ln_g + (size_t)(l * 2 + 1) * DMODEL,
                                  ln_b + (size_t)(l * 2 + 1) * DMODEL, g_ac, nullptr, nullptr);
        {
            dim3 grid(DFF / 128, 1);
            tgemm_kernel<<<grid, 128, TGSMEM>>>(
                g_ac, g_wt + lw + 4u * 1048576u,
                ff_b1 + (size_t)l * DFF, nullptr, g_fc, DMODEL, DFF, 1);
        }
        {
            dim3 grid(DMODEL / 128, 1, 8);
            tgemm_atomic_kernel<<<grid, 128, TGSMEM>>>(
                g_fc, g_wt + lw + 8u * 1048576u, ff_b2 + (size_t)l * DMODEL,
                g_hc, DFF, DFF / 8, DMODEL);
        }
    }

    // ---- classifier head (fp16 tensor path) ----
    pool_ln_scale_kernel<<<BATCH, 256>>>(g_hc, fin_g, fin_b, cf_bn_g, cf_bn_b, g_z0h, g_z1);
    {
        dim3 grid(DMODEL / 128, 1, 8);
        tgemm_atomic_kernel<<<grid, 128, TGSMEM>>>(
            g_z0h, g_wt + WT_CF, cf_b, g_z1, DMODEL, DMODEL / 8, DMODEL);
    }
    fc_kernel<<<BATCH, 128>>>(g_z1, fc_bn_g, fc_bn_b, fc_w, fc_b, (float*)d_out);
}